// round 1
// baseline (speedup 1.0000x reference)
#include <cuda_runtime.h>
#include <cuda_bf16.h>
#include <math.h>

#define Bb   2
#define Lseq 1024
#define DM   768
#define DI   1536
#define NS   16
#define DTR  96
#define XDB  (DTR + 2*NS)   // 128
#define TT   (Bb*Lseq)      // 2048

// ---------------- scratch (device globals; no allocation allowed) ----------------
__device__ float g_un[TT*DM];            // layernorm output
__device__ float g_xz[2][TT*2*DI];       // in-proj output per branch (x | z)
__device__ float g_xc[2][TT*DI];         // conv+silu output per branch
__device__ float g_xdbl[2][TT*XDB];      // xproj output per branch
__device__ float g_dt[2][TT*DI];         // dt per branch
__device__ float g_ycat[TT*2*DI];        // concat(y_fwd, y_bwd) for out GEMM

// ---------------- layernorm ----------------
__global__ __launch_bounds__(256) void ln_kernel(const float* __restrict__ u,
                                                 const float* __restrict__ w,
                                                 const float* __restrict__ bvec)
{
    int t = blockIdx.x;                   // token 0..2047
    const float* row = u + (size_t)t * DM;
    float v[3];
    float s = 0.f, s2 = 0.f;
#pragma unroll
    for (int i = 0; i < 3; i++) {
        v[i] = row[threadIdx.x + i*256];
        s  += v[i];
        s2 += v[i]*v[i];
    }
#pragma unroll
    for (int o = 16; o; o >>= 1) {
        s  += __shfl_xor_sync(0xffffffffu, s,  o);
        s2 += __shfl_xor_sync(0xffffffffu, s2, o);
    }
    __shared__ float ss[8], ss2[8];
    int wid = threadIdx.x >> 5, ln = threadIdx.x & 31;
    if (ln == 0) { ss[wid] = s; ss2[wid] = s2; }
    __syncthreads();
    float ts = 0.f, ts2 = 0.f;
#pragma unroll
    for (int i = 0; i < 8; i++) { ts += ss[i]; ts2 += ss2[i]; }
    float mu  = ts * (1.f/DM);
    float var = ts2 * (1.f/DM) - mu*mu;
    float rs  = rsqrtf(var + 1e-5f);
#pragma unroll
    for (int i = 0; i < 3; i++) {
        int c = threadIdx.x + i*256;
        g_un[(size_t)t*DM + c] = (v[i]-mu)*rs*w[c] + bvec[c];
    }
}

// ---------------- generic SGEMM: C[m,n] = sum_k A[m,k] * W[n,k] ----------------
// mode 0: plain store; mode 1: softplus(acc + bias[n]); mode 2: acc + resid[m,n]
__global__ __launch_bounds__(256) void sgemm_nt(
    const float* __restrict__ A0, const float* __restrict__ A1, int lda,
    const float* __restrict__ W0, const float* __restrict__ W1,
    float* __restrict__ C0, float* __restrict__ C1, int ldc,
    int M, int N, int K, int mode,
    const float* __restrict__ bias0, const float* __restrict__ bias1,
    const float* __restrict__ resid)
{
    const float* A    = blockIdx.z ? A1 : A0;
    const float* W    = blockIdx.z ? W1 : W0;
    float*       C    = blockIdx.z ? C1 : C0;
    const float* bias = blockIdx.z ? bias1 : bias0;

    __shared__ __align__(16) float As[8][128];
    __shared__ __align__(16) float Bs[8][128];

    int tid  = threadIdx.x;
    int bm   = blockIdx.y * 128;
    int bn   = blockIdx.x * 128;
    int lrow = tid >> 1;
    int lcol = (tid & 1) * 4;
    int tr   = (tid >> 4) * 8;
    int tc   = (tid & 15) * 8;

    float acc[8][8];
#pragma unroll
    for (int i = 0; i < 8; i++)
#pragma unroll
        for (int j = 0; j < 8; j++) acc[i][j] = 0.f;

    const float* Aptr = A + (size_t)(bm + lrow) * lda + lcol;
    const float* Wptr = W + (size_t)(bn + lrow) * K   + lcol;

    for (int k0 = 0; k0 < K; k0 += 8) {
        float4 av = *(const float4*)(Aptr + k0);
        float4 bv = *(const float4*)(Wptr + k0);
        As[lcol+0][lrow] = av.x; As[lcol+1][lrow] = av.y;
        As[lcol+2][lrow] = av.z; As[lcol+3][lrow] = av.w;
        Bs[lcol+0][lrow] = bv.x; Bs[lcol+1][lrow] = bv.y;
        Bs[lcol+2][lrow] = bv.z; Bs[lcol+3][lrow] = bv.w;
        __syncthreads();
#pragma unroll
        for (int kk = 0; kk < 8; kk++) {
            float ar[8], br[8];
            *(float4*)(ar)   = *(const float4*)&As[kk][tr];
            *(float4*)(ar+4) = *(const float4*)&As[kk][tr+4];
            *(float4*)(br)   = *(const float4*)&Bs[kk][tc];
            *(float4*)(br+4) = *(const float4*)&Bs[kk][tc+4];
#pragma unroll
            for (int i = 0; i < 8; i++)
#pragma unroll
                for (int j = 0; j < 8; j++)
                    acc[i][j] = fmaf(ar[i], br[j], acc[i][j]);
        }
        __syncthreads();
    }

#pragma unroll
    for (int i = 0; i < 8; i++) {
        int m = bm + tr + i;
#pragma unroll
        for (int j = 0; j < 8; j++) {
            int nn = bn + tc + j;
            float v = acc[i][j];
            if (mode == 1) {
                v += bias[nn];
                v = fmaxf(v, 0.f) + log1pf(__expf(-fabsf(v)));  // softplus
            } else if (mode == 2) {
                v += resid[(size_t)m*ldc + nn];
            }
            C[(size_t)m*ldc + nn] = v;
        }
    }
}

// ---------------- depthwise causal/anticausal conv (K=4) + silu ----------------
__global__ __launch_bounds__(256) void conv_silu(
    const float* __restrict__ cw0, const float* __restrict__ cb0,
    const float* __restrict__ cw1, const float* __restrict__ cb1)
{
    int br = blockIdx.y;
    const float* cw = br ? cw1 : cw0;
    const float* cb = br ? cb1 : cb0;
    const float* xz = g_xz[br];
    float*       xc = g_xc[br];

    int idx = blockIdx.x * 256 + threadIdx.x;   // over TT*DI
    if (idx >= TT*DI) return;
    int d = idx % DI;
    int t = idx / DI;
    int l = t % Lseq;

    float w0 = cw[d*4+0], w1 = cw[d*4+1], w2 = cw[d*4+2], w3 = cw[d*4+3];
    float acc = cb[d];
    if (br == 0) {          // causal: out[l] = sum_k w[k]*x[l-3+k]
        acc += w3 * xz[(size_t)t*2*DI + d];
        if (l >= 1) acc += w2 * xz[(size_t)(t-1)*2*DI + d];
        if (l >= 2) acc += w1 * xz[(size_t)(t-2)*2*DI + d];
        if (l >= 3) acc += w0 * xz[(size_t)(t-3)*2*DI + d];
    } else {                // anticausal (reversed-seq causal in fwd coords)
        acc += w3 * xz[(size_t)t*2*DI + d];
        if (l+1 < Lseq) acc += w2 * xz[(size_t)(t+1)*2*DI + d];
        if (l+2 < Lseq) acc += w1 * xz[(size_t)(t+2)*2*DI + d];
        if (l+3 < Lseq) acc += w0 * xz[(size_t)(t+3)*2*DI + d];
    }
    float sg = 1.f / (1.f + __expf(-acc));
    xc[idx] = acc * sg;
}

// ---------------- selective scan (fwd + bwd), gate, write ycat ----------------
// lanes: 16 per d (one per state n); h-recurrence critical path = 1 FFMA/step
__global__ __launch_bounds__(128) void scan_kernel(
    const float* __restrict__ Alog0, const float* __restrict__ Alog1,
    const float* __restrict__ Dv0,   const float* __restrict__ Dv1)
{
    int br = blockIdx.z;
    int b  = blockIdx.y;
    const float* Alog = br ? Alog1 : Alog0;
    const float* Dvec = br ? Dv1   : Dv0;
    const float* dt   = g_dt[br];
    const float* xc   = g_xc[br];
    const float* xd   = g_xdbl[br];
    const float* xz   = g_xz[br];

    int lane = threadIdx.x & 31;
    int warp = threadIdx.x >> 5;
    int n    = lane & 15;
    int d    = blockIdx.x * 8 + warp * 2 + (lane >> 4);

    float A  = -__expf(Alog[d*NS + n]);
    float Dp = Dvec[d];
    float h  = 0.f;

    for (int s = 0; s < Lseq; s++) {
        int l = br ? (Lseq-1-s) : s;
        int t = b*Lseq + l;
        float dtv = dt[(size_t)t*DI + d];
        float xv  = xc[(size_t)t*DI + d];
        float Bv  = xd[(size_t)t*XDB + DTR + n];
        float Cv  = xd[(size_t)t*XDB + DTR + NS + n];
        float a   = __expf(dtv * A);
        h = fmaf(a, h, dtv * xv * Bv);
        float y = h * Cv;
        y += __shfl_xor_sync(0xffffffffu, y, 8);
        y += __shfl_xor_sync(0xffffffffu, y, 4);
        y += __shfl_xor_sync(0xffffffffu, y, 2);
        y += __shfl_xor_sync(0xffffffffu, y, 1);
        if (n == 0) {
            float z  = xz[(size_t)t*2*DI + DI + d];
            float sz = z / (1.f + __expf(-z));
            g_ycat[(size_t)t*2*DI + br*DI + d] = fmaf(xv, Dp, y) * sz;
        }
    }
}

// ---------------- launcher ----------------
extern "C" void kernel_launch(void* const* d_in, const int* in_sizes, int n_in,
                              void* d_out, int out_size)
{
    const float* u       = (const float*)d_in[0];
    const float* norm_w  = (const float*)d_in[1];
    const float* norm_b  = (const float*)d_in[2];
    const float* f_in_w  = (const float*)d_in[3];
    const float* f_cw    = (const float*)d_in[4];
    const float* f_cb    = (const float*)d_in[5];
    const float* f_Alog  = (const float*)d_in[6];
    const float* f_xpw   = (const float*)d_in[7];
    const float* f_dtw   = (const float*)d_in[8];
    const float* f_dtb   = (const float*)d_in[9];
    const float* f_D     = (const float*)d_in[10];
    const float* b_in_w  = (const float*)d_in[11];
    const float* b_cw    = (const float*)d_in[12];
    const float* b_cb    = (const float*)d_in[13];
    const float* b_Alog  = (const float*)d_in[14];
    const float* b_xpw   = (const float*)d_in[15];
    const float* b_dtw   = (const float*)d_in[16];
    const float* b_dtb   = (const float*)d_in[17];
    const float* b_D     = (const float*)d_in[18];
    const float* out_w   = (const float*)d_in[19];
    float* out = (float*)d_out;

    float *un, *xz, *xc, *xdbl, *dt, *ycat;
    cudaGetSymbolAddress((void**)&un,   g_un);
    cudaGetSymbolAddress((void**)&xz,   g_xz);
    cudaGetSymbolAddress((void**)&xc,   g_xc);
    cudaGetSymbolAddress((void**)&xdbl, g_xdbl);
    cudaGetSymbolAddress((void**)&dt,   g_dt);
    cudaGetSymbolAddress((void**)&ycat, g_ycat);
    float* xz0   = xz;             float* xz1   = xz   + (size_t)TT*2*DI;
    float* xc0   = xc;             float* xc1   = xc   + (size_t)TT*DI;
    float* xd0   = xdbl;           float* xd1   = xdbl + (size_t)TT*XDB;
    float* dt0   = dt;             float* dt1   = dt   + (size_t)TT*DI;

    // 1) layernorm
    ln_kernel<<<TT, 256>>>(u, norm_w, norm_b);

    // 2) in-proj both branches: (2048 x 768) x (768 -> 3072)
    sgemm_nt<<<dim3(3072/128, TT/128, 2), 256>>>(
        un, un, DM, f_in_w, b_in_w, xz0, xz1, 2*DI,
        TT, 2*DI, DM, 0, nullptr, nullptr, nullptr);

    // 3) conv + silu (causal fwd / anticausal bwd)
    conv_silu<<<dim3((TT*DI + 255)/256, 2), 256>>>(f_cw, f_cb, b_cw, b_cb);

    // 4) xproj: (2048 x 1536) x (1536 -> 128)
    sgemm_nt<<<dim3(XDB/128, TT/128, 2), 256>>>(
        xc0, xc1, DI, f_xpw, b_xpw, xd0, xd1, XDB,
        TT, XDB, DI, 0, nullptr, nullptr, nullptr);

    // 5) dt: (2048 x 96[stride 128]) x (96 -> 1536), + bias, softplus
    sgemm_nt<<<dim3(DI/128, TT/128, 2), 256>>>(
        xd0, xd1, XDB, f_dtw, b_dtw, dt0, dt1, DI,
        TT, DI, DTR, 1, f_dtb, b_dtb, nullptr);

    // 6) selective scan + gate, both directions
    scan_kernel<<<dim3(DI/8, Bb, 2), 128>>>(f_Alog, b_Alog, f_D, b_D);

    // 7) out-proj + residual: (2048 x 3072) x (3072 -> 768)
    sgemm_nt<<<dim3(DM/128, TT/128, 1), 256>>>(
        ycat, ycat, 2*DI, out_w, out_w, out, out, DM,
        TT, DM, 2*DI, 2, nullptr, nullptr, u);
}

// round 2
// speedup vs baseline: 1.6209x; 1.6209x over previous
#include <cuda_runtime.h>
#include <cuda_bf16.h>
#include <math.h>
#include <stdint.h>

#define Bb   2
#define Lseq 1024
#define DM   768
#define DI   1536
#define NS   16
#define DTR  96
#define XDB  (DTR + 2*NS)   // 128
#define TT   (Bb*Lseq)      // 2048

// ---------------- scratch ----------------
__device__ float g_un[TT*DM];
__device__ float g_xz[2][TT*2*DI];
__device__ float g_xc[2][TT*DI];
__device__ float g_xdbl[2][TT*XDB];
__device__ float g_dt[2][TT*DI];
__device__ float g_ycat[TT*2*DI];

__device__ __forceinline__ float totf(float x) {
    uint32_t r;
    asm("cvt.rna.tf32.f32 %0, %1;" : "=r"(r) : "f"(x));
    return __uint_as_float(r);
}

__device__ __forceinline__ void mma_tf32_16x8x8(
    float& c0, float& c1, float& c2, float& c3,
    uint32_t a0, uint32_t a1, uint32_t a2, uint32_t a3,
    uint32_t b0, uint32_t b1)
{
    asm volatile(
        "mma.sync.aligned.m16n8k8.row.col.f32.tf32.tf32.f32 "
        "{%0,%1,%2,%3}, {%4,%5,%6,%7}, {%8,%9}, {%0,%1,%2,%3};\n"
        : "+f"(c0), "+f"(c1), "+f"(c2), "+f"(c3)
        : "r"(a0), "r"(a1), "r"(a2), "r"(a3), "r"(b0), "r"(b1));
}

// ---------------- layernorm ----------------
__global__ __launch_bounds__(256) void ln_kernel(const float* __restrict__ u,
                                                 const float* __restrict__ w,
                                                 const float* __restrict__ bvec)
{
    int t = blockIdx.x;
    const float* row = u + (size_t)t * DM;
    float v[3];
    float s = 0.f, s2 = 0.f;
#pragma unroll
    for (int i = 0; i < 3; i++) {
        v[i] = row[threadIdx.x + i*256];
        s  += v[i];
        s2 += v[i]*v[i];
    }
#pragma unroll
    for (int o = 16; o; o >>= 1) {
        s  += __shfl_xor_sync(0xffffffffu, s,  o);
        s2 += __shfl_xor_sync(0xffffffffu, s2, o);
    }
    __shared__ float ss[8], ss2[8];
    int wid = threadIdx.x >> 5, ln = threadIdx.x & 31;
    if (ln == 0) { ss[wid] = s; ss2[wid] = s2; }
    __syncthreads();
    float ts = 0.f, ts2 = 0.f;
#pragma unroll
    for (int i = 0; i < 8; i++) { ts += ss[i]; ts2 += ss2[i]; }
    float mu  = ts * (1.f/DM);
    float var = ts2 * (1.f/DM) - mu*mu;
    float rs  = rsqrtf(var + 1e-5f);
#pragma unroll
    for (int i = 0; i < 3; i++) {
        int c = threadIdx.x + i*256;
        g_un[(size_t)t*DM + c] = (v[i]-mu)*rs*w[c] + bvec[c];
    }
}

// ---------------- TF32 tensor-core GEMM: C[m,n] = sum_k A[m,k]*W[n,k] ----------------
// mode 0: plain; mode 1: softplus(acc + bias[n]); mode 2: acc + resid[m,n]
// Requires BM == BN (row-loader shared between A and W), K % 16 == 0.
template<int BM, int BN, int WARPS_M, int WARPS_N>
__global__ void __launch_bounds__(WARPS_M*WARPS_N*32) gemm_tf32(
    const float* __restrict__ A0, const float* __restrict__ A1, int lda,
    const float* __restrict__ W0, const float* __restrict__ W1, int ldw,
    float* __restrict__ C0, float* __restrict__ C1, int ldc,
    int K, int mode,
    const float* __restrict__ bias0, const float* __restrict__ bias1,
    const float* __restrict__ resid)
{
    constexpr int WM = BM / WARPS_M;   // warp tile m
    constexpr int WN = BN / WARPS_N;   // warp tile n
    constexpr int MT = WM / 16;
    constexpr int NT = WN / 8;
    constexpr int SROW = 24;           // 16 data floats + 8 pad (bank-safe)

    const float* A    = blockIdx.z ? A1 : A0;
    const float* W    = blockIdx.z ? W1 : W0;
    float*       C    = blockIdx.z ? C1 : C0;
    const float* bias = blockIdx.z ? bias1 : bias0;

    __shared__ __align__(16) float As[BM * SROW];
    __shared__ __align__(16) float Bs[BN * SROW];

    int tid  = threadIdx.x;
    int lane = tid & 31;
    int w    = tid >> 5;
    int wm   = w / WARPS_N;
    int wn   = w % WARPS_N;
    int bm   = blockIdx.y * BM;
    int bn   = blockIdx.x * BN;

    // global staging: thread -> (row, 8-k-group)
    int row = tid >> 1;
    int g   = tid & 1;
    const float* aptr = A + (size_t)(bm + row) * lda + g * 8;
    const float* wptr = W + (size_t)(bn + row) * ldw + g * 8;

    float acc[MT][NT][4] = {};

    float4 av0 = *(const float4*)(aptr);
    float4 av1 = *(const float4*)(aptr + 4);
    float4 wv0 = *(const float4*)(wptr);
    float4 wv1 = *(const float4*)(wptr + 4);

    for (int k0 = 0; k0 < K; k0 += 16) {
        // store to shared with tf32 convert + (k, k+4) pairing
        {
            float2* as = (float2*)&As[row * SROW + g * 8];
            float2* bs = (float2*)&Bs[row * SROW + g * 8];
            as[0] = make_float2(totf(av0.x), totf(av1.x));
            as[1] = make_float2(totf(av0.y), totf(av1.y));
            as[2] = make_float2(totf(av0.z), totf(av1.z));
            as[3] = make_float2(totf(av0.w), totf(av1.w));
            bs[0] = make_float2(totf(wv0.x), totf(wv1.x));
            bs[1] = make_float2(totf(wv0.y), totf(wv1.y));
            bs[2] = make_float2(totf(wv0.z), totf(wv1.z));
            bs[3] = make_float2(totf(wv0.w), totf(wv1.w));
        }
        __syncthreads();

        aptr += 16; wptr += 16;
        if (k0 + 16 < K) {
            av0 = *(const float4*)(aptr);
            av1 = *(const float4*)(aptr + 4);
            wv0 = *(const float4*)(wptr);
            wv1 = *(const float4*)(wptr + 4);
        }

#pragma unroll
        for (int g2 = 0; g2 < 2; g2++) {
            int kcol = g2 * 8 + (lane & 3) * 2;
            uint32_t ar[MT][4];
#pragma unroll
            for (int i = 0; i < MT; i++) {
                int r0 = (wm * WM + i * 16 + (lane >> 2)) * SROW + kcol;
                float2 lo = *(const float2*)&As[r0];
                float2 hi = *(const float2*)&As[r0 + 8 * SROW];
                ar[i][0] = __float_as_uint(lo.x);
                ar[i][1] = __float_as_uint(hi.x);
                ar[i][2] = __float_as_uint(lo.y);
                ar[i][3] = __float_as_uint(hi.y);
            }
            uint32_t br[NT][2];
#pragma unroll
            for (int j = 0; j < NT; j++) {
                int r0 = (wn * WN + j * 8 + (lane >> 2)) * SROW + kcol;
                float2 bv = *(const float2*)&Bs[r0];
                br[j][0] = __float_as_uint(bv.x);
                br[j][1] = __float_as_uint(bv.y);
            }
#pragma unroll
            for (int i = 0; i < MT; i++)
#pragma unroll
                for (int j = 0; j < NT; j++)
                    mma_tf32_16x8x8(acc[i][j][0], acc[i][j][1],
                                    acc[i][j][2], acc[i][j][3],
                                    ar[i][0], ar[i][1], ar[i][2], ar[i][3],
                                    br[j][0], br[j][1]);
        }
        __syncthreads();
    }

    // epilogue
#pragma unroll
    for (int i = 0; i < MT; i++) {
        int m0 = bm + wm * WM + i * 16 + (lane >> 2);
#pragma unroll
        for (int j = 0; j < NT; j++) {
            int n0 = bn + wn * WN + j * 8 + (lane & 3) * 2;
            float v0 = acc[i][j][0], v1 = acc[i][j][1];
            float v2 = acc[i][j][2], v3 = acc[i][j][3];
            if (mode == 1) {
                float b0v = bias[n0], b1v = bias[n0 + 1];
                v0 += b0v; v1 += b1v; v2 += b0v; v3 += b1v;
                v0 = fmaxf(v0, 0.f) + log1pf(__expf(-fabsf(v0)));
                v1 = fmaxf(v1, 0.f) + log1pf(__expf(-fabsf(v1)));
                v2 = fmaxf(v2, 0.f) + log1pf(__expf(-fabsf(v2)));
                v3 = fmaxf(v3, 0.f) + log1pf(__expf(-fabsf(v3)));
            } else if (mode == 2) {
                const float2 r0 = *(const float2*)&resid[(size_t)m0 * ldc + n0];
                const float2 r1 = *(const float2*)&resid[(size_t)(m0+8) * ldc + n0];
                v0 += r0.x; v1 += r0.y; v2 += r1.x; v3 += r1.y;
            }
            *(float2*)&C[(size_t)m0 * ldc + n0]     = make_float2(v0, v1);
            *(float2*)&C[(size_t)(m0+8) * ldc + n0] = make_float2(v2, v3);
        }
    }
}

// ---------------- depthwise causal/anticausal conv (K=4) + silu ----------------
__global__ __launch_bounds__(256) void conv_silu(
    const float* __restrict__ cw0, const float* __restrict__ cb0,
    const float* __restrict__ cw1, const float* __restrict__ cb1)
{
    int br = blockIdx.y;
    const float* cw = br ? cw1 : cw0;
    const float* cb = br ? cb1 : cb0;
    const float* xz = g_xz[br];
    float*       xc = g_xc[br];

    int idx = blockIdx.x * 256 + threadIdx.x;
    if (idx >= TT*DI) return;
    int d = idx % DI;
    int t = idx / DI;
    int l = t % Lseq;

    float w0 = cw[d*4+0], w1 = cw[d*4+1], w2 = cw[d*4+2], w3 = cw[d*4+3];
    float acc = cb[d];
    if (br == 0) {
        acc += w3 * xz[(size_t)t*2*DI + d];
        if (l >= 1) acc += w2 * xz[(size_t)(t-1)*2*DI + d];
        if (l >= 2) acc += w1 * xz[(size_t)(t-2)*2*DI + d];
        if (l >= 3) acc += w0 * xz[(size_t)(t-3)*2*DI + d];
    } else {
        acc += w3 * xz[(size_t)t*2*DI + d];
        if (l+1 < Lseq) acc += w2 * xz[(size_t)(t+1)*2*DI + d];
        if (l+2 < Lseq) acc += w1 * xz[(size_t)(t+2)*2*DI + d];
        if (l+3 < Lseq) acc += w0 * xz[(size_t)(t+3)*2*DI + d];
    }
    float sg = 1.f / (1.f + __expf(-acc));
    xc[idx] = acc * sg;
}

// ---------------- selective scan ----------------
__global__ __launch_bounds__(128) void scan_kernel(
    const float* __restrict__ Alog0, const float* __restrict__ Alog1,
    const float* __restrict__ Dv0,   const float* __restrict__ Dv1)
{
    int br = blockIdx.z;
    int b  = blockIdx.y;
    const float* Alog = br ? Alog1 : Alog0;
    const float* Dvec = br ? Dv1   : Dv0;
    const float* dt   = g_dt[br];
    const float* xc   = g_xc[br];
    const float* xd   = g_xdbl[br];
    const float* xz   = g_xz[br];

    int lane = threadIdx.x & 31;
    int warp = threadIdx.x >> 5;
    int n    = lane & 15;
    int d    = blockIdx.x * 8 + warp * 2 + (lane >> 4);

    float A  = -__expf(Alog[d*NS + n]);
    float Dp = Dvec[d];
    float h  = 0.f;

    for (int s = 0; s < Lseq; s++) {
        int l = br ? (Lseq-1-s) : s;
        int t = b*Lseq + l;
        float dtv = dt[(size_t)t*DI + d];
        float xv  = xc[(size_t)t*DI + d];
        float Bv  = xd[(size_t)t*XDB + DTR + n];
        float Cv  = xd[(size_t)t*XDB + DTR + NS + n];
        float a   = __expf(dtv * A);
        h = fmaf(a, h, dtv * xv * Bv);
        float y = h * Cv;
        y += __shfl_xor_sync(0xffffffffu, y, 8);
        y += __shfl_xor_sync(0xffffffffu, y, 4);
        y += __shfl_xor_sync(0xffffffffu, y, 2);
        y += __shfl_xor_sync(0xffffffffu, y, 1);
        if (n == 0) {
            float z  = xz[(size_t)t*2*DI + DI + d];
            float sz = z / (1.f + __expf(-z));
            g_ycat[(size_t)t*2*DI + br*DI + d] = fmaf(xv, Dp, y) * sz;
        }
    }
}

// ---------------- launcher ----------------
extern "C" void kernel_launch(void* const* d_in, const int* in_sizes, int n_in,
                              void* d_out, int out_size)
{
    const float* u       = (const float*)d_in[0];
    const float* norm_w  = (const float*)d_in[1];
    const float* norm_b  = (const float*)d_in[2];
    const float* f_in_w  = (const float*)d_in[3];
    const float* f_cw    = (const float*)d_in[4];
    const float* f_cb    = (const float*)d_in[5];
    const float* f_Alog  = (const float*)d_in[6];
    const float* f_xpw   = (const float*)d_in[7];
    const float* f_dtw   = (const float*)d_in[8];
    const float* f_dtb   = (const float*)d_in[9];
    const float* f_D     = (const float*)d_in[10];
    const float* b_in_w  = (const float*)d_in[11];
    const float* b_cw    = (const float*)d_in[12];
    const float* b_cb    = (const float*)d_in[13];
    const float* b_Alog  = (const float*)d_in[14];
    const float* b_xpw   = (const float*)d_in[15];
    const float* b_dtw   = (const float*)d_in[16];
    const float* b_dtb   = (const float*)d_in[17];
    const float* b_D     = (const float*)d_in[18];
    const float* out_w   = (const float*)d_in[19];
    float* out = (float*)d_out;

    float *un, *xz, *xc, *xdbl, *dt, *ycat;
    cudaGetSymbolAddress((void**)&un,   g_un);
    cudaGetSymbolAddress((void**)&xz,   g_xz);
    cudaGetSymbolAddress((void**)&xc,   g_xc);
    cudaGetSymbolAddress((void**)&xdbl, g_xdbl);
    cudaGetSymbolAddress((void**)&dt,   g_dt);
    cudaGetSymbolAddress((void**)&ycat, g_ycat);
    float* xz0 = xz;   float* xz1 = xz   + (size_t)TT*2*DI;
    float* xc0 = xc;   float* xc1 = xc   + (size_t)TT*DI;
    float* xd0 = xdbl; float* xd1 = xdbl + (size_t)TT*XDB;
    float* dt0 = dt;   float* dt1 = dt   + (size_t)TT*DI;

    // 1) layernorm
    ln_kernel<<<TT, 256>>>(u, norm_w, norm_b);

    // 2) in-proj: (2048 x 768) -> 3072, both branches.  TF32, 128x128 tiles.
    gemm_tf32<128,128,4,2><<<dim3(2*DI/128, TT/128, 2), 256>>>(
        un, un, DM, f_in_w, b_in_w, DM, xz0, xz1, 2*DI,
        DM, 0, nullptr, nullptr, nullptr);

    // 3) conv + silu
    conv_silu<<<dim3((TT*DI + 255)/256, 2), 256>>>(f_cw, f_cb, b_cw, b_cb);

    // 4) xproj: (2048 x 1536) -> 128.  64x64 tiles for parallelism.
    gemm_tf32<64,64,2,2><<<dim3(XDB/64, TT/64, 2), 128>>>(
        xc0, xc1, DI, f_xpw, b_xpw, DI, xd0, xd1, XDB,
        DI, 0, nullptr, nullptr, nullptr);

    // 5) dt: (2048 x 96) -> 1536, bias + softplus.
    gemm_tf32<128,128,4,2><<<dim3(DI/128, TT/128, 2), 256>>>(
        xd0, xd1, XDB, f_dtw, b_dtw, DTR, dt0, dt1, DI,
        DTR, 1, f_dtb, b_dtb, nullptr);

    // 6) selective scan + gate
    scan_kernel<<<dim3(DI/8, Bb, 2), 128>>>(f_Alog, b_Alog, f_D, b_D);

    // 7) out-proj + residual: (2048 x 3072) -> 768.  64x64 tiles (384 blocks).
    gemm_tf32<64,64,2,2><<<dim3(DM/64, TT/64, 1), 128>>>(
        ycat, ycat, 2*DI, out_w, out_w, 2*DI, out, out, DM,
        2*DI, 2, nullptr, nullptr, u);
}

// round 3
// speedup vs baseline: 1.8417x; 1.1363x over previous
#include <cuda_runtime.h>
#include <cuda_bf16.h>
#include <math.h>
#include <stdint.h>

#define Bb   2
#define Lseq 1024
#define DM   768
#define DI   1536
#define NS   16
#define DTR  96
#define XDB  (DTR + 2*NS)   // 128
#define TT   (Bb*Lseq)      // 2048

// ---------------- scratch ----------------
__device__ float g_un[TT*DM];
__device__ float g_xz[2][TT*2*DI];
__device__ float g_xc[2][TT*DI];
__device__ float g_xdbl[2][TT*XDB];
__device__ float g_dt[2][TT*DI];
__device__ float g_ycat[TT*2*DI];

// ---------------- async copy helpers ----------------
__device__ __forceinline__ void cp16(float* dst, const float* src) {
    uint32_t s = (uint32_t)__cvta_generic_to_shared(dst);
    asm volatile("cp.async.ca.shared.global [%0], [%1], 16;\n" :: "r"(s), "l"(src));
}
__device__ __forceinline__ void cp_commit() {
    asm volatile("cp.async.commit_group;\n");
}
template<int N> __device__ __forceinline__ void cp_wait() {
    asm volatile("cp.async.wait_group %0;\n" :: "n"(N));
}

__device__ __forceinline__ void mma_tf32_16x8x8(
    float& c0, float& c1, float& c2, float& c3,
    uint32_t a0, uint32_t a1, uint32_t a2, uint32_t a3,
    uint32_t b0, uint32_t b1)
{
    asm volatile(
        "mma.sync.aligned.m16n8k8.row.col.f32.tf32.tf32.f32 "
        "{%0,%1,%2,%3}, {%4,%5,%6,%7}, {%8,%9}, {%0,%1,%2,%3};\n"
        : "+f"(c0), "+f"(c1), "+f"(c2), "+f"(c3)
        : "r"(a0), "r"(a1), "r"(a2), "r"(a3), "r"(b0), "r"(b1));
}

// ---------------- layernorm ----------------
__global__ __launch_bounds__(256) void ln_kernel(const float* __restrict__ u,
                                                 const float* __restrict__ w,
                                                 const float* __restrict__ bvec)
{
    int t = blockIdx.x;
    const float* row = u + (size_t)t * DM;
    float v[3];
    float s = 0.f, s2 = 0.f;
#pragma unroll
    for (int i = 0; i < 3; i++) {
        v[i] = row[threadIdx.x + i*256];
        s  += v[i];
        s2 += v[i]*v[i];
    }
#pragma unroll
    for (int o = 16; o; o >>= 1) {
        s  += __shfl_xor_sync(0xffffffffu, s,  o);
        s2 += __shfl_xor_sync(0xffffffffu, s2, o);
    }
    __shared__ float ss[8], ss2[8];
    int wid = threadIdx.x >> 5, ln = threadIdx.x & 31;
    if (ln == 0) { ss[wid] = s; ss2[wid] = s2; }
    __syncthreads();
    float ts = 0.f, ts2 = 0.f;
#pragma unroll
    for (int i = 0; i < 8; i++) { ts += ss[i]; ts2 += ss2[i]; }
    float mu  = ts * (1.f/DM);
    float var = ts2 * (1.f/DM) - mu*mu;
    float rs  = rsqrtf(var + 1e-5f);
#pragma unroll
    for (int i = 0; i < 3; i++) {
        int c = threadIdx.x + i*256;
        g_un[(size_t)t*DM + c] = (v[i]-mu)*rs*w[c] + bvec[c];
    }
}

// ---------------- TF32 GEMM, 3-stage cp.async pipeline ----------------
// C[m,n] = sum_k A[m,k] * W[n,k]
// mode 0: plain; mode 1: softplus(acc + bias[n]); mode 2: acc + resid[m,n]
// Requires THREADS == BM + BN, K % 16 == 0.
template<int BM, int BN, int WRM, int WRN>
__global__ void __launch_bounds__(WRM*WRN*32) gemm_cp(
    const float* __restrict__ A0, const float* __restrict__ A1, int lda,
    const float* __restrict__ W0, const float* __restrict__ W1, int ldw,
    float* __restrict__ C0, float* __restrict__ C1, int ldc,
    int K, int mode,
    const float* __restrict__ bias0, const float* __restrict__ bias1,
    const float* __restrict__ resid)
{
    constexpr int THREADS = WRM*WRN*32;
    static_assert(THREADS == BM + BN, "one loader thread per tile row");
    constexpr int WM = BM / WRM;
    constexpr int WN = BN / WRN;
    constexpr int MT = WM / 16;
    constexpr int NT = WN / 8;
    constexpr int SROW = 20;          // 16 data + 4 pad floats: (20r+c)%32 hits all banks
    constexpr int NST = 3;

    __shared__ __align__(16) float As[NST][BM*SROW];
    __shared__ __align__(16) float Bs[NST][BN*SROW];

    const float* A    = blockIdx.z ? A1 : A0;
    const float* W    = blockIdx.z ? W1 : W0;
    float*       C    = blockIdx.z ? C1 : C0;
    const float* bias = blockIdx.z ? bias1 : bias0;

    int tid  = threadIdx.x;
    int lane = tid & 31;
    int w    = tid >> 5;
    int wm   = w / WRN;
    int wn   = w % WRN;
    int bm   = blockIdx.y * BM;
    int bn   = blockIdx.x * BN;

    // one row per thread
    bool isB = tid >= BM;
    int  lrow = isB ? tid - BM : tid;
    const float* gp = isB ? (W + (size_t)(bn + lrow) * ldw)
                          : (A + (size_t)(bm + lrow) * lda);
    float* srow[NST];
#pragma unroll
    for (int s = 0; s < NST; s++)
        srow[s] = (isB ? &Bs[s][lrow*SROW] : &As[s][lrow*SROW]);

    int nk = K / 16;

    // prologue: prime 2 stages
    {
        const float* g = gp;
        cp16(srow[0],    g);    cp16(srow[0]+4,  g+4);
        cp16(srow[0]+8,  g+8);  cp16(srow[0]+12, g+12);
        cp_commit();
    }
    if (nk > 1) {
        const float* g = gp + 16;
        cp16(srow[1],    g);    cp16(srow[1]+4,  g+4);
        cp16(srow[1]+8,  g+8);  cp16(srow[1]+12, g+12);
        cp_commit();
    }

    float acc[MT][NT][4] = {};
    int r0 = lane >> 2;
    int c0 = lane & 3;

    for (int i = 0; i < nk; i++) {
        int st = i % NST;
        if (i + 2 < nk) {
            int st2 = (i + 2) % NST;
            const float* g = gp + (i + 2) * 16;
            cp16(srow[st2],    g);    cp16(srow[st2]+4,  g+4);
            cp16(srow[st2]+8,  g+8);  cp16(srow[st2]+12, g+12);
            cp_commit();
        }
        int rem = nk - 1 - i;
        if (rem >= 2)      cp_wait<2>();
        else if (rem == 1) cp_wait<1>();
        else               cp_wait<0>();
        __syncthreads();

        const float* as = As[st];
        const float* bs = Bs[st];
#pragma unroll
        for (int g2 = 0; g2 < 2; g2++) {
            int c = g2 * 8 + c0;
            uint32_t ar[MT][4];
            uint32_t br[NT][2];
#pragma unroll
            for (int ii = 0; ii < MT; ii++) {
                int r = (wm*WM + ii*16 + r0) * SROW + c;
                ar[ii][0] = __float_as_uint(as[r]);
                ar[ii][1] = __float_as_uint(as[r + 8*SROW]);
                ar[ii][2] = __float_as_uint(as[r + 4]);
                ar[ii][3] = __float_as_uint(as[r + 8*SROW + 4]);
            }
#pragma unroll
            for (int j = 0; j < NT; j++) {
                int r = (wn*WN + j*8 + r0) * SROW + c;
                br[j][0] = __float_as_uint(bs[r]);
                br[j][1] = __float_as_uint(bs[r + 4]);
            }
#pragma unroll
            for (int ii = 0; ii < MT; ii++)
#pragma unroll
                for (int j = 0; j < NT; j++)
                    mma_tf32_16x8x8(acc[ii][j][0], acc[ii][j][1],
                                    acc[ii][j][2], acc[ii][j][3],
                                    ar[ii][0], ar[ii][1], ar[ii][2], ar[ii][3],
                                    br[j][0], br[j][1]);
        }
        __syncthreads();
    }

    // epilogue
#pragma unroll
    for (int i = 0; i < MT; i++) {
        int m0 = bm + wm*WM + i*16 + r0;
#pragma unroll
        for (int j = 0; j < NT; j++) {
            int n0 = bn + wn*WN + j*8 + c0*2;
            float v0 = acc[i][j][0], v1 = acc[i][j][1];
            float v2 = acc[i][j][2], v3 = acc[i][j][3];
            if (mode == 1) {
                float b0v = bias[n0], b1v = bias[n0 + 1];
                v0 += b0v; v1 += b1v; v2 += b0v; v3 += b1v;
                v0 = fmaxf(v0, 0.f) + log1pf(__expf(-fabsf(v0)));
                v1 = fmaxf(v1, 0.f) + log1pf(__expf(-fabsf(v1)));
                v2 = fmaxf(v2, 0.f) + log1pf(__expf(-fabsf(v2)));
                v3 = fmaxf(v3, 0.f) + log1pf(__expf(-fabsf(v3)));
            } else if (mode == 2) {
                const float2 rr0 = *(const float2*)&resid[(size_t)m0 * ldc + n0];
                const float2 rr1 = *(const float2*)&resid[(size_t)(m0+8) * ldc + n0];
                v0 += rr0.x; v1 += rr0.y; v2 += rr1.x; v3 += rr1.y;
            }
            *(float2*)&C[(size_t)m0 * ldc + n0]     = make_float2(v0, v1);
            *(float2*)&C[(size_t)(m0+8) * ldc + n0] = make_float2(v2, v3);
        }
    }
}

// ---------------- depthwise causal/anticausal conv (K=4) + silu ----------------
__global__ __launch_bounds__(256) void conv_silu(
    const float* __restrict__ cw0, const float* __restrict__ cb0,
    const float* __restrict__ cw1, const float* __restrict__ cb1)
{
    int br = blockIdx.y;
    const float* cw = br ? cw1 : cw0;
    const float* cb = br ? cb1 : cb0;
    const float* xz = g_xz[br];
    float*       xc = g_xc[br];

    int idx = blockIdx.x * 256 + threadIdx.x;
    if (idx >= TT*DI) return;
    int d = idx % DI;
    int t = idx / DI;
    int l = t % Lseq;

    float w0 = cw[d*4+0], w1 = cw[d*4+1], w2 = cw[d*4+2], w3 = cw[d*4+3];
    float acc = cb[d];
    if (br == 0) {
        acc += w3 * xz[(size_t)t*2*DI + d];
        if (l >= 1) acc += w2 * xz[(size_t)(t-1)*2*DI + d];
        if (l >= 2) acc += w1 * xz[(size_t)(t-2)*2*DI + d];
        if (l >= 3) acc += w0 * xz[(size_t)(t-3)*2*DI + d];
    } else {
        acc += w3 * xz[(size_t)t*2*DI + d];
        if (l+1 < Lseq) acc += w2 * xz[(size_t)(t+1)*2*DI + d];
        if (l+2 < Lseq) acc += w1 * xz[(size_t)(t+2)*2*DI + d];
        if (l+3 < Lseq) acc += w0 * xz[(size_t)(t+3)*2*DI + d];
    }
    float sg = 1.f / (1.f + __expf(-acc));
    xc[idx] = acc * sg;
}

// ---------------- selective scan (prefetched) ----------------
__global__ __launch_bounds__(128) void scan_kernel(
    const float* __restrict__ Alog0, const float* __restrict__ Alog1,
    const float* __restrict__ Dv0,   const float* __restrict__ Dv1)
{
    int br = blockIdx.z;
    int b  = blockIdx.y;
    const float* Alog = br ? Alog1 : Alog0;
    const float* Dvec = br ? Dv1   : Dv0;
    const float* dt   = g_dt[br];
    const float* xc   = g_xc[br];
    const float* xd   = g_xdbl[br];
    const float* xz   = g_xz[br];

    int lane = threadIdx.x & 31;
    int warp = threadIdx.x >> 5;
    int n    = lane & 15;
    int d    = blockIdx.x * 8 + warp * 2 + (lane >> 4);

    float A  = -__expf(Alog[d*NS + n]);
    float Dp = Dvec[d];
    float h  = 0.f;

    int t0   = b*Lseq + (br ? Lseq-1 : 0);
    int step = br ? -1 : 1;

    int t = t0;
    float dtv = dt[(size_t)t*DI + d];
    float xv  = xc[(size_t)t*DI + d];
    float Bv  = xd[(size_t)t*XDB + DTR + n];
    float Cv  = xd[(size_t)t*XDB + DTR + NS + n];

    for (int s = 0; s < Lseq; s++) {
        // prefetch next step (independent of recurrence)
        float ndt = 0.f, nx = 0.f, nB = 0.f, nC = 0.f;
        int tn = t + step;
        if (s + 1 < Lseq) {
            ndt = dt[(size_t)tn*DI + d];
            nx  = xc[(size_t)tn*DI + d];
            nB  = xd[(size_t)tn*XDB + DTR + n];
            nC  = xd[(size_t)tn*XDB + DTR + NS + n];
        }
        float a = __expf(dtv * A);
        h = fmaf(a, h, dtv * xv * Bv);
        float y = h * Cv;
        y += __shfl_xor_sync(0xffffffffu, y, 8);
        y += __shfl_xor_sync(0xffffffffu, y, 4);
        y += __shfl_xor_sync(0xffffffffu, y, 2);
        y += __shfl_xor_sync(0xffffffffu, y, 1);
        if (n == 0) {
            float z  = xz[(size_t)t*2*DI + DI + d];
            float sz = z / (1.f + __expf(-z));
            g_ycat[(size_t)t*2*DI + br*DI + d] = fmaf(xv, Dp, y) * sz;
        }
        dtv = ndt; xv = nx; Bv = nB; Cv = nC; t = tn;
    }
}

// ---------------- launcher ----------------
extern "C" void kernel_launch(void* const* d_in, const int* in_sizes, int n_in,
                              void* d_out, int out_size)
{
    const float* u       = (const float*)d_in[0];
    const float* norm_w  = (const float*)d_in[1];
    const float* norm_b  = (const float*)d_in[2];
    const float* f_in_w  = (const float*)d_in[3];
    const float* f_cw    = (const float*)d_in[4];
    const float* f_cb    = (const float*)d_in[5];
    const float* f_Alog  = (const float*)d_in[6];
    const float* f_xpw   = (const float*)d_in[7];
    const float* f_dtw   = (const float*)d_in[8];
    const float* f_dtb   = (const float*)d_in[9];
    const float* f_D     = (const float*)d_in[10];
    const float* b_in_w  = (const float*)d_in[11];
    const float* b_cw    = (const float*)d_in[12];
    const float* b_cb    = (const float*)d_in[13];
    const float* b_Alog  = (const float*)d_in[14];
    const float* b_xpw   = (const float*)d_in[15];
    const float* b_dtw   = (const float*)d_in[16];
    const float* b_dtb   = (const float*)d_in[17];
    const float* b_D     = (const float*)d_in[18];
    const float* out_w   = (const float*)d_in[19];
    float* out = (float*)d_out;

    float *un, *xz, *xc, *xdbl, *dt, *ycat;
    cudaGetSymbolAddress((void**)&un,   g_un);
    cudaGetSymbolAddress((void**)&xz,   g_xz);
    cudaGetSymbolAddress((void**)&xc,   g_xc);
    cudaGetSymbolAddress((void**)&xdbl, g_xdbl);
    cudaGetSymbolAddress((void**)&dt,   g_dt);
    cudaGetSymbolAddress((void**)&ycat, g_ycat);
    float* xz0 = xz;   float* xz1 = xz   + (size_t)TT*2*DI;
    float* xc0 = xc;   float* xc1 = xc   + (size_t)TT*DI;
    float* xd0 = xdbl; float* xd1 = xdbl + (size_t)TT*XDB;
    float* dt0 = dt;   float* dt1 = dt   + (size_t)TT*DI;

    // 1) layernorm
    ln_kernel<<<TT, 256>>>(u, norm_w, norm_b);

    // 2) in-proj: (2048 x 768) -> 3072, both branches
    gemm_cp<128,128,4,2><<<dim3(2*DI/128, TT/128, 2), 256>>>(
        un, un, DM, f_in_w, b_in_w, DM, xz0, xz1, 2*DI,
        DM, 0, nullptr, nullptr, nullptr);

    // 3) conv + silu
    conv_silu<<<dim3((TT*DI + 255)/256, 2), 256>>>(f_cw, f_cb, b_cw, b_cb);

    // 4) xproj: (2048 x 1536) -> 128
    gemm_cp<64,64,2,2><<<dim3(XDB/64, TT/64, 2), 128>>>(
        xc0, xc1, DI, f_xpw, b_xpw, DI, xd0, xd1, XDB,
        DI, 0, nullptr, nullptr, nullptr);

    // 5) dt: (2048 x 96) -> 1536, bias + softplus
    gemm_cp<128,128,4,2><<<dim3(DI/128, TT/128, 2), 256>>>(
        xd0, xd1, XDB, f_dtw, b_dtw, DTR, dt0, dt1, DI,
        DTR, 1, f_dtb, b_dtb, nullptr);

    // 6) selective scan + gate
    scan_kernel<<<dim3(DI/8, Bb, 2), 128>>>(f_Alog, b_Alog, f_D, b_D);

    // 7) out-proj + residual: (2048 x 3072) -> 768
    gemm_cp<64,64,2,2><<<dim3(DM/64, TT/64, 1), 128>>>(
        ycat, ycat, 2*DI, out_w, out_w, 2*DI, out, out, DM,
        2*DI, 2, nullptr, nullptr, u);
}

// round 4
// speedup vs baseline: 2.6554x; 1.4418x over previous
#include <cuda_runtime.h>
#include <cuda_bf16.h>
#include <math.h>
#include <stdint.h>

#define Bb   2
#define Lseq 1024
#define DM   768
#define DI   1536
#define NS   16
#define DTR  96
#define XDB  (DTR + 2*NS)   // 128
#define TT   (Bb*Lseq)      // 2048

#define IN_W  (2*DI*DM)     // 2359296
#define XP_W  (XDB*DI)      // 196608
#define DT_W  (DI*DTR)      // 147456
#define OUT_W (DM*2*DI)     // 2359296
#define WTOT  (2*IN_W + 2*XP_W + 2*DT_W + OUT_W)

// ---------------- fp32 scratch ----------------
__device__ float g_xz[2][TT*2*DI];
__device__ float g_xc[2][TT*DI];
__device__ float g_xdbl[2][TT*XDB];
__device__ float g_dt[2][TT*DI];
// ---------------- bf16 scratch ----------------
__device__ __nv_bfloat16 g_un_bf[TT*DM];
__device__ __nv_bfloat16 g_xc_bf[2][TT*DI];
__device__ __nv_bfloat16 g_xd_bf[2][TT*XDB];
__device__ __nv_bfloat16 g_ycat_bf[TT*2*DI];
__device__ __nv_bfloat16 g_inw_bf[2][IN_W];
__device__ __nv_bfloat16 g_xpw_bf[2][XP_W];
__device__ __nv_bfloat16 g_dtw_bf[2][DT_W];
__device__ __nv_bfloat16 g_outw_bf[OUT_W];

// ---------------- async copy helpers ----------------
__device__ __forceinline__ void cp16(void* dst, const void* src) {
    uint32_t s = (uint32_t)__cvta_generic_to_shared(dst);
    asm volatile("cp.async.ca.shared.global [%0], [%1], 16;\n" :: "r"(s), "l"(src));
}
__device__ __forceinline__ void cp_commit() {
    asm volatile("cp.async.commit_group;\n");
}
template<int N> __device__ __forceinline__ void cp_wait() {
    asm volatile("cp.async.wait_group %0;\n" :: "n"(N));
}

__device__ __forceinline__ void mma_bf16(
    float& c0, float& c1, float& c2, float& c3,
    uint32_t a0, uint32_t a1, uint32_t a2, uint32_t a3,
    uint32_t b0, uint32_t b1)
{
    asm volatile(
        "mma.sync.aligned.m16n8k16.row.col.f32.bf16.bf16.f32 "
        "{%0,%1,%2,%3}, {%4,%5,%6,%7}, {%8,%9}, {%0,%1,%2,%3};\n"
        : "+f"(c0), "+f"(c1), "+f"(c2), "+f"(c3)
        : "r"(a0), "r"(a1), "r"(a2), "r"(a3), "r"(b0), "r"(b1));
}

// ---------------- weight conversion ----------------
__global__ __launch_bounds__(256) void cvt_weights(
    const float* __restrict__ fw, const float* __restrict__ bw,
    const float* __restrict__ fx, const float* __restrict__ bx,
    const float* __restrict__ fd, const float* __restrict__ bd,
    const float* __restrict__ ow)
{
    int i = blockIdx.x * 256 + threadIdx.x;
    if (i < IN_W)  { g_inw_bf[0][i] = __float2bfloat16(fw[i]); return; }
    i -= IN_W;
    if (i < IN_W)  { g_inw_bf[1][i] = __float2bfloat16(bw[i]); return; }
    i -= IN_W;
    if (i < XP_W)  { g_xpw_bf[0][i] = __float2bfloat16(fx[i]); return; }
    i -= XP_W;
    if (i < XP_W)  { g_xpw_bf[1][i] = __float2bfloat16(bx[i]); return; }
    i -= XP_W;
    if (i < DT_W)  { g_dtw_bf[0][i] = __float2bfloat16(fd[i]); return; }
    i -= DT_W;
    if (i < DT_W)  { g_dtw_bf[1][i] = __float2bfloat16(bd[i]); return; }
    i -= DT_W;
    if (i < OUT_W) { g_outw_bf[i]   = __float2bfloat16(ow[i]); }
}

// ---------------- layernorm (bf16 out) ----------------
__global__ __launch_bounds__(256) void ln_kernel(const float* __restrict__ u,
                                                 const float* __restrict__ w,
                                                 const float* __restrict__ bvec)
{
    int t = blockIdx.x;
    const float* row = u + (size_t)t * DM;
    float v[3];
    float s = 0.f, s2 = 0.f;
#pragma unroll
    for (int i = 0; i < 3; i++) {
        v[i] = row[threadIdx.x + i*256];
        s  += v[i];
        s2 += v[i]*v[i];
    }
#pragma unroll
    for (int o = 16; o; o >>= 1) {
        s  += __shfl_xor_sync(0xffffffffu, s,  o);
        s2 += __shfl_xor_sync(0xffffffffu, s2, o);
    }
    __shared__ float ss[8], ss2[8];
    int wid = threadIdx.x >> 5, ln = threadIdx.x & 31;
    if (ln == 0) { ss[wid] = s; ss2[wid] = s2; }
    __syncthreads();
    float ts = 0.f, ts2 = 0.f;
#pragma unroll
    for (int i = 0; i < 8; i++) { ts += ss[i]; ts2 += ss2[i]; }
    float mu  = ts * (1.f/DM);
    float var = ts2 * (1.f/DM) - mu*mu;
    float rs  = rsqrtf(var + 1e-5f);
#pragma unroll
    for (int i = 0; i < 3; i++) {
        int c = threadIdx.x + i*256;
        g_un_bf[(size_t)t*DM + c] = __float2bfloat16((v[i]-mu)*rs*w[c] + bvec[c]);
    }
}

// ---------------- bf16 HMMA GEMM, 3-stage cp.async pipeline ----------------
// C[m,n] = sum_k A[m,k] * W[n,k];  A,W bf16; acc fp32.
// mode 0: plain fp32 (+ optional bf16 dual-store); 1: softplus(acc+bias); 2: acc+resid
template<int BM, int BN, int WRM, int WRN, int THREADS>
__global__ void __launch_bounds__(THREADS) gemm_bf16(
    const __nv_bfloat16* __restrict__ A0, const __nv_bfloat16* __restrict__ A1, int lda,
    const __nv_bfloat16* __restrict__ W0, const __nv_bfloat16* __restrict__ W1, int ldw,
    float* __restrict__ C0, float* __restrict__ C1, int ldc,
    __nv_bfloat16* __restrict__ Cb0, __nv_bfloat16* __restrict__ Cb1,
    int K, int mode,
    const float* __restrict__ bias0, const float* __restrict__ bias1,
    const float* __restrict__ resid)
{
    constexpr int WM = BM / WRM;
    constexpr int WN = BN / WRN;
    constexpr int MT = WM / 16;
    constexpr int NT = WN / 8;
    constexpr int SROW = 20;                 // 32-bit words/row: 16 data + 4 pad
    constexpr int NST  = 3;
    constexpr int SWORDS = (BM + BN) * SROW; // words per stage
    constexpr int CH  = (BM + BN) * 4;       // 16B chunks per slab
    constexpr int LPT = CH / THREADS;
    static_assert(CH % THREADS == 0, "loader divisibility");

    extern __shared__ uint32_t sm[];

    const __nv_bfloat16* A = blockIdx.z ? A1 : A0;
    const __nv_bfloat16* W = blockIdx.z ? W1 : W0;
    float*            C    = blockIdx.z ? C1 : C0;
    __nv_bfloat16*    Cb   = blockIdx.z ? Cb1 : Cb0;
    const float*      bias = blockIdx.z ? bias1 : bias0;

    int tid  = threadIdx.x;
    int lane = tid & 31;
    int w    = tid >> 5;
    int wm   = w / WRN;
    int wn   = w % WRN;
    int bm   = blockIdx.y * BM;
    int bn   = blockIdx.x * BN;
    int r0   = lane >> 2;
    int c0   = lane & 3;

    // loader assignments
    const __nv_bfloat16* lsrc[LPT];
    uint32_t ldst[LPT];
#pragma unroll
    for (int u = 0; u < LPT; u++) {
        int i   = tid + u * THREADS;
        int row = i >> 2;
        int ch  = i & 3;
        if (row < BM) {
            lsrc[u] = A + (size_t)(bm + row) * lda + ch * 8;
            ldst[u] = row * SROW + ch * 4;
        } else {
            int r = row - BM;
            lsrc[u] = W + (size_t)(bn + r) * ldw + ch * 8;
            ldst[u] = BM * SROW + r * SROW + ch * 4;
        }
    }

    int nk = K / 32;
#pragma unroll
    for (int p = 0; p < 2; p++) {
        if (p < nk) {
#pragma unroll
            for (int u = 0; u < LPT; u++)
                cp16(&sm[p*SWORDS + ldst[u]], lsrc[u] + p*32);
            cp_commit();
        }
    }

    float acc[MT][NT][4] = {};

    for (int i = 0; i < nk; i++) {
        int st = i % NST;
        if (i + 2 < nk) {
            int st2 = (i + 2) % NST;
#pragma unroll
            for (int u = 0; u < LPT; u++)
                cp16(&sm[st2*SWORDS + ldst[u]], lsrc[u] + (i+2)*32);
            cp_commit();
        }
        int rem = nk - 1 - i;
        if (rem >= 2)      cp_wait<2>();
        else if (rem == 1) cp_wait<1>();
        else               cp_wait<0>();
        __syncthreads();

        const uint32_t* as = &sm[st*SWORDS];
        const uint32_t* bs = &sm[st*SWORDS + BM*SROW];
#pragma unroll
        for (int kk = 0; kk < 2; kk++) {        // two k16 steps per k32 slab
            int cw = kk * 8 + c0;
            uint32_t ar[MT][4];
            uint32_t br[NT][2];
#pragma unroll
            for (int ii = 0; ii < MT; ii++) {
                int base = (wm*WM + ii*16 + r0) * SROW + cw;
                ar[ii][0] = as[base];
                ar[ii][1] = as[base + 8*SROW];
                ar[ii][2] = as[base + 4];
                ar[ii][3] = as[base + 8*SROW + 4];
            }
#pragma unroll
            for (int j = 0; j < NT; j++) {
                int base = (wn*WN + j*8 + r0) * SROW + cw;
                br[j][0] = bs[base];
                br[j][1] = bs[base + 4];
            }
#pragma unroll
            for (int ii = 0; ii < MT; ii++)
#pragma unroll
                for (int j = 0; j < NT; j++)
                    mma_bf16(acc[ii][j][0], acc[ii][j][1],
                             acc[ii][j][2], acc[ii][j][3],
                             ar[ii][0], ar[ii][1], ar[ii][2], ar[ii][3],
                             br[j][0], br[j][1]);
        }
        __syncthreads();
    }

    // epilogue
#pragma unroll
    for (int i = 0; i < MT; i++) {
        int m0 = bm + wm*WM + i*16 + r0;
#pragma unroll
        for (int j = 0; j < NT; j++) {
            int n0 = bn + wn*WN + j*8 + c0*2;
            float v0 = acc[i][j][0], v1 = acc[i][j][1];
            float v2 = acc[i][j][2], v3 = acc[i][j][3];
            if (mode == 1) {
                float b0v = bias[n0], b1v = bias[n0 + 1];
                v0 += b0v; v1 += b1v; v2 += b0v; v3 += b1v;
                v0 = fmaxf(v0, 0.f) + log1pf(__expf(-fabsf(v0)));
                v1 = fmaxf(v1, 0.f) + log1pf(__expf(-fabsf(v1)));
                v2 = fmaxf(v2, 0.f) + log1pf(__expf(-fabsf(v2)));
                v3 = fmaxf(v3, 0.f) + log1pf(__expf(-fabsf(v3)));
            } else if (mode == 2) {
                const float2 rr0 = *(const float2*)&resid[(size_t)m0 * ldc + n0];
                const float2 rr1 = *(const float2*)&resid[(size_t)(m0+8) * ldc + n0];
                v0 += rr0.x; v1 += rr0.y; v2 += rr1.x; v3 += rr1.y;
            }
            *(float2*)&C[(size_t)m0 * ldc + n0]     = make_float2(v0, v1);
            *(float2*)&C[(size_t)(m0+8) * ldc + n0] = make_float2(v2, v3);
            if (Cb) {
                *(__nv_bfloat162*)&Cb[(size_t)m0 * ldc + n0] =
                    __float22bfloat162_rn(make_float2(v0, v1));
                *(__nv_bfloat162*)&Cb[(size_t)(m0+8) * ldc + n0] =
                    __float22bfloat162_rn(make_float2(v2, v3));
            }
        }
    }
}

// ---------------- depthwise conv (K=4) + silu; fp32 + bf16 out ----------------
__global__ __launch_bounds__(256) void conv_silu(
    const float* __restrict__ cw0, const float* __restrict__ cb0,
    const float* __restrict__ cw1, const float* __restrict__ cb1)
{
    int br = blockIdx.y;
    const float* cw = br ? cw1 : cw0;
    const float* cb = br ? cb1 : cb0;
    const float* xz = g_xz[br];

    int idx = blockIdx.x * 256 + threadIdx.x;
    if (idx >= TT*DI) return;
    int d = idx % DI;
    int t = idx / DI;
    int l = t % Lseq;

    float w0 = cw[d*4+0], w1 = cw[d*4+1], w2 = cw[d*4+2], w3 = cw[d*4+3];
    float acc = cb[d];
    if (br == 0) {
        acc += w3 * xz[(size_t)t*2*DI + d];
        if (l >= 1) acc += w2 * xz[(size_t)(t-1)*2*DI + d];
        if (l >= 2) acc += w1 * xz[(size_t)(t-2)*2*DI + d];
        if (l >= 3) acc += w0 * xz[(size_t)(t-3)*2*DI + d];
    } else {
        acc += w3 * xz[(size_t)t*2*DI + d];
        if (l+1 < Lseq) acc += w2 * xz[(size_t)(t+1)*2*DI + d];
        if (l+2 < Lseq) acc += w1 * xz[(size_t)(t+2)*2*DI + d];
        if (l+3 < Lseq) acc += w0 * xz[(size_t)(t+3)*2*DI + d];
    }
    float sg = 1.f / (1.f + __expf(-acc));
    float o  = acc * sg;
    g_xc[br][idx]    = o;
    g_xc_bf[br][idx] = __float2bfloat16(o);
}

// ---------------- selective scan (prefetched; bf16 ycat out) ----------------
__global__ __launch_bounds__(128) void scan_kernel(
    const float* __restrict__ Alog0, const float* __restrict__ Alog1,
    const float* __restrict__ Dv0,   const float* __restrict__ Dv1)
{
    int br = blockIdx.z;
    int b  = blockIdx.y;
    const float* Alog = br ? Alog1 : Alog0;
    const float* Dvec = br ? Dv1   : Dv0;
    const float* dt   = g_dt[br];
    const float* xc   = g_xc[br];
    const float* xd   = g_xdbl[br];
    const float* xz   = g_xz[br];

    int lane = threadIdx.x & 31;
    int warp = threadIdx.x >> 5;
    int n    = lane & 15;
    int d    = blockIdx.x * 8 + warp * 2 + (lane >> 4);

    float A  = -__expf(Alog[d*NS + n]);
    float Dp = Dvec[d];
    float h  = 0.f;

    int step = br ? -1 : 1;
    int t = b*Lseq + (br ? Lseq-1 : 0);
    float dtv = dt[(size_t)t*DI + d];
    float xv  = xc[(size_t)t*DI + d];
    float Bv  = xd[(size_t)t*XDB + DTR + n];
    float Cv  = xd[(size_t)t*XDB + DTR + NS + n];

    for (int s = 0; s < Lseq; s++) {
        float ndt = 0.f, nx = 0.f, nB = 0.f, nC = 0.f;
        int tn = t + step;
        if (s + 1 < Lseq) {
            ndt = dt[(size_t)tn*DI + d];
            nx  = xc[(size_t)tn*DI + d];
            nB  = xd[(size_t)tn*XDB + DTR + n];
            nC  = xd[(size_t)tn*XDB + DTR + NS + n];
        }
        float a = __expf(dtv * A);
        h = fmaf(a, h, dtv * xv * Bv);
        float y = h * Cv;
        y += __shfl_xor_sync(0xffffffffu, y, 8);
        y += __shfl_xor_sync(0xffffffffu, y, 4);
        y += __shfl_xor_sync(0xffffffffu, y, 2);
        y += __shfl_xor_sync(0xffffffffu, y, 1);
        if (n == 0) {
            float z  = xz[(size_t)t*2*DI + DI + d];
            float sz = z / (1.f + __expf(-z));
            g_ycat_bf[(size_t)t*2*DI + br*DI + d] =
                __float2bfloat16(fmaf(xv, Dp, y) * sz);
        }
        dtv = ndt; xv = nx; Bv = nB; Cv = nC; t = tn;
    }
}

// ---------------- launcher ----------------
extern "C" void kernel_launch(void* const* d_in, const int* in_sizes, int n_in,
                              void* d_out, int out_size)
{
    const float* u       = (const float*)d_in[0];
    const float* norm_w  = (const float*)d_in[1];
    const float* norm_b  = (const float*)d_in[2];
    const float* f_in_w  = (const float*)d_in[3];
    const float* f_cw    = (const float*)d_in[4];
    const float* f_cb    = (const float*)d_in[5];
    const float* f_Alog  = (const float*)d_in[6];
    const float* f_xpw   = (const float*)d_in[7];
    const float* f_dtw   = (const float*)d_in[8];
    const float* f_dtb   = (const float*)d_in[9];
    const float* f_D     = (const float*)d_in[10];
    const float* b_in_w  = (const float*)d_in[11];
    const float* b_cw    = (const float*)d_in[12];
    const float* b_cb    = (const float*)d_in[13];
    const float* b_Alog  = (const float*)d_in[14];
    const float* b_xpw   = (const float*)d_in[15];
    const float* b_dtw   = (const float*)d_in[16];
    const float* b_dtb   = (const float*)d_in[17];
    const float* b_D     = (const float*)d_in[18];
    const float* out_w   = (const float*)d_in[19];
    float* out = (float*)d_out;

    float *xz, *xc, *xdbl, *dt;
    __nv_bfloat16 *un_bf, *xc_bf, *xd_bf, *ycat_bf;
    __nv_bfloat16 *inw_bf, *xpw_bf, *dtw_bf, *outw_bf;
    cudaGetSymbolAddress((void**)&xz,     g_xz);
    cudaGetSymbolAddress((void**)&xc,     g_xc);
    cudaGetSymbolAddress((void**)&xdbl,   g_xdbl);
    cudaGetSymbolAddress((void**)&dt,     g_dt);
    cudaGetSymbolAddress((void**)&un_bf,  g_un_bf);
    cudaGetSymbolAddress((void**)&xc_bf,  g_xc_bf);
    cudaGetSymbolAddress((void**)&xd_bf,  g_xd_bf);
    cudaGetSymbolAddress((void**)&ycat_bf,g_ycat_bf);
    cudaGetSymbolAddress((void**)&inw_bf, g_inw_bf);
    cudaGetSymbolAddress((void**)&xpw_bf, g_xpw_bf);
    cudaGetSymbolAddress((void**)&dtw_bf, g_dtw_bf);
    cudaGetSymbolAddress((void**)&outw_bf,g_outw_bf);

    float* xz0 = xz;   float* xz1 = xz   + (size_t)TT*2*DI;
    float* xd0 = xdbl; float* xd1 = xdbl + (size_t)TT*XDB;
    float* dt0 = dt;   float* dt1 = dt   + (size_t)TT*DI;
    __nv_bfloat16* xcb0 = xc_bf;  __nv_bfloat16* xcb1 = xc_bf + (size_t)TT*DI;
    __nv_bfloat16* xdb0 = xd_bf;  __nv_bfloat16* xdb1 = xd_bf + (size_t)TT*XDB;
    __nv_bfloat16* inw0 = inw_bf; __nv_bfloat16* inw1 = inw_bf + (size_t)IN_W;
    __nv_bfloat16* xpw0 = xpw_bf; __nv_bfloat16* xpw1 = xpw_bf + (size_t)XP_W;
    __nv_bfloat16* dtw0 = dtw_bf; __nv_bfloat16* dtw1 = dtw_bf + (size_t)DT_W;

    constexpr int SM_BIG = 3 * 256 * 20 * 4;   // 61440
    constexpr int SM_XP  = 3 *  96 * 20 * 4;   // 23040
    constexpr int SM_OUT = 3 * 128 * 20 * 4;   // 30720
    cudaFuncSetAttribute((const void*)gemm_bf16<128,128,4,2,256>,
        cudaFuncAttributeMaxDynamicSharedMemorySize, SM_BIG);
    cudaFuncSetAttribute((const void*)gemm_bf16<32,64,2,2,128>,
        cudaFuncAttributeMaxDynamicSharedMemorySize, SM_XP);
    cudaFuncSetAttribute((const void*)gemm_bf16<64,64,2,2,128>,
        cudaFuncAttributeMaxDynamicSharedMemorySize, SM_OUT);

    // 0) weights -> bf16
    cvt_weights<<<(WTOT + 255)/256, 256>>>(f_in_w, b_in_w, f_xpw, b_xpw,
                                           f_dtw, b_dtw, out_w);
    // 1) layernorm -> bf16
    ln_kernel<<<TT, 256>>>(u, norm_w, norm_b);

    // 2) in-proj: (2048x768) -> 3072, fp32 out
    gemm_bf16<128,128,4,2,256><<<dim3(2*DI/128, TT/128, 2), 256, SM_BIG>>>(
        un_bf, un_bf, DM, inw0, inw1, DM, xz0, xz1, 2*DI,
        nullptr, nullptr, DM, 0, nullptr, nullptr, nullptr);

    // 3) conv + silu -> fp32 + bf16
    conv_silu<<<dim3((TT*DI + 255)/256, 2), 256>>>(f_cw, f_cb, b_cw, b_cb);

    // 4) xproj: (2048x1536) -> 128, fp32 + bf16 out
    gemm_bf16<32,64,2,2,128><<<dim3(XDB/64, TT/32, 2), 128, SM_XP>>>(
        xcb0, xcb1, DI, xpw0, xpw1, DI, xd0, xd1, XDB,
        xdb0, xdb1, DI, 0, nullptr, nullptr, nullptr);

    // 5) dt: (2048x96) -> 1536, softplus+bias, fp32 out
    gemm_bf16<128,128,4,2,256><<<dim3(DI/128, TT/128, 2), 256, SM_BIG>>>(
        xdb0, xdb1, XDB, dtw0, dtw1, DTR, dt0, dt1, DI,
        nullptr, nullptr, XDB, 1, f_dtb, b_dtb, nullptr);

    // 6) selective scan + gate -> bf16 ycat
    scan_kernel<<<dim3(DI/8, Bb, 2), 128>>>(f_Alog, b_Alog, f_D, b_D);

    // 7) out-proj + residual: (2048x3072) -> 768, fp32 out
    gemm_bf16<64,64,2,2,128><<<dim3(DM/64, TT/64, 1), 128, SM_OUT>>>(
        ycat_bf, ycat_bf, 2*DI, outw_bf, outw_bf, 2*DI, out, out, DM,
        nullptr, nullptr, 2*DI, 2, nullptr, nullptr, u);
}

// round 5
// speedup vs baseline: 2.7214x; 1.0248x over previous
#include <cuda_runtime.h>
#include <cuda_bf16.h>
#include <math.h>
#include <stdint.h>

#define Bb   2
#define Lseq 1024
#define DM   768
#define DI   1536
#define NS   16
#define DTR  96
#define XDB  (DTR + 2*NS)   // 128
#define TT   (Bb*Lseq)      // 2048

#define IN_W  (2*DI*DM)
#define XP_W  (XDB*DI)
#define DT_W  (DI*DTR)
#define OUT_W (DM*2*DI)
#define WTOT  (2*IN_W + 2*XP_W + 2*DT_W + OUT_W)

// ---------------- fp32 scratch ----------------
__device__ float g_xz[2][TT*2*DI];
__device__ float g_xc[2][TT*DI];
__device__ float g_xdbl[2][TT*XDB];
__device__ float g_dt[2][TT*DI];
// ---------------- bf16 scratch ----------------
__device__ __nv_bfloat16 g_un_bf[TT*DM];
__device__ __nv_bfloat16 g_xc_bf[2][TT*DI];
__device__ __nv_bfloat16 g_xd_bf[2][TT*XDB];
__device__ __nv_bfloat16 g_ycat_bf[TT*2*DI];
__device__ __nv_bfloat16 g_inw_bf[2][IN_W];
__device__ __nv_bfloat16 g_xpw_bf[2][XP_W];
__device__ __nv_bfloat16 g_dtw_bf[2][DT_W];
__device__ __nv_bfloat16 g_outw_bf[OUT_W];

// ---------------- helpers ----------------
__device__ __forceinline__ void cp16(uint32_t dst_s, const void* src) {
    asm volatile("cp.async.ca.shared.global [%0], [%1], 16;\n" :: "r"(dst_s), "l"(src));
}
__device__ __forceinline__ void cp_commit() {
    asm volatile("cp.async.commit_group;\n");
}
template<int N> __device__ __forceinline__ void cp_wait() {
    asm volatile("cp.async.wait_group %0;\n" :: "n"(N));
}
__device__ __forceinline__ void ldsm4(uint32_t& r0, uint32_t& r1,
                                      uint32_t& r2, uint32_t& r3, uint32_t a) {
    asm volatile("ldmatrix.sync.aligned.m8n8.x4.shared.b16 {%0,%1,%2,%3}, [%4];\n"
        : "=r"(r0), "=r"(r1), "=r"(r2), "=r"(r3) : "r"(a));
}
__device__ __forceinline__ void mma_bf16(
    float& c0, float& c1, float& c2, float& c3,
    uint32_t a0, uint32_t a1, uint32_t a2, uint32_t a3,
    uint32_t b0, uint32_t b1)
{
    asm volatile(
        "mma.sync.aligned.m16n8k16.row.col.f32.bf16.bf16.f32 "
        "{%0,%1,%2,%3}, {%4,%5,%6,%7}, {%8,%9}, {%0,%1,%2,%3};\n"
        : "+f"(c0), "+f"(c1), "+f"(c2), "+f"(c3)
        : "r"(a0), "r"(a1), "r"(a2), "r"(a3), "r"(b0), "r"(b1));
}

// ---------------- weight conversion ----------------
__global__ __launch_bounds__(256) void cvt_weights(
    const float* __restrict__ fw, const float* __restrict__ bw,
    const float* __restrict__ fx, const float* __restrict__ bx,
    const float* __restrict__ fd, const float* __restrict__ bd,
    const float* __restrict__ ow)
{
    int i = blockIdx.x * 256 + threadIdx.x;
    if (i < IN_W)  { g_inw_bf[0][i] = __float2bfloat16(fw[i]); return; }
    i -= IN_W;
    if (i < IN_W)  { g_inw_bf[1][i] = __float2bfloat16(bw[i]); return; }
    i -= IN_W;
    if (i < XP_W)  { g_xpw_bf[0][i] = __float2bfloat16(fx[i]); return; }
    i -= XP_W;
    if (i < XP_W)  { g_xpw_bf[1][i] = __float2bfloat16(bx[i]); return; }
    i -= XP_W;
    if (i < DT_W)  { g_dtw_bf[0][i] = __float2bfloat16(fd[i]); return; }
    i -= DT_W;
    if (i < DT_W)  { g_dtw_bf[1][i] = __float2bfloat16(bd[i]); return; }
    i -= DT_W;
    if (i < OUT_W) { g_outw_bf[i]   = __float2bfloat16(ow[i]); }
}

// ---------------- layernorm (bf16 out) ----------------
__global__ __launch_bounds__(256) void ln_kernel(const float* __restrict__ u,
                                                 const float* __restrict__ w,
                                                 const float* __restrict__ bvec)
{
    int t = blockIdx.x;
    const float* row = u + (size_t)t * DM;
    float v[3];
    float s = 0.f, s2 = 0.f;
#pragma unroll
    for (int i = 0; i < 3; i++) {
        v[i] = row[threadIdx.x + i*256];
        s  += v[i];
        s2 += v[i]*v[i];
    }
#pragma unroll
    for (int o = 16; o; o >>= 1) {
        s  += __shfl_xor_sync(0xffffffffu, s,  o);
        s2 += __shfl_xor_sync(0xffffffffu, s2, o);
    }
    __shared__ float ss[8], ss2[8];
    int wid = threadIdx.x >> 5, ln = threadIdx.x & 31;
    if (ln == 0) { ss[wid] = s; ss2[wid] = s2; }
    __syncthreads();
    float ts = 0.f, ts2 = 0.f;
#pragma unroll
    for (int i = 0; i < 8; i++) { ts += ss[i]; ts2 += ss2[i]; }
    float mu  = ts * (1.f/DM);
    float var = ts2 * (1.f/DM) - mu*mu;
    float rs  = rsqrtf(var + 1e-5f);
#pragma unroll
    for (int i = 0; i < 3; i++) {
        int c = threadIdx.x + i*256;
        g_un_bf[(size_t)t*DM + c] = __float2bfloat16((v[i]-mu)*rs*w[c] + bvec[c]);
    }
}

// ---------------- bf16 HMMA GEMM: ldmatrix + 4-stage cp.async, 1 sync/slab ------
// C[m,n] = sum_k A[m,k] * W[n,k];  A,W bf16 row-major (k contiguous); acc fp32.
// smem: per stage, (BM+BN) rows of 64B (one k32 slab), chunk swizzle c^((r>>1)&3).
// mode 0: fp32 (+ optional bf16 dual store); 1: softplus(acc+bias); 2: acc+resid.
template<int BM, int BN, int WRM, int WRN>
__global__ void __launch_bounds__(WRM*WRN*32) gemm_bf16(
    const __nv_bfloat16* __restrict__ A0, const __nv_bfloat16* __restrict__ A1, int lda,
    const __nv_bfloat16* __restrict__ W0, const __nv_bfloat16* __restrict__ W1, int ldw,
    float* __restrict__ C0, float* __restrict__ C1, int ldc,
    __nv_bfloat16* __restrict__ Cb0, __nv_bfloat16* __restrict__ Cb1,
    int K, int mode,
    const float* __restrict__ bias0, const float* __restrict__ bias1,
    const float* __restrict__ resid)
{
    constexpr int THREADS = WRM*WRN*32;
    constexpr int WM = BM / WRM;
    constexpr int WN = BN / WRN;
    constexpr int MT = WM / 16;
    constexpr int NT = WN / 8;
    static_assert(NT % 2 == 0, "B ldmatrix loads n16");
    constexpr int NST = 4;
    constexpr int SWORDS = (BM + BN) * 16;        // u32 words per stage
    constexpr int CH  = (BM + BN) * 4;            // 16B chunks per slab
    constexpr int LPT = CH / THREADS;
    static_assert(CH % THREADS == 0, "loader divisibility");

    extern __shared__ uint32_t sm[];
    uint32_t smem_base = (uint32_t)__cvta_generic_to_shared(sm);

    const __nv_bfloat16* A = blockIdx.z ? A1 : A0;
    const __nv_bfloat16* W = blockIdx.z ? W1 : W0;
    float*            C    = blockIdx.z ? C1 : C0;
    __nv_bfloat16*    Cb   = blockIdx.z ? Cb1 : Cb0;
    const float*      bias = blockIdx.z ? bias1 : bias0;

    int tid  = threadIdx.x;
    int lane = tid & 31;
    int w    = tid >> 5;
    int wm   = w / WRN;
    int wn   = w % WRN;
    int bm   = blockIdx.y * BM;
    int bn   = blockIdx.x * BN;
    int r0   = lane >> 2;
    int c0   = lane & 3;

    // loader: chunk i -> row i>>2 (A rows then B rows), chunk x = i&3
    const __nv_bfloat16* lsrc[LPT];
    uint32_t ldst[LPT];                           // word offset within a stage
#pragma unroll
    for (int u = 0; u < LPT; u++) {
        int i   = tid + u * THREADS;
        int row = i >> 2;
        int x   = i & 3;
        if (row < BM) {
            lsrc[u] = A + (size_t)(bm + row) * lda + x * 8;
            ldst[u] = row * 16 + (x ^ ((row >> 1) & 3)) * 4;
        } else {
            int r = row - BM;
            lsrc[u] = W + (size_t)(bn + r) * ldw + x * 8;
            ldst[u] = BM * 16 + r * 16 + (x ^ ((r >> 1) & 3)) * 4;
        }
    }

    int nk = K / 32;
#pragma unroll
    for (int p = 0; p < 3; p++) {
        if (p < nk) {
#pragma unroll
            for (int u = 0; u < LPT; u++)
                cp16(smem_base + (p*SWORDS + ldst[u])*4, lsrc[u] + p*32);
            cp_commit();
        }
    }

    float acc[MT][NT][4] = {};

    // precomputed ldmatrix row/lane components
    int arow = (lane & 15);                   // A: rows mo + lane&15
    int ach  = lane >> 4;                     // A: chunk half
    int brow = ((lane >> 4) << 3) + (lane & 7);  // B: 0..7 then +8 for hi lanes
    int bch  = (lane >> 3) & 1;

    for (int i = 0; i < nk; i++) {
        int st = i & (NST-1);
        int rem = nk - 1 - i;
        if (rem >= 2)      cp_wait<2>();
        else if (rem == 1) cp_wait<1>();
        else               cp_wait<0>();
        __syncthreads();

        if (i + 3 < nk) {
            int st2 = (i + 3) & (NST-1);
#pragma unroll
            for (int u = 0; u < LPT; u++)
                cp16(smem_base + (st2*SWORDS + ldst[u])*4, lsrc[u] + (i+3)*32);
            cp_commit();
        }

        uint32_t stw = smem_base + st*SWORDS*4;
#pragma unroll
        for (int kk = 0; kk < 2; kk++) {
            uint32_t ar[MT][4];
#pragma unroll
            for (int ii = 0; ii < MT; ii++) {
                int row = wm*WM + ii*16 + arow;
                int pos = (2*kk + ach) ^ ((row >> 1) & 3);
                ldsm4(ar[ii][0], ar[ii][1], ar[ii][2], ar[ii][3],
                      stw + (row*16 + pos*4)*4);
            }
            uint32_t br_[NT][2];
#pragma unroll
            for (int j2 = 0; j2 < NT/2; j2++) {
                int row = wn*WN + j2*16 + brow;
                int pos = (2*kk + bch) ^ ((row >> 1) & 3);
                ldsm4(br_[2*j2][0], br_[2*j2][1], br_[2*j2+1][0], br_[2*j2+1][1],
                      stw + (BM*16 + row*16 + pos*4)*4);
            }
#pragma unroll
            for (int ii = 0; ii < MT; ii++)
#pragma unroll
                for (int j = 0; j < NT; j++)
                    mma_bf16(acc[ii][j][0], acc[ii][j][1],
                             acc[ii][j][2], acc[ii][j][3],
                             ar[ii][0], ar[ii][1], ar[ii][2], ar[ii][3],
                             br_[j][0], br_[j][1]);
        }
    }

    // epilogue
#pragma unroll
    for (int i = 0; i < MT; i++) {
        int m0 = bm + wm*WM + i*16 + r0;
#pragma unroll
        for (int j = 0; j < NT; j++) {
            int n0 = bn + wn*WN + j*8 + c0*2;
            float v0 = acc[i][j][0], v1 = acc[i][j][1];
            float v2 = acc[i][j][2], v3 = acc[i][j][3];
            if (mode == 1) {
                float b0v = bias[n0], b1v = bias[n0 + 1];
                v0 += b0v; v1 += b1v; v2 += b0v; v3 += b1v;
                v0 = fmaxf(v0, 0.f) + log1pf(__expf(-fabsf(v0)));
                v1 = fmaxf(v1, 0.f) + log1pf(__expf(-fabsf(v1)));
                v2 = fmaxf(v2, 0.f) + log1pf(__expf(-fabsf(v2)));
                v3 = fmaxf(v3, 0.f) + log1pf(__expf(-fabsf(v3)));
            } else if (mode == 2) {
                const float2 rr0 = *(const float2*)&resid[(size_t)m0 * ldc + n0];
                const float2 rr1 = *(const float2*)&resid[(size_t)(m0+8) * ldc + n0];
                v0 += rr0.x; v1 += rr0.y; v2 += rr1.x; v3 += rr1.y;
            }
            *(float2*)&C[(size_t)m0 * ldc + n0]     = make_float2(v0, v1);
            *(float2*)&C[(size_t)(m0+8) * ldc + n0] = make_float2(v2, v3);
            if (Cb) {
                *(__nv_bfloat162*)&Cb[(size_t)m0 * ldc + n0] =
                    __float22bfloat162_rn(make_float2(v0, v1));
                *(__nv_bfloat162*)&Cb[(size_t)(m0+8) * ldc + n0] =
                    __float22bfloat162_rn(make_float2(v2, v3));
            }
        }
    }
}

// ---------------- depthwise conv (K=4) + silu; float4 vectorized ----------------
__global__ __launch_bounds__(256) void conv_silu(
    const float* __restrict__ cw0, const float* __restrict__ cb0,
    const float* __restrict__ cw1, const float* __restrict__ cb1)
{
    int br = blockIdx.y;
    const float* cw = br ? cw1 : cw0;
    const float* cb = br ? cb1 : cb0;
    const float* xz = g_xz[br];

    int idx = blockIdx.x * 256 + threadIdx.x;       // over TT*DI/4
    if (idx >= TT*DI/4) return;
    constexpr int ND4 = DI/4;
    int t  = idx / ND4;
    int d4 = (idx % ND4) * 4;
    int l  = t % Lseq;

    float4 wr[4];
#pragma unroll
    for (int i = 0; i < 4; i++) wr[i] = *(const float4*)&cw[(d4+i)*4];
    float4 bias4 = *(const float4*)&cb[d4];

    float4 x0, x1, x2, x3;   // taps: x3 = current, x2/x1/x0 = further away
    x3 = *(const float4*)&xz[(size_t)t*2*DI + d4];
    x2 = x1 = x0 = make_float4(0.f,0.f,0.f,0.f);
    if (br == 0) {
        if (l >= 1) x2 = *(const float4*)&xz[(size_t)(t-1)*2*DI + d4];
        if (l >= 2) x1 = *(const float4*)&xz[(size_t)(t-2)*2*DI + d4];
        if (l >= 3) x0 = *(const float4*)&xz[(size_t)(t-3)*2*DI + d4];
    } else {
        if (l+1 < Lseq) x2 = *(const float4*)&xz[(size_t)(t+1)*2*DI + d4];
        if (l+2 < Lseq) x1 = *(const float4*)&xz[(size_t)(t+2)*2*DI + d4];
        if (l+3 < Lseq) x0 = *(const float4*)&xz[(size_t)(t+3)*2*DI + d4];
    }
    float o[4];
    const float* xs0 = (const float*)&x0;
    const float* xs1 = (const float*)&x1;
    const float* xs2 = (const float*)&x2;
    const float* xs3 = (const float*)&x3;
    const float* bb  = (const float*)&bias4;
#pragma unroll
    for (int i = 0; i < 4; i++) {
        float a = bb[i];
        a = fmaf(wr[i].x, xs0[i], a);
        a = fmaf(wr[i].y, xs1[i], a);
        a = fmaf(wr[i].z, xs2[i], a);
        a = fmaf(wr[i].w, xs3[i], a);
        float sg = 1.f / (1.f + __expf(-a));
        o[i] = a * sg;
    }
    *(float4*)&g_xc[br][(size_t)t*DI + d4] = make_float4(o[0], o[1], o[2], o[3]);
    *(__nv_bfloat162*)&g_xc_bf[br][(size_t)t*DI + d4] =
        __float22bfloat162_rn(make_float2(o[0], o[1]));
    *(__nv_bfloat162*)&g_xc_bf[br][(size_t)t*DI + d4 + 2] =
        __float22bfloat162_rn(make_float2(o[2], o[3]));
}

// ---------------- selective scan (prefetched; bf16 ycat out) ----------------
__global__ __launch_bounds__(128) void scan_kernel(
    const float* __restrict__ Alog0, const float* __restrict__ Alog1,
    const float* __restrict__ Dv0,   const float* __restrict__ Dv1)
{
    int br = blockIdx.z;
    int b  = blockIdx.y;
    const float* Alog = br ? Alog1 : Alog0;
    const float* Dvec = br ? Dv1   : Dv0;
    const float* dt   = g_dt[br];
    const float* xc   = g_xc[br];
    const float* xd   = g_xdbl[br];
    const float* xz   = g_xz[br];

    int lane = threadIdx.x & 31;
    int warp = threadIdx.x >> 5;
    int n    = lane & 15;
    int d    = blockIdx.x * 8 + warp * 2 + (lane >> 4);

    float A  = -__expf(Alog[d*NS + n]);
    float Dp = Dvec[d];
    float h  = 0.f;

    int step = br ? -1 : 1;
    int t = b*Lseq + (br ? Lseq-1 : 0);
    float dtv = dt[(size_t)t*DI + d];
    float xv  = xc[(size_t)t*DI + d];
    float Bv  = xd[(size_t)t*XDB + DTR + n];
    float Cv  = xd[(size_t)t*XDB + DTR + NS + n];

    for (int s = 0; s < Lseq; s++) {
        float ndt = 0.f, nx = 0.f, nB = 0.f, nC = 0.f;
        int tn = t + step;
        if (s + 1 < Lseq) {
            ndt = dt[(size_t)tn*DI + d];
            nx  = xc[(size_t)tn*DI + d];
            nB  = xd[(size_t)tn*XDB + DTR + n];
            nC  = xd[(size_t)tn*XDB + DTR + NS + n];
        }
        float a = __expf(dtv * A);
        h = fmaf(a, h, dtv * xv * Bv);
        float y = h * Cv;
        y += __shfl_xor_sync(0xffffffffu, y, 8);
        y += __shfl_xor_sync(0xffffffffu, y, 4);
        y += __shfl_xor_sync(0xffffffffu, y, 2);
        y += __shfl_xor_sync(0xffffffffu, y, 1);
        if (n == 0) {
            float z  = xz[(size_t)t*2*DI + DI + d];
            float sz = z / (1.f + __expf(-z));
            g_ycat_bf[(size_t)t*2*DI + br*DI + d] =
                __float2bfloat16(fmaf(xv, Dp, y) * sz);
        }
        dtv = ndt; xv = nx; Bv = nB; Cv = nC; t = tn;
    }
}

// ---------------- launcher ----------------
extern "C" void kernel_launch(void* const* d_in, const int* in_sizes, int n_in,
                              void* d_out, int out_size)
{
    const float* u       = (const float*)d_in[0];
    const float* norm_w  = (const float*)d_in[1];
    const float* norm_b  = (const float*)d_in[2];
    const float* f_in_w  = (const float*)d_in[3];
    const float* f_cw    = (const float*)d_in[4];
    const float* f_cb    = (const float*)d_in[5];
    const float* f_Alog  = (const float*)d_in[6];
    const float* f_xpw   = (const float*)d_in[7];
    const float* f_dtw   = (const float*)d_in[8];
    const float* f_dtb   = (const float*)d_in[9];
    const float* f_D     = (const float*)d_in[10];
    const float* b_in_w  = (const float*)d_in[11];
    const float* b_cw    = (const float*)d_in[12];
    const float* b_cb    = (const float*)d_in[13];
    const float* b_Alog  = (const float*)d_in[14];
    const float* b_xpw   = (const float*)d_in[15];
    const float* b_dtw   = (const float*)d_in[16];
    const float* b_dtb   = (const float*)d_in[17];
    const float* b_D     = (const float*)d_in[18];
    const float* out_w   = (const float*)d_in[19];
    float* out = (float*)d_out;

    float *xz, *xdbl, *dt;
    __nv_bfloat16 *un_bf, *xc_bf, *xd_bf, *ycat_bf;
    __nv_bfloat16 *inw_bf, *xpw_bf, *dtw_bf, *outw_bf;
    cudaGetSymbolAddress((void**)&xz,     g_xz);
    cudaGetSymbolAddress((void**)&xdbl,   g_xdbl);
    cudaGetSymbolAddress((void**)&dt,     g_dt);
    cudaGetSymbolAddress((void**)&un_bf,  g_un_bf);
    cudaGetSymbolAddress((void**)&xc_bf,  g_xc_bf);
    cudaGetSymbolAddress((void**)&xd_bf,  g_xd_bf);
    cudaGetSymbolAddress((void**)&ycat_bf,g_ycat_bf);
    cudaGetSymbolAddress((void**)&inw_bf, g_inw_bf);
    cudaGetSymbolAddress((void**)&xpw_bf, g_xpw_bf);
    cudaGetSymbolAddress((void**)&dtw_bf, g_dtw_bf);
    cudaGetSymbolAddress((void**)&outw_bf,g_outw_bf);

    float* xz0 = xz;   float* xz1 = xz   + (size_t)TT*2*DI;
    float* xd0 = xdbl; float* xd1 = xdbl + (size_t)TT*XDB;
    float* dt0 = dt;   float* dt1 = dt   + (size_t)TT*DI;
    __nv_bfloat16* xcb0 = xc_bf;  __nv_bfloat16* xcb1 = xc_bf + (size_t)TT*DI;
    __nv_bfloat16* xdb0 = xd_bf;  __nv_bfloat16* xdb1 = xd_bf + (size_t)TT*XDB;
    __nv_bfloat16* inw0 = inw_bf; __nv_bfloat16* inw1 = inw_bf + (size_t)IN_W;
    __nv_bfloat16* xpw0 = xpw_bf; __nv_bfloat16* xpw1 = xpw_bf + (size_t)XP_W;
    __nv_bfloat16* dtw0 = dtw_bf; __nv_bfloat16* dtw1 = dtw_bf + (size_t)DT_W;

    constexpr int SM_BIG = 4 * 256 * 64;   // 65536
    constexpr int SM_XP  = 4 *  96 * 64;   // 24576
    constexpr int SM_OUT = 4 * 192 * 64;   // 49152
    cudaFuncSetAttribute((const void*)gemm_bf16<128,128,4,2>,
        cudaFuncAttributeMaxDynamicSharedMemorySize, SM_BIG);
    cudaFuncSetAttribute((const void*)gemm_bf16<32,64,2,2>,
        cudaFuncAttributeMaxDynamicSharedMemorySize, SM_XP);
    cudaFuncSetAttribute((const void*)gemm_bf16<128,64,4,2>,
        cudaFuncAttributeMaxDynamicSharedMemorySize, SM_OUT);

    // 0) weights -> bf16
    cvt_weights<<<(WTOT + 255)/256, 256>>>(f_in_w, b_in_w, f_xpw, b_xpw,
                                           f_dtw, b_dtw, out_w);
    // 1) layernorm -> bf16
    ln_kernel<<<TT, 256>>>(u, norm_w, norm_b);

    // 2) in-proj: (2048x768) -> 3072, fp32 out
    gemm_bf16<128,128,4,2><<<dim3(2*DI/128, TT/128, 2), 256, SM_BIG>>>(
        un_bf, un_bf, DM, inw0, inw1, DM, xz0, xz1, 2*DI,
        nullptr, nullptr, DM, 0, nullptr, nullptr, nullptr);

    // 3) conv + silu -> fp32 + bf16 (vectorized x4)
    conv_silu<<<dim3(TT*DI/4/256, 2), 256>>>(f_cw, f_cb, b_cw, b_cb);

    // 4) xproj: (2048x1536) -> 128, fp32 + bf16 out
    gemm_bf16<32,64,2,2><<<dim3(XDB/64, TT/32, 2), 128, SM_XP>>>(
        xcb0, xcb1, DI, xpw0, xpw1, DI, xd0, xd1, XDB,
        xdb0, xdb1, DI, 0, nullptr, nullptr, nullptr);

    // 5) dt: (2048x96) -> 1536, softplus+bias, fp32 out
    gemm_bf16<128,128,4,2><<<dim3(DI/128, TT/128, 2), 256, SM_BIG>>>(
        xdb0, xdb1, XDB, dtw0, dtw1, DTR, dt0, dt1, DI,
        nullptr, nullptr, XDB, 1, f_dtb, b_dtb, nullptr);

    // 6) selective scan + gate -> bf16 ycat
    scan_kernel<<<dim3(DI/8, Bb, 2), 128>>>(f_Alog, b_Alog, f_D, b_D);

    // 7) out-proj + residual: (2048x3072) -> 768, fp32 out
    gemm_bf16<128,64,4,2><<<dim3(DM/64, TT/128, 1), 256, SM_OUT>>>(
        ycat_bf, ycat_bf, 2*DI, outw_bf, outw_bf, 2*DI, out, out, DM,
        nullptr, nullptr, 2*DI, 2, nullptr, nullptr, u);
}

// round 7
// speedup vs baseline: 4.6741x; 1.7175x over previous
#include <cuda_runtime.h>
#include <cuda_bf16.h>
#include <math.h>
#include <stdint.h>

#define Bb   2
#define Lseq 1024
#define DM   768
#define DI   1536
#define NS   16
#define DTR  96
#define XDB  (DTR + 2*NS)   // 128
#define TT   (Bb*Lseq)      // 2048

#define IN_W  (2*DI*DM)
#define XP_W  (XDB*DI)
#define DT_W  (DI*DTR)
#define OUT_W (DM*2*DI)
#define WTOT  (2*IN_W + 2*XP_W + 2*DT_W + OUT_W)

// ---------------- fp32 scratch ----------------
__device__ float g_xz[2][TT*2*DI];
__device__ float g_xc[2][TT*DI];
__device__ float g_xdbl[2][TT*XDB];
__device__ float g_dt[2][TT*DI];
__device__ float g_xdp[4][TT*XDB];        // xproj split-K partials [br*2+kh]
// ---------------- bf16 scratch ----------------
__device__ __nv_bfloat16 g_un_bf[TT*DM];
__device__ __nv_bfloat16 g_xc_bf[2][TT*DI];
__device__ __nv_bfloat16 g_xd_bf[2][TT*XDB];
__device__ __nv_bfloat16 g_ycat_bf[TT*2*DI];
__device__ __nv_bfloat16 g_inw_bf[2][IN_W];
__device__ __nv_bfloat16 g_xpw_bf[2][XP_W];
__device__ __nv_bfloat16 g_dtw_bf[2][DT_W];
__device__ __nv_bfloat16 g_outw_bf[OUT_W];

// ---------------- helpers ----------------
__device__ __forceinline__ void cp16(uint32_t dst_s, const void* src) {
    asm volatile("cp.async.ca.shared.global [%0], [%1], 16;\n" :: "r"(dst_s), "l"(src));
}
__device__ __forceinline__ void cp_commit() {
    asm volatile("cp.async.commit_group;\n");
}
template<int N> __device__ __forceinline__ void cp_wait() {
    asm volatile("cp.async.wait_group %0;\n" :: "n"(N));
}
__device__ __forceinline__ void ldsm4(uint32_t& r0, uint32_t& r1,
                                      uint32_t& r2, uint32_t& r3, uint32_t a) {
    asm volatile("ldmatrix.sync.aligned.m8n8.x4.shared.b16 {%0,%1,%2,%3}, [%4];\n"
        : "=r"(r0), "=r"(r1), "=r"(r2), "=r"(r3) : "r"(a));
}
__device__ __forceinline__ void mma_bf16(
    float& c0, float& c1, float& c2, float& c3,
    uint32_t a0, uint32_t a1, uint32_t a2, uint32_t a3,
    uint32_t b0, uint32_t b1)
{
    asm volatile(
        "mma.sync.aligned.m16n8k16.row.col.f32.bf16.bf16.f32 "
        "{%0,%1,%2,%3}, {%4,%5,%6,%7}, {%8,%9}, {%0,%1,%2,%3};\n"
        : "+f"(c0), "+f"(c1), "+f"(c2), "+f"(c3)
        : "r"(a0), "r"(a1), "r"(a2), "r"(a3), "r"(b0), "r"(b1));
}

// ---------------- weight conversion ----------------
__global__ __launch_bounds__(256) void cvt_weights(
    const float* __restrict__ fw, const float* __restrict__ bw,
    const float* __restrict__ fx, const float* __restrict__ bx,
    const float* __restrict__ fd, const float* __restrict__ bd,
    const float* __restrict__ ow)
{
    int i = blockIdx.x * 256 + threadIdx.x;
    if (i < IN_W)  { g_inw_bf[0][i] = __float2bfloat16(fw[i]); return; }
    i -= IN_W;
    if (i < IN_W)  { g_inw_bf[1][i] = __float2bfloat16(bw[i]); return; }
    i -= IN_W;
    if (i < XP_W)  { g_xpw_bf[0][i] = __float2bfloat16(fx[i]); return; }
    i -= XP_W;
    if (i < XP_W)  { g_xpw_bf[1][i] = __float2bfloat16(bx[i]); return; }
    i -= XP_W;
    if (i < DT_W)  { g_dtw_bf[0][i] = __float2bfloat16(fd[i]); return; }
    i -= DT_W;
    if (i < DT_W)  { g_dtw_bf[1][i] = __float2bfloat16(bd[i]); return; }
    i -= DT_W;
    if (i < OUT_W) { g_outw_bf[i]   = __float2bfloat16(ow[i]); }
}

// ---------------- layernorm (bf16 out) ----------------
__global__ __launch_bounds__(256) void ln_kernel(const float* __restrict__ u,
                                                 const float* __restrict__ w,
                                                 const float* __restrict__ bvec)
{
    int t = blockIdx.x;
    const float* row = u + (size_t)t * DM;
    float v[3];
    float s = 0.f, s2 = 0.f;
#pragma unroll
    for (int i = 0; i < 3; i++) {
        v[i] = row[threadIdx.x + i*256];
        s  += v[i];
        s2 += v[i]*v[i];
    }
#pragma unroll
    for (int o = 16; o; o >>= 1) {
        s  += __shfl_xor_sync(0xffffffffu, s,  o);
        s2 += __shfl_xor_sync(0xffffffffu, s2, o);
    }
    __shared__ float ss[8], ss2[8];
    int wid = threadIdx.x >> 5, ln = threadIdx.x & 31;
    if (ln == 0) { ss[wid] = s; ss2[wid] = s2; }
    __syncthreads();
    float ts = 0.f, ts2 = 0.f;
#pragma unroll
    for (int i = 0; i < 8; i++) { ts += ss[i]; ts2 += ss2[i]; }
    float mu  = ts * (1.f/DM);
    float var = ts2 * (1.f/DM) - mu*mu;
    float rs  = rsqrtf(var + 1e-5f);
#pragma unroll
    for (int i = 0; i < 3; i++) {
        int c = threadIdx.x + i*256;
        g_un_bf[(size_t)t*DM + c] = __float2bfloat16((v[i]-mu)*rs*w[c] + bvec[c]);
    }
}

// ======== gemm_big: 128x128 CTA tile, 4 warps (64x64 each), k64 slabs ========
// C[m,n] = sum_k A[m,k] * W[n,k].  MODE 0: plain fp32.  MODE 2: + resid.
// K % 64 == 0, K/64 >= 2.  128 threads.  smem: 3 stages x 32KB.
template<int MODE>
__global__ void __launch_bounds__(128) gemm_big(
    const __nv_bfloat16* __restrict__ A0, const __nv_bfloat16* __restrict__ A1, int lda,
    const __nv_bfloat16* __restrict__ W0, const __nv_bfloat16* __restrict__ W1, int ldw,
    float* __restrict__ C0, float* __restrict__ C1, int ldc,
    int K, const float* __restrict__ resid)
{
    extern __shared__ char smem[];
    uint32_t sb = (uint32_t)__cvta_generic_to_shared(smem);

    const __nv_bfloat16* A = blockIdx.z ? A1 : A0;
    const __nv_bfloat16* W = blockIdx.z ? W1 : W0;
    float* C = blockIdx.z ? C1 : C0;

    int tid  = threadIdx.x;
    int lane = tid & 31;
    int w    = tid >> 5;
    int wm   = w >> 1;
    int wn   = w & 1;
    int bm   = blockIdx.y * 128;
    int bn   = blockIdx.x * 128;

    // loader: thread -> (row base rb in 0..15, chunk ch in 0..7), row stride 16
    int ch = tid & 7;
    int rb = tid >> 3;
    const __nv_bfloat16* ap = A + (size_t)(bm + rb) * lda + ch * 8;
    const __nv_bfloat16* wp = W + (size_t)(bn + rb) * ldw + ch * 8;
    uint32_t ao = (uint32_t)(rb * 128 + ((ch ^ (rb & 7)) * 16));
    uint32_t bo = 16384u + ao;

    int nk = K / 64;
    // prime 2 stages
#pragma unroll
    for (int p = 0; p < 2; p++) {
#pragma unroll
        for (int v = 0; v < 8; v++) {
            cp16(sb + p*32768 + ao + v*2048, ap + (size_t)v*16*lda + p*64);
            cp16(sb + p*32768 + bo + v*2048, wp + (size_t)v*16*ldw + p*64);
        }
        cp_commit();
    }

    float acc[4][8][4] = {};
    int arow = lane & 15;
    int ach  = lane >> 4;
    int brow = ((lane >> 4) << 3) + (lane & 7);
    int bch  = (lane >> 3) & 1;
    int r0   = lane >> 2;
    int c0   = lane & 3;

    for (int i = 0; i < nk; i++) {
        int st = i % 3;
        cp_wait<1>();
        __syncthreads();
        {
            int s2 = (i + 2) % 3;
            if (i + 2 < nk) {
#pragma unroll
                for (int v = 0; v < 8; v++) {
                    cp16(sb + s2*32768 + ao + v*2048, ap + (size_t)v*16*lda + (i+2)*64);
                    cp16(sb + s2*32768 + bo + v*2048, wp + (size_t)v*16*ldw + (i+2)*64);
                }
            }
            cp_commit();
        }
        uint32_t base = sb + st*32768;
#pragma unroll
        for (int kk = 0; kk < 4; kk++) {
            uint32_t ar[4][4];
#pragma unroll
            for (int ii = 0; ii < 4; ii++) {
                int row = wm*64 + ii*16 + arow;
                int pos = (2*kk + ach) ^ (row & 7);
                ldsm4(ar[ii][0], ar[ii][1], ar[ii][2], ar[ii][3],
                      base + row*128 + pos*16);
            }
            uint32_t br_[8][2];
#pragma unroll
            for (int j2 = 0; j2 < 4; j2++) {
                int row = wn*64 + j2*16 + brow;
                int pos = (2*kk + bch) ^ (row & 7);
                ldsm4(br_[2*j2][0], br_[2*j2][1], br_[2*j2+1][0], br_[2*j2+1][1],
                      base + 16384 + row*128 + pos*16);
            }
#pragma unroll
            for (int ii = 0; ii < 4; ii++)
#pragma unroll
                for (int j = 0; j < 8; j++)
                    mma_bf16(acc[ii][j][0], acc[ii][j][1],
                             acc[ii][j][2], acc[ii][j][3],
                             ar[ii][0], ar[ii][1], ar[ii][2], ar[ii][3],
                             br_[j][0], br_[j][1]);
        }
    }

#pragma unroll
    for (int ii = 0; ii < 4; ii++) {
        int m0 = bm + wm*64 + ii*16 + r0;
#pragma unroll
        for (int j = 0; j < 8; j++) {
            int n0 = bn + wn*64 + j*8 + c0*2;
            float v0 = acc[ii][j][0], v1 = acc[ii][j][1];
            float v2 = acc[ii][j][2], v3 = acc[ii][j][3];
            if (MODE == 2) {
                const float2 rr0 = *(const float2*)&resid[(size_t)m0 * ldc + n0];
                const float2 rr1 = *(const float2*)&resid[(size_t)(m0+8) * ldc + n0];
                v0 += rr0.x; v1 += rr0.y; v2 += rr1.x; v3 += rr1.y;
            }
            *(float2*)&C[(size_t)m0 * ldc + n0]     = make_float2(v0, v1);
            *(float2*)&C[(size_t)(m0+8) * ldc + n0] = make_float2(v2, v3);
        }
    }
}

// ======== gemm_xp: xproj split-K.  BM=32, BN=64, 4 warps, K=768/part ========
// z = br*2 + kh.  C -> g_xdp[z], fp32.  k32 slabs, 4 stages.
__global__ void __launch_bounds__(128) gemm_xp(
    const __nv_bfloat16* __restrict__ Ab0, const __nv_bfloat16* __restrict__ Ab1,
    const __nv_bfloat16* __restrict__ Wb0, const __nv_bfloat16* __restrict__ Wb1,
    float* __restrict__ Cp)
{
    constexpr int BM = 32, BN = 64, THREADS = 128;
    constexpr int SWORDS = (BM + BN) * 16;
    constexpr int LPT = (BM + BN) * 4 / THREADS;   // 3
    constexpr int KPART = 768;

    extern __shared__ uint32_t sm[];
    uint32_t smem_base = (uint32_t)__cvta_generic_to_shared(sm);

    int z  = blockIdx.z;
    int br = z >> 1;
    int kh = z & 1;
    const __nv_bfloat16* A = (br ? Ab1 : Ab0) + kh * KPART;
    const __nv_bfloat16* W = (br ? Wb1 : Wb0) + kh * KPART;
    float* C = Cp + (size_t)z * (TT*XDB);

    int tid  = threadIdx.x;
    int lane = tid & 31;
    int w    = tid >> 5;
    int wm   = w >> 1;          // 0..1
    int wn   = w & 1;           // 0..1
    int bm   = blockIdx.y * BM;
    int bn   = blockIdx.x * BN;
    int r0   = lane >> 2;
    int c0   = lane & 3;

    const __nv_bfloat16* lsrc[LPT];
    uint32_t ldst[LPT];
#pragma unroll
    for (int u = 0; u < LPT; u++) {
        int i   = tid + u * THREADS;
        int row = i >> 2;
        int x   = i & 3;
        if (row < BM) {
            lsrc[u] = A + (size_t)(bm + row) * DI + x * 8;
            ldst[u] = row * 16 + (x ^ ((row >> 1) & 3)) * 4;
        } else {
            int r = row - BM;
            lsrc[u] = W + (size_t)(bn + r) * DI + x * 8;
            ldst[u] = BM * 16 + r * 16 + (x ^ ((r >> 1) & 3)) * 4;
        }
    }

    constexpr int nk = KPART / 32;   // 24
#pragma unroll
    for (int p = 0; p < 3; p++) {
#pragma unroll
        for (int u = 0; u < LPT; u++)
            cp16(smem_base + (p*SWORDS + ldst[u])*4, lsrc[u] + p*32);
        cp_commit();
    }

    float acc[1][4][4] = {};
    int arow = lane & 15;
    int ach  = lane >> 4;
    int brow = ((lane >> 4) << 3) + (lane & 7);
    int bch  = (lane >> 3) & 1;

    for (int i = 0; i < nk; i++) {
        int st = i & 3;
        int rem = nk - 1 - i;
        if (rem >= 2)      cp_wait<2>();
        else if (rem == 1) cp_wait<1>();
        else               cp_wait<0>();
        __syncthreads();
        if (i + 3 < nk) {
            int st2 = (i + 3) & 3;
#pragma unroll
            for (int u = 0; u < LPT; u++)
                cp16(smem_base + (st2*SWORDS + ldst[u])*4, lsrc[u] + (i+3)*32);
            cp_commit();
        }
        uint32_t stw = smem_base + st*SWORDS*4;
#pragma unroll
        for (int kk = 0; kk < 2; kk++) {
            uint32_t ar[4];
            {
                int row = wm*16 + arow;
                int pos = (2*kk + ach) ^ ((row >> 1) & 3);
                ldsm4(ar[0], ar[1], ar[2], ar[3], stw + (row*16 + pos*4)*4);
            }
            uint32_t br_[4][2];
#pragma unroll
            for (int j2 = 0; j2 < 2; j2++) {
                int row = wn*32 + j2*16 + brow;
                int pos = (2*kk + bch) ^ ((row >> 1) & 3);
                ldsm4(br_[2*j2][0], br_[2*j2][1], br_[2*j2+1][0], br_[2*j2+1][1],
                      stw + (BM*16 + row*16 + pos*4)*4);
            }
#pragma unroll
            for (int j = 0; j < 4; j++)
                mma_bf16(acc[0][j][0], acc[0][j][1], acc[0][j][2], acc[0][j][3],
                         ar[0], ar[1], ar[2], ar[3], br_[j][0], br_[j][1]);
        }
    }

    {
        int m0 = bm + wm*16 + r0;
#pragma unroll
        for (int j = 0; j < 4; j++) {
            int n0 = bn + wn*32 + j*8 + c0*2;
            *(float2*)&C[(size_t)m0 * XDB + n0]     = make_float2(acc[0][j][0], acc[0][j][1]);
            *(float2*)&C[(size_t)(m0+8) * XDB + n0] = make_float2(acc[0][j][2], acc[0][j][3]);
        }
    }
}

// ---------------- reduce xproj partials -> fp32 + bf16 ----------------
__global__ __launch_bounds__(256) void reduce_xd()
{
    int br = blockIdx.y;
    int i4 = (blockIdx.x * 256 + threadIdx.x) * 4;
    if (i4 >= TT*XDB) return;
    float4 a = *(const float4*)&g_xdp[br*2 + 0][i4];
    float4 b = *(const float4*)&g_xdp[br*2 + 1][i4];
    float4 s = make_float4(a.x+b.x, a.y+b.y, a.z+b.z, a.w+b.w);
    *(float4*)&g_xdbl[br][i4] = s;
    *(__nv_bfloat162*)&g_xd_bf[br][i4]   = __float22bfloat162_rn(make_float2(s.x, s.y));
    *(__nv_bfloat162*)&g_xd_bf[br][i4+2] = __float22bfloat162_rn(make_float2(s.z, s.w));
}

// ---------------- dt GEMM: mma.sync, 128x128, K=96, softplus ----------------
__global__ void __launch_bounds__(256) gemm_dt(
    const __nv_bfloat16* __restrict__ A0, const __nv_bfloat16* __restrict__ A1,
    const __nv_bfloat16* __restrict__ W0, const __nv_bfloat16* __restrict__ W1,
    float* __restrict__ C0, float* __restrict__ C1,
    const float* __restrict__ bias0, const float* __restrict__ bias1)
{
    constexpr int BM = 128, BN = 128, THREADS = 256;
    constexpr int SWORDS = (BM + BN) * 16;
    constexpr int LPT = (BM + BN) * 4 / THREADS;  // 4
    constexpr int K = DTR;                        // 96

    extern __shared__ uint32_t sm[];
    uint32_t smem_base = (uint32_t)__cvta_generic_to_shared(sm);

    const __nv_bfloat16* A = blockIdx.z ? A1 : A0;
    const __nv_bfloat16* W = blockIdx.z ? W1 : W0;
    float*       C    = blockIdx.z ? C1 : C0;
    const float* bias = blockIdx.z ? bias1 : bias0;

    int tid  = threadIdx.x;
    int lane = tid & 31;
    int w    = tid >> 5;
    int wm   = w >> 1;      // 0..3 (WRM=4)
    int wn   = w & 1;       // 0..1 (WRN=2), warp tile 32x64
    int bm   = blockIdx.y * BM;
    int bn   = blockIdx.x * BN;
    int r0   = lane >> 2;
    int c0   = lane & 3;

    const __nv_bfloat16* lsrc[LPT];
    uint32_t ldst[LPT];
#pragma unroll
    for (int u = 0; u < LPT; u++) {
        int i   = tid + u * THREADS;
        int row = i >> 2;
        int x   = i & 3;
        if (row < BM) {
            lsrc[u] = A + (size_t)(bm + row) * XDB + x * 8;
            ldst[u] = row * 16 + (x ^ ((row >> 1) & 3)) * 4;
        } else {
            int r = row - BM;
            lsrc[u] = W + (size_t)(bn + r) * DTR + x * 8;
            ldst[u] = BM * 16 + r * 16 + (x ^ ((r >> 1) & 3)) * 4;
        }
    }

    constexpr int nk = K / 32;   // 3
#pragma unroll
    for (int p = 0; p < 3; p++) {
#pragma unroll
        for (int u = 0; u < LPT; u++)
            cp16(smem_base + (p*SWORDS + ldst[u])*4, lsrc[u] + p*32);
        cp_commit();
    }

    float acc[2][8][4] = {};
    int arow = lane & 15;
    int ach  = lane >> 4;
    int brow = ((lane >> 4) << 3) + (lane & 7);
    int bch  = (lane >> 3) & 1;

    for (int i = 0; i < nk; i++) {
        int st = i & 3;
        int rem = nk - 1 - i;
        if (rem >= 2)      cp_wait<2>();
        else if (rem == 1) cp_wait<1>();
        else               cp_wait<0>();
        __syncthreads();
        uint32_t stw = smem_base + st*SWORDS*4;
#pragma unroll
        for (int kk = 0; kk < 2; kk++) {
            uint32_t ar[2][4];
#pragma unroll
            for (int ii = 0; ii < 2; ii++) {
                int row = wm*32 + ii*16 + arow;
                int pos = (2*kk + ach) ^ ((row >> 1) & 3);
                ldsm4(ar[ii][0], ar[ii][1], ar[ii][2], ar[ii][3],
                      stw + (row*16 + pos*4)*4);
            }
            uint32_t br_[8][2];
#pragma unroll
            for (int j2 = 0; j2 < 4; j2++) {
                int row = wn*64 + j2*16 + brow;
                int pos = (2*kk + bch) ^ ((row >> 1) & 3);
                ldsm4(br_[2*j2][0], br_[2*j2][1], br_[2*j2+1][0], br_[2*j2+1][1],
                      stw + (BM*16 + row*16 + pos*4)*4);
            }
#pragma unroll
            for (int ii = 0; ii < 2; ii++)
#pragma unroll
                for (int j = 0; j < 8; j++)
                    mma_bf16(acc[ii][j][0], acc[ii][j][1],
                             acc[ii][j][2], acc[ii][j][3],
                             ar[ii][0], ar[ii][1], ar[ii][2], ar[ii][3],
                             br_[j][0], br_[j][1]);
        }
    }

#pragma unroll
    for (int ii = 0; ii < 2; ii++) {
        int m0 = bm + wm*32 + ii*16 + r0;
#pragma unroll
        for (int j = 0; j < 8; j++) {
            int n0 = bn + wn*64 + j*8 + c0*2;
            float v0 = acc[ii][j][0], v1 = acc[ii][j][1];
            float v2 = acc[ii][j][2], v3 = acc[ii][j][3];
            float b0v = bias[n0], b1v = bias[n0 + 1];
            v0 += b0v; v1 += b1v; v2 += b0v; v3 += b1v;
            v0 = fmaxf(v0, 0.f) + log1pf(__expf(-fabsf(v0)));
            v1 = fmaxf(v1, 0.f) + log1pf(__expf(-fabsf(v1)));
            v2 = fmaxf(v2, 0.f) + log1pf(__expf(-fabsf(v2)));
            v3 = fmaxf(v3, 0.f) + log1pf(__expf(-fabsf(v3)));
            *(float2*)&C[(size_t)m0 * DI + n0]     = make_float2(v0, v1);
            *(float2*)&C[(size_t)(m0+8) * DI + n0] = make_float2(v2, v3);
        }
    }
}

// ---------------- depthwise conv (K=4) + silu; float4 vectorized ----------------
__global__ __launch_bounds__(256) void conv_silu(
    const float* __restrict__ cw0, const float* __restrict__ cb0,
    const float* __restrict__ cw1, const float* __restrict__ cb1)
{
    int br = blockIdx.y;
    const float* cw = br ? cw1 : cw0;
    const float* cb = br ? cb1 : cb0;
    const float* xz = g_xz[br];

    int idx = blockIdx.x * 256 + threadIdx.x;
    if (idx >= TT*DI/4) return;
    constexpr int ND4 = DI/4;
    int t  = idx / ND4;
    int d4 = (idx % ND4) * 4;
    int l  = t % Lseq;

    float4 wr[4];
#pragma unroll
    for (int i = 0; i < 4; i++) wr[i] = *(const float4*)&cw[(d4+i)*4];
    float4 bias4 = *(const float4*)&cb[d4];

    float4 x0, x1, x2, x3;
    x3 = *(const float4*)&xz[(size_t)t*2*DI + d4];
    x2 = x1 = x0 = make_float4(0.f,0.f,0.f,0.f);
    if (br == 0) {
        if (l >= 1) x2 = *(const float4*)&xz[(size_t)(t-1)*2*DI + d4];
        if (l >= 2) x1 = *(const float4*)&xz[(size_t)(t-2)*2*DI + d4];
        if (l >= 3) x0 = *(const float4*)&xz[(size_t)(t-3)*2*DI + d4];
    } else {
        if (l+1 < Lseq) x2 = *(const float4*)&xz[(size_t)(t+1)*2*DI + d4];
        if (l+2 < Lseq) x1 = *(const float4*)&xz[(size_t)(t+2)*2*DI + d4];
        if (l+3 < Lseq) x0 = *(const float4*)&xz[(size_t)(t+3)*2*DI + d4];
    }
    float o[4];
    const float* xs0 = (const float*)&x0;
    const float* xs1 = (const float*)&x1;
    const float* xs2 = (const float*)&x2;
    const float* xs3 = (const float*)&x3;
    const float* bb  = (const float*)&bias4;
#pragma unroll
    for (int i = 0; i < 4; i++) {
        float a = bb[i];
        a = fmaf(wr[i].x, xs0[i], a);
        a = fmaf(wr[i].y, xs1[i], a);
        a = fmaf(wr[i].z, xs2[i], a);
        a = fmaf(wr[i].w, xs3[i], a);
        float sg = 1.f / (1.f + __expf(-a));
        o[i] = a * sg;
    }
    *(float4*)&g_xc[br][(size_t)t*DI + d4] = make_float4(o[0], o[1], o[2], o[3]);
    *(__nv_bfloat162*)&g_xc_bf[br][(size_t)t*DI + d4] =
        __float22bfloat162_rn(make_float2(o[0], o[1]));
    *(__nv_bfloat162*)&g_xc_bf[br][(size_t)t*DI + d4 + 2] =
        __float22bfloat162_rn(make_float2(o[2], o[3]));
}

// ---------------- selective scan: 4-step pipelined reduction ----------------
__global__ __launch_bounds__(128) void scan_kernel(
    const float* __restrict__ Alog0, const float* __restrict__ Alog1,
    const float* __restrict__ Dv0,   const float* __restrict__ Dv1)
{
    int br = blockIdx.z;
    int b  = blockIdx.y;
    const float* Alog = br ? Alog1 : Alog0;
    const float* Dvec = br ? Dv1   : Dv0;
    const float* dt   = g_dt[br];
    const float* xc   = g_xc[br];
    const float* xd   = g_xdbl[br];
    const float* xz   = g_xz[br];

    int lane = threadIdx.x & 31;
    int warp = threadIdx.x >> 5;
    int n    = lane & 15;
    int d    = blockIdx.x * 8 + warp * 2 + (lane >> 4);

    float A  = -__expf(Alog[d*NS + n]);
    float Dp = Dvec[d];
    float h  = 0.f;

    int step = br ? -1 : 1;
    int t = b*Lseq + (br ? Lseq-1 : 0);

    float dt4[4], xv4[4], Bv4[4], Cv4[4], z4[4];
    {
        int tq = t;
#pragma unroll
        for (int j = 0; j < 4; j++) {
            dt4[j] = dt[(size_t)tq*DI + d];
            xv4[j] = xc[(size_t)tq*DI + d];
            Bv4[j] = xd[(size_t)tq*XDB + DTR + n];
            Cv4[j] = xd[(size_t)tq*XDB + DTR + NS + n];
            z4[j]  = xz[(size_t)tq*2*DI + DI + d];
            tq += step;
        }
    }

    for (int s = 0; s < Lseq; s += 4) {
        float nd[4], nx[4], nB[4], nC[4], nz[4];
        if (s + 4 < Lseq) {
            int tq = t + 4*step;
#pragma unroll
            for (int j = 0; j < 4; j++) {
                nd[j] = dt[(size_t)tq*DI + d];
                nx[j] = xc[(size_t)tq*DI + d];
                nB[j] = xd[(size_t)tq*XDB + DTR + n];
                nC[j] = xd[(size_t)tq*XDB + DTR + NS + n];
                nz[j] = xz[(size_t)tq*2*DI + DI + d];
                tq += step;
            }
        } else {
#pragma unroll
            for (int j = 0; j < 4; j++) {
                nd[j] = 0.f; nx[j] = 0.f; nB[j] = 0.f; nC[j] = 0.f; nz[j] = 0.f;
            }
        }
        float ya[4];
#pragma unroll
        for (int j = 0; j < 4; j++) {
            float a = __expf(dt4[j] * A);
            h = fmaf(a, h, dt4[j] * xv4[j] * Bv4[j]);
            ya[j] = h * Cv4[j];
        }
#pragma unroll
        for (int off = 8; off; off >>= 1) {
#pragma unroll
            for (int j = 0; j < 4; j++)
                ya[j] += __shfl_xor_sync(0xffffffffu, ya[j], off);
        }
        if (n == 0) {
#pragma unroll
            for (int j = 0; j < 4; j++) {
                float sz = z4[j] / (1.f + __expf(-z4[j]));
                int tj = t + j*step;
                g_ycat_bf[(size_t)tj*2*DI + br*DI + d] =
                    __float2bfloat16(fmaf(xv4[j], Dp, ya[j]) * sz);
            }
        }
#pragma unroll
        for (int j = 0; j < 4; j++) {
            dt4[j] = nd[j]; xv4[j] = nx[j]; Bv4[j] = nB[j];
            Cv4[j] = nC[j]; z4[j]  = nz[j];
        }
        t += 4*step;
    }
}

// ---------------- launcher ----------------
extern "C" void kernel_launch(void* const* d_in, const int* in_sizes, int n_in,
                              void* d_out, int out_size)
{
    const float* u       = (const float*)d_in[0];
    const float* norm_w  = (const float*)d_in[1];
    const float* norm_b  = (const float*)d_in[2];
    const float* f_in_w  = (const float*)d_in[3];
    const float* f_cw    = (const float*)d_in[4];
    const float* f_cb    = (const float*)d_in[5];
    const float* f_Alog  = (const float*)d_in[6];
    const float* f_xpw   = (const float*)d_in[7];
    const float* f_dtw   = (const float*)d_in[8];
    const float* f_dtb   = (const float*)d_in[9];
    const float* f_D     = (const float*)d_in[10];
    const float* b_in_w  = (const float*)d_in[11];
    const float* b_cw    = (const float*)d_in[12];
    const float* b_cb    = (const float*)d_in[13];
    const float* b_Alog  = (const float*)d_in[14];
    const float* b_xpw   = (const float*)d_in[15];
    const float* b_dtw   = (const float*)d_in[16];
    const float* b_dtb   = (const float*)d_in[17];
    const float* b_D     = (const float*)d_in[18];
    const float* out_w   = (const float*)d_in[19];
    float* out = (float*)d_out;

    float *xz, *dt, *xdp;
    __nv_bfloat16 *un_bf, *xc_bf, *xd_bf, *ycat_bf;
    __nv_bfloat16 *inw_bf, *xpw_bf, *dtw_bf, *outw_bf;
    cudaGetSymbolAddress((void**)&xz,     g_xz);
    cudaGetSymbolAddress((void**)&dt,     g_dt);
    cudaGetSymbolAddress((void**)&xdp,    g_xdp);
    cudaGetSymbolAddress((void**)&un_bf,  g_un_bf);
    cudaGetSymbolAddress((void**)&xc_bf,  g_xc_bf);
    cudaGetSymbolAddress((void**)&xd_bf,  g_xd_bf);
    cudaGetSymbolAddress((void**)&ycat_bf,g_ycat_bf);
    cudaGetSymbolAddress((void**)&inw_bf, g_inw_bf);
    cudaGetSymbolAddress((void**)&xpw_bf, g_xpw_bf);
    cudaGetSymbolAddress((void**)&dtw_bf, g_dtw_bf);
    cudaGetSymbolAddress((void**)&outw_bf,g_outw_bf);

    float* xz0 = xz;   float* xz1 = xz + (size_t)TT*2*DI;
    float* dt0 = dt;   float* dt1 = dt + (size_t)TT*DI;
    __nv_bfloat16* xcb0 = xc_bf;  __nv_bfloat16* xcb1 = xc_bf + (size_t)TT*DI;
    __nv_bfloat16* xdb0 = xd_bf;  __nv_bfloat16* xdb1 = xd_bf + (size_t)TT*XDB;
    __nv_bfloat16* inw0 = inw_bf; __nv_bfloat16* inw1 = inw_bf + (size_t)IN_W;
    __nv_bfloat16* xpw0 = xpw_bf; __nv_bfloat16* xpw1 = xpw_bf + (size_t)XP_W;
    __nv_bfloat16* dtw0 = dtw_bf; __nv_bfloat16* dtw1 = dtw_bf + (size_t)DT_W;

    constexpr int SM_BIG = 3 * 32768;        // 98304
    constexpr int SM_XP  = 4 *  96 * 64;     // 24576
    constexpr int SM_DT  = 4 * 256 * 64;     // 65536
    cudaFuncSetAttribute((const void*)gemm_big<0>,
        cudaFuncAttributeMaxDynamicSharedMemorySize, SM_BIG);
    cudaFuncSetAttribute((const void*)gemm_big<2>,
        cudaFuncAttributeMaxDynamicSharedMemorySize, SM_BIG);
    cudaFuncSetAttribute((const void*)gemm_xp,
        cudaFuncAttributeMaxDynamicSharedMemorySize, SM_XP);
    cudaFuncSetAttribute((const void*)gemm_dt,
        cudaFuncAttributeMaxDynamicSharedMemorySize, SM_DT);

    // 0) weights -> bf16
    cvt_weights<<<(WTOT + 255)/256, 256>>>(f_in_w, b_in_w, f_xpw, b_xpw,
                                           f_dtw, b_dtw, out_w);
    // 1) layernorm -> bf16
    ln_kernel<<<TT, 256>>>(u, norm_w, norm_b);

    // 2) in-proj: (2048x768) -> 3072 per branch.  768 blocks.
    gemm_big<0><<<dim3(2*DI/128, TT/128, 2), 128, SM_BIG>>>(
        un_bf, un_bf, DM, inw0, inw1, DM, xz0, xz1, 2*DI, DM, nullptr);

    // 3) conv + silu
    conv_silu<<<dim3(TT*DI/4/256, 2), 256>>>(f_cw, f_cb, b_cw, b_cb);

    // 4) xproj split-K: 512 blocks -> partials, then reduce
    gemm_xp<<<dim3(XDB/64, TT/32, 4), 128, SM_XP>>>(
        xcb0, xcb1, xpw0, xpw1, xdp);
    reduce_xd<<<dim3(TT*XDB/4/256, 2), 256>>>();

    // 5) dt: (2048x96) -> 1536, softplus+bias
    gemm_dt<<<dim3(DI/128, TT/128, 2), 256, SM_DT>>>(
        xdb0, xdb1, dtw0, dtw1, dt0, dt1, f_dtb, b_dtb);

    // 6) selective scan + gate -> bf16 ycat
    scan_kernel<<<dim3(DI/8, Bb, 2), 128>>>(f_Alog, b_Alog, f_D, b_D);

    // 7) out-proj + residual: (2048x3072) -> 768.  96 blocks, K=3072.
    gemm_big<2><<<dim3(DM/128, TT/128, 1), 128, SM_BIG>>>(
        ycat_bf, ycat_bf, 2*DI, outw_bf, outw_bf, 2*DI, out, out, DM,
        2*DI, u);
}

// round 8
// speedup vs baseline: 4.7711x; 1.0208x over previous
#include <cuda_runtime.h>
#include <cuda_bf16.h>
#include <math.h>
#include <stdint.h>

#define Bb   2
#define Lseq 1024
#define DM   768
#define DI   1536
#define NS   16
#define DTR  96
#define XDB  (DTR + 2*NS)   // 128
#define TT   (Bb*Lseq)      // 2048

#define IN_W  (2*DI*DM)
#define XP_W  (XDB*DI)
#define DT_W  (DI*DTR)
#define OUT_W (DM*2*DI)
#define WTOT  (2*IN_W + 2*XP_W + 2*DT_W + OUT_W)
#define OSPLIT 4

// ---------------- fp32 scratch ----------------
__device__ float g_xz[2][TT*2*DI];
__device__ float g_xc[2][TT*DI];
__device__ float g_xdbl[2][TT*XDB];
__device__ float g_dt[2][TT*DI];
__device__ float g_xdp[4][TT*XDB];        // xproj split-K partials
__device__ float g_odp[OSPLIT][TT*DM];    // out-proj split-K partials
// ---------------- bf16 scratch ----------------
__device__ __nv_bfloat16 g_un_bf[TT*DM];
__device__ __nv_bfloat16 g_xc_bf[2][TT*DI];
__device__ __nv_bfloat16 g_xd_bf[2][TT*XDB];
__device__ __nv_bfloat16 g_ycat_bf[TT*2*DI];
__device__ __nv_bfloat16 g_inw_bf[2][IN_W];
__device__ __nv_bfloat16 g_xpw_bf[2][XP_W];
__device__ __nv_bfloat16 g_dtw_bf[2][DT_W];
__device__ __nv_bfloat16 g_outw_bf[OUT_W];

// ---------------- helpers ----------------
__device__ __forceinline__ void cp16(uint32_t dst_s, const void* src) {
    asm volatile("cp.async.ca.shared.global [%0], [%1], 16;\n" :: "r"(dst_s), "l"(src));
}
__device__ __forceinline__ void cp_commit() {
    asm volatile("cp.async.commit_group;\n");
}
template<int N> __device__ __forceinline__ void cp_wait() {
    asm volatile("cp.async.wait_group %0;\n" :: "n"(N));
}
__device__ __forceinline__ void ldsm4(uint32_t& r0, uint32_t& r1,
                                      uint32_t& r2, uint32_t& r3, uint32_t a) {
    asm volatile("ldmatrix.sync.aligned.m8n8.x4.shared.b16 {%0,%1,%2,%3}, [%4];\n"
        : "=r"(r0), "=r"(r1), "=r"(r2), "=r"(r3) : "r"(a));
}
__device__ __forceinline__ void mma_bf16(
    float& c0, float& c1, float& c2, float& c3,
    uint32_t a0, uint32_t a1, uint32_t a2, uint32_t a3,
    uint32_t b0, uint32_t b1)
{
    asm volatile(
        "mma.sync.aligned.m16n8k16.row.col.f32.bf16.bf16.f32 "
        "{%0,%1,%2,%3}, {%4,%5,%6,%7}, {%8,%9}, {%0,%1,%2,%3};\n"
        : "+f"(c0), "+f"(c1), "+f"(c2), "+f"(c3)
        : "r"(a0), "r"(a1), "r"(a2), "r"(a3), "r"(b0), "r"(b1));
}
__device__ __forceinline__ uint32_t pk2(float a, float b) {
    __nv_bfloat162 h = __float22bfloat162_rn(make_float2(a, b));
    return *reinterpret_cast<uint32_t*>(&h);
}

// ---------------- weight conversion (vectorized x8) ----------------
__global__ __launch_bounds__(256) void cvt_weights(
    const float* __restrict__ fw, const float* __restrict__ bw,
    const float* __restrict__ fx, const float* __restrict__ bx,
    const float* __restrict__ fd, const float* __restrict__ bd,
    const float* __restrict__ ow)
{
    long long i = ((long long)blockIdx.x * 256 + threadIdx.x) * 8;
    const float* s; __nv_bfloat16* dst;
    if (i < IN_W)                 { s = fw + i; dst = &g_inw_bf[0][i]; }
    else if ((i -= IN_W) < IN_W)  { s = bw + i; dst = &g_inw_bf[1][i]; }
    else if ((i -= IN_W) < XP_W)  { s = fx + i; dst = &g_xpw_bf[0][i]; }
    else if ((i -= XP_W) < XP_W)  { s = bx + i; dst = &g_xpw_bf[1][i]; }
    else if ((i -= XP_W) < DT_W)  { s = fd + i; dst = &g_dtw_bf[0][i]; }
    else if ((i -= DT_W) < DT_W)  { s = bd + i; dst = &g_dtw_bf[1][i]; }
    else if ((i -= DT_W) < OUT_W) { s = ow + i; dst = &g_outw_bf[i]; }
    else return;
    float4 lo = *(const float4*)s;
    float4 hi = *(const float4*)(s + 4);
    uint4 o;
    o.x = pk2(lo.x, lo.y); o.y = pk2(lo.z, lo.w);
    o.z = pk2(hi.x, hi.y); o.w = pk2(hi.z, hi.w);
    *(uint4*)dst = o;
}

// ---------------- layernorm (bf16 out) ----------------
__global__ __launch_bounds__(256) void ln_kernel(const float* __restrict__ u,
                                                 const float* __restrict__ w,
                                                 const float* __restrict__ bvec)
{
    int t = blockIdx.x;
    const float* row = u + (size_t)t * DM;
    float v[3];
    float s = 0.f, s2 = 0.f;
#pragma unroll
    for (int i = 0; i < 3; i++) {
        v[i] = row[threadIdx.x + i*256];
        s  += v[i];
        s2 += v[i]*v[i];
    }
#pragma unroll
    for (int o = 16; o; o >>= 1) {
        s  += __shfl_xor_sync(0xffffffffu, s,  o);
        s2 += __shfl_xor_sync(0xffffffffu, s2, o);
    }
    __shared__ float ss[8], ss2[8];
    int wid = threadIdx.x >> 5, ln = threadIdx.x & 31;
    if (ln == 0) { ss[wid] = s; ss2[wid] = s2; }
    __syncthreads();
    float ts = 0.f, ts2 = 0.f;
#pragma unroll
    for (int i = 0; i < 8; i++) { ts += ss[i]; ts2 += ss2[i]; }
    float mu  = ts * (1.f/DM);
    float var = ts2 * (1.f/DM) - mu*mu;
    float rs  = rsqrtf(var + 1e-5f);
#pragma unroll
    for (int i = 0; i < 3; i++) {
        int c = threadIdx.x + i*256;
        g_un_bf[(size_t)t*DM + c] = __float2bfloat16((v[i]-mu)*rs*w[c] + bvec[c]);
    }
}

// ======== gemm_big: 128x128 CTA tile, 4 warps (64x64 each), k64 slabs ========
// C[m,n] = sum_k A[m,k] * W[n,k].
// MODE 0: plain fp32 (z = branch).  MODE 2: + resid (z = branch).
// MODE 3: split-K (z = k-chunk of size K; partial -> C0 + z*TT*DM).
template<int MODE>
__global__ void __launch_bounds__(128) gemm_big(
    const __nv_bfloat16* __restrict__ A0, const __nv_bfloat16* __restrict__ A1, int lda,
    const __nv_bfloat16* __restrict__ W0, const __nv_bfloat16* __restrict__ W1, int ldw,
    float* __restrict__ C0, float* __restrict__ C1, int ldc,
    int K, const float* __restrict__ resid)
{
    extern __shared__ char smem[];
    uint32_t sb = (uint32_t)__cvta_generic_to_shared(smem);

    const __nv_bfloat16* A;
    const __nv_bfloat16* W;
    float* C;
    if (MODE == 3) {
        A = A0 + (size_t)blockIdx.z * K;
        W = W0 + (size_t)blockIdx.z * K;
        C = C0 + (size_t)blockIdx.z * ((size_t)TT * DM);
    } else {
        A = blockIdx.z ? A1 : A0;
        W = blockIdx.z ? W1 : W0;
        C = blockIdx.z ? C1 : C0;
    }

    int tid  = threadIdx.x;
    int lane = tid & 31;
    int w    = tid >> 5;
    int wm   = w >> 1;
    int wn   = w & 1;
    int bm   = blockIdx.y * 128;
    int bn   = blockIdx.x * 128;

    int ch = tid & 7;
    int rb = tid >> 3;
    const __nv_bfloat16* ap = A + (size_t)(bm + rb) * lda + ch * 8;
    const __nv_bfloat16* wp = W + (size_t)(bn + rb) * ldw + ch * 8;
    uint32_t ao = (uint32_t)(rb * 128 + ((ch ^ (rb & 7)) * 16));
    uint32_t bo = 16384u + ao;

    int nk = K / 64;
#pragma unroll
    for (int p = 0; p < 2; p++) {
#pragma unroll
        for (int v = 0; v < 8; v++) {
            cp16(sb + p*32768 + ao + v*2048, ap + (size_t)v*16*lda + p*64);
            cp16(sb + p*32768 + bo + v*2048, wp + (size_t)v*16*ldw + p*64);
        }
        cp_commit();
    }

    float acc[4][8][4] = {};
    int arow = lane & 15;
    int ach  = lane >> 4;
    int brow = ((lane >> 4) << 3) + (lane & 7);
    int bch  = (lane >> 3) & 1;
    int r0   = lane >> 2;
    int c0   = lane & 3;

    for (int i = 0; i < nk; i++) {
        int st = i % 3;
        cp_wait<1>();
        __syncthreads();
        {
            int s2 = (i + 2) % 3;
            if (i + 2 < nk) {
#pragma unroll
                for (int v = 0; v < 8; v++) {
                    cp16(sb + s2*32768 + ao + v*2048, ap + (size_t)v*16*lda + (i+2)*64);
                    cp16(sb + s2*32768 + bo + v*2048, wp + (size_t)v*16*ldw + (i+2)*64);
                }
            }
            cp_commit();
        }
        uint32_t base = sb + st*32768;
#pragma unroll
        for (int kk = 0; kk < 4; kk++) {
            uint32_t ar[4][4];
#pragma unroll
            for (int ii = 0; ii < 4; ii++) {
                int row = wm*64 + ii*16 + arow;
                int pos = (2*kk + ach) ^ (row & 7);
                ldsm4(ar[ii][0], ar[ii][1], ar[ii][2], ar[ii][3],
                      base + row*128 + pos*16);
            }
            uint32_t br_[8][2];
#pragma unroll
            for (int j2 = 0; j2 < 4; j2++) {
                int row = wn*64 + j2*16 + brow;
                int pos = (2*kk + bch) ^ (row & 7);
                ldsm4(br_[2*j2][0], br_[2*j2][1], br_[2*j2+1][0], br_[2*j2+1][1],
                      base + 16384 + row*128 + pos*16);
            }
#pragma unroll
            for (int ii = 0; ii < 4; ii++)
#pragma unroll
                for (int j = 0; j < 8; j++)
                    mma_bf16(acc[ii][j][0], acc[ii][j][1],
                             acc[ii][j][2], acc[ii][j][3],
                             ar[ii][0], ar[ii][1], ar[ii][2], ar[ii][3],
                             br_[j][0], br_[j][1]);
        }
    }

#pragma unroll
    for (int ii = 0; ii < 4; ii++) {
        int m0 = bm + wm*64 + ii*16 + r0;
#pragma unroll
        for (int j = 0; j < 8; j++) {
            int n0 = bn + wn*64 + j*8 + c0*2;
            float v0 = acc[ii][j][0], v1 = acc[ii][j][1];
            float v2 = acc[ii][j][2], v3 = acc[ii][j][3];
            if (MODE == 2) {
                const float2 rr0 = *(const float2*)&resid[(size_t)m0 * ldc + n0];
                const float2 rr1 = *(const float2*)&resid[(size_t)(m0+8) * ldc + n0];
                v0 += rr0.x; v1 += rr0.y; v2 += rr1.x; v3 += rr1.y;
            }
            *(float2*)&C[(size_t)m0 * ldc + n0]     = make_float2(v0, v1);
            *(float2*)&C[(size_t)(m0+8) * ldc + n0] = make_float2(v2, v3);
        }
    }
}

// ---------------- out-proj reduce: partials + residual -> out ----------------
__global__ __launch_bounds__(256) void reduce_out(const float* __restrict__ u,
                                                  float* __restrict__ out)
{
    int i4 = (blockIdx.x * 256 + threadIdx.x) * 4;
    if (i4 >= TT*DM) return;
    float4 s = *(const float4*)&u[i4];
#pragma unroll
    for (int p = 0; p < OSPLIT; p++) {
        float4 a = *(const float4*)&g_odp[p][i4];
        s.x += a.x; s.y += a.y; s.z += a.z; s.w += a.w;
    }
    *(float4*)&out[i4] = s;
}

// ======== gemm_xp: xproj split-K.  BM=32, BN=64, 4 warps, K=768/part ========
__global__ void __launch_bounds__(128) gemm_xp(
    const __nv_bfloat16* __restrict__ Ab0, const __nv_bfloat16* __restrict__ Ab1,
    const __nv_bfloat16* __restrict__ Wb0, const __nv_bfloat16* __restrict__ Wb1,
    float* __restrict__ Cp)
{
    constexpr int BM = 32, BN = 64, THREADS = 128;
    constexpr int SWORDS = (BM + BN) * 16;
    constexpr int LPT = (BM + BN) * 4 / THREADS;   // 3
    constexpr int KPART = 768;

    extern __shared__ uint32_t sm[];
    uint32_t smem_base = (uint32_t)__cvta_generic_to_shared(sm);

    int z  = blockIdx.z;
    int br = z >> 1;
    int kh = z & 1;
    const __nv_bfloat16* A = (br ? Ab1 : Ab0) + kh * KPART;
    const __nv_bfloat16* W = (br ? Wb1 : Wb0) + kh * KPART;
    float* C = Cp + (size_t)z * (TT*XDB);

    int tid  = threadIdx.x;
    int lane = tid & 31;
    int w    = tid >> 5;
    int wm   = w >> 1;
    int wn   = w & 1;
    int bm   = blockIdx.y * BM;
    int bn   = blockIdx.x * BN;
    int r0   = lane >> 2;
    int c0   = lane & 3;

    const __nv_bfloat16* lsrc[LPT];
    uint32_t ldst[LPT];
#pragma unroll
    for (int u = 0; u < LPT; u++) {
        int i   = tid + u * THREADS;
        int row = i >> 2;
        int x   = i & 3;
        if (row < BM) {
            lsrc[u] = A + (size_t)(bm + row) * DI + x * 8;
            ldst[u] = row * 16 + (x ^ ((row >> 1) & 3)) * 4;
        } else {
            int r = row - BM;
            lsrc[u] = W + (size_t)(bn + r) * DI + x * 8;
            ldst[u] = BM * 16 + r * 16 + (x ^ ((r >> 1) & 3)) * 4;
        }
    }

    constexpr int nk = KPART / 32;   // 24
#pragma unroll
    for (int p = 0; p < 3; p++) {
#pragma unroll
        for (int u = 0; u < LPT; u++)
            cp16(smem_base + (p*SWORDS + ldst[u])*4, lsrc[u] + p*32);
        cp_commit();
    }

    float acc[1][4][4] = {};
    int arow = lane & 15;
    int ach  = lane >> 4;
    int brow = ((lane >> 4) << 3) + (lane & 7);
    int bch  = (lane >> 3) & 1;

    for (int i = 0; i < nk; i++) {
        int st = i & 3;
        int rem = nk - 1 - i;
        if (rem >= 2)      cp_wait<2>();
        else if (rem == 1) cp_wait<1>();
        else               cp_wait<0>();
        __syncthreads();
        if (i + 3 < nk) {
            int st2 = (i + 3) & 3;
#pragma unroll
            for (int u = 0; u < LPT; u++)
                cp16(smem_base + (st2*SWORDS + ldst[u])*4, lsrc[u] + (i+3)*32);
            cp_commit();
        }
        uint32_t stw = smem_base + st*SWORDS*4;
#pragma unroll
        for (int kk = 0; kk < 2; kk++) {
            uint32_t ar[4];
            {
                int row = wm*16 + arow;
                int pos = (2*kk + ach) ^ ((row >> 1) & 3);
                ldsm4(ar[0], ar[1], ar[2], ar[3], stw + (row*16 + pos*4)*4);
            }
            uint32_t br_[4][2];
#pragma unroll
            for (int j2 = 0; j2 < 2; j2++) {
                int row = wn*32 + j2*16 + brow;
                int pos = (2*kk + bch) ^ ((row >> 1) & 3);
                ldsm4(br_[2*j2][0], br_[2*j2][1], br_[2*j2+1][0], br_[2*j2+1][1],
                      stw + (BM*16 + row*16 + pos*4)*4);
            }
#pragma unroll
            for (int j = 0; j < 4; j++)
                mma_bf16(acc[0][j][0], acc[0][j][1], acc[0][j][2], acc[0][j][3],
                         ar[0], ar[1], ar[2], ar[3], br_[j][0], br_[j][1]);
        }
    }

    {
        int m0 = bm + wm*16 + r0;
#pragma unroll
        for (int j = 0; j < 4; j++) {
            int n0 = bn + wn*32 + j*8 + c0*2;
            *(float2*)&C[(size_t)m0 * XDB + n0]     = make_float2(acc[0][j][0], acc[0][j][1]);
            *(float2*)&C[(size_t)(m0+8) * XDB + n0] = make_float2(acc[0][j][2], acc[0][j][3]);
        }
    }
}

// ---------------- reduce xproj partials -> fp32 + bf16 ----------------
__global__ __launch_bounds__(256) void reduce_xd()
{
    int br = blockIdx.y;
    int i4 = (blockIdx.x * 256 + threadIdx.x) * 4;
    if (i4 >= TT*XDB) return;
    float4 a = *(const float4*)&g_xdp[br*2 + 0][i4];
    float4 b = *(const float4*)&g_xdp[br*2 + 1][i4];
    float4 s = make_float4(a.x+b.x, a.y+b.y, a.z+b.z, a.w+b.w);
    *(float4*)&g_xdbl[br][i4] = s;
    *(__nv_bfloat162*)&g_xd_bf[br][i4]   = __float22bfloat162_rn(make_float2(s.x, s.y));
    *(__nv_bfloat162*)&g_xd_bf[br][i4+2] = __float22bfloat162_rn(make_float2(s.z, s.w));
}

// ---------------- dt GEMM: mma.sync, 128x128, K=96, softplus ----------------
__global__ void __launch_bounds__(256) gemm_dt(
    const __nv_bfloat16* __restrict__ A0, const __nv_bfloat16* __restrict__ A1,
    const __nv_bfloat16* __restrict__ W0, const __nv_bfloat16* __restrict__ W1,
    float* __restrict__ C0, float* __restrict__ C1,
    const float* __restrict__ bias0, const float* __restrict__ bias1)
{
    constexpr int BM = 128, BN = 128, THREADS = 256;
    constexpr int SWORDS = (BM + BN) * 16;
    constexpr int LPT = (BM + BN) * 4 / THREADS;  // 4
    constexpr int K = DTR;                        // 96

    extern __shared__ uint32_t sm[];
    uint32_t smem_base = (uint32_t)__cvta_generic_to_shared(sm);

    const __nv_bfloat16* A = blockIdx.z ? A1 : A0;
    const __nv_bfloat16* W = blockIdx.z ? W1 : W0;
    float*       C    = blockIdx.z ? C1 : C0;
    const float* bias = blockIdx.z ? bias1 : bias0;

    int tid  = threadIdx.x;
    int lane = tid & 31;
    int w    = tid >> 5;
    int wm   = w >> 1;
    int wn   = w & 1;
    int bm   = blockIdx.y * BM;
    int bn   = blockIdx.x * BN;
    int r0   = lane >> 2;
    int c0   = lane & 3;

    const __nv_bfloat16* lsrc[LPT];
    uint32_t ldst[LPT];
#pragma unroll
    for (int u = 0; u < LPT; u++) {
        int i   = tid + u * THREADS;
        int row = i >> 2;
        int x   = i & 3;
        if (row < BM) {
            lsrc[u] = A + (size_t)(bm + row) * XDB + x * 8;
            ldst[u] = row * 16 + (x ^ ((row >> 1) & 3)) * 4;
        } else {
            int r = row - BM;
            lsrc[u] = W + (size_t)(bn + r) * DTR + x * 8;
            ldst[u] = BM * 16 + r * 16 + (x ^ ((r >> 1) & 3)) * 4;
        }
    }

    constexpr int nk = K / 32;   // 3
#pragma unroll
    for (int p = 0; p < 3; p++) {
#pragma unroll
        for (int u = 0; u < LPT; u++)
            cp16(smem_base + (p*SWORDS + ldst[u])*4, lsrc[u] + p*32);
        cp_commit();
    }

    float acc[2][8][4] = {};
    int arow = lane & 15;
    int ach  = lane >> 4;
    int brow = ((lane >> 4) << 3) + (lane & 7);
    int bch  = (lane >> 3) & 1;

    for (int i = 0; i < nk; i++) {
        int st = i & 3;
        int rem = nk - 1 - i;
        if (rem >= 2)      cp_wait<2>();
        else if (rem == 1) cp_wait<1>();
        else               cp_wait<0>();
        __syncthreads();
        uint32_t stw = smem_base + st*SWORDS*4;
#pragma unroll
        for (int kk = 0; kk < 2; kk++) {
            uint32_t ar[2][4];
#pragma unroll
            for (int ii = 0; ii < 2; ii++) {
                int row = wm*32 + ii*16 + arow;
                int pos = (2*kk + ach) ^ ((row >> 1) & 3);
                ldsm4(ar[ii][0], ar[ii][1], ar[ii][2], ar[ii][3],
                      stw + (row*16 + pos*4)*4);
            }
            uint32_t br_[8][2];
#pragma unroll
            for (int j2 = 0; j2 < 4; j2++) {
                int row = wn*64 + j2*16 + brow;
                int pos = (2*kk + bch) ^ ((row >> 1) & 3);
                ldsm4(br_[2*j2][0], br_[2*j2][1], br_[2*j2+1][0], br_[2*j2+1][1],
                      stw + (BM*16 + row*16 + pos*4)*4);
            }
#pragma unroll
            for (int ii = 0; ii < 2; ii++)
#pragma unroll
                for (int j = 0; j < 8; j++)
                    mma_bf16(acc[ii][j][0], acc[ii][j][1],
                             acc[ii][j][2], acc[ii][j][3],
                             ar[ii][0], ar[ii][1], ar[ii][2], ar[ii][3],
                             br_[j][0], br_[j][1]);
        }
    }

#pragma unroll
    for (int ii = 0; ii < 2; ii++) {
        int m0 = bm + wm*32 + ii*16 + r0;
#pragma unroll
        for (int j = 0; j < 8; j++) {
            int n0 = bn + wn*64 + j*8 + c0*2;
            float v0 = acc[ii][j][0], v1 = acc[ii][j][1];
            float v2 = acc[ii][j][2], v3 = acc[ii][j][3];
            float b0v = bias[n0], b1v = bias[n0 + 1];
            v0 += b0v; v1 += b1v; v2 += b0v; v3 += b1v;
            v0 = fmaxf(v0, 0.f) + log1pf(__expf(-fabsf(v0)));
            v1 = fmaxf(v1, 0.f) + log1pf(__expf(-fabsf(v1)));
            v2 = fmaxf(v2, 0.f) + log1pf(__expf(-fabsf(v2)));
            v3 = fmaxf(v3, 0.f) + log1pf(__expf(-fabsf(v3)));
            *(float2*)&C[(size_t)m0 * DI + n0]     = make_float2(v0, v1);
            *(float2*)&C[(size_t)(m0+8) * DI + n0] = make_float2(v2, v3);
        }
    }
}

// ---------------- depthwise conv (K=4) + silu; 4 tokens x 4 channels ----------------
__global__ __launch_bounds__(256) void conv_silu(
    const float* __restrict__ cw0, const float* __restrict__ cb0,
    const float* __restrict__ cw1, const float* __restrict__ cb1)
{
    int br = blockIdx.y;
    const float* cw = br ? cw1 : cw0;
    const float* cb = br ? cb1 : cb0;
    const float* xz = g_xz[br];

    constexpr int ND4 = DI/4;
    int idx = blockIdx.x * 256 + threadIdx.x;
    if (idx >= (TT/4)*ND4) return;
    int tq = idx / ND4;
    int d4 = (idx % ND4) * 4;
    int t0 = tq * 4;
    int l0 = t0 % Lseq;

    float4 wr[4];
#pragma unroll
    for (int i = 0; i < 4; i++) wr[i] = *(const float4*)&cw[(d4+i)*4];
    float4 b4 = *(const float4*)&cb[d4];

    float4 xr[7];
    if (br == 0) {
#pragma unroll
        for (int j = 0; j < 7; j++) {
            int off = j - 3;
            xr[j] = (l0 + off >= 0)
                  ? *(const float4*)&xz[(size_t)(t0+off)*2*DI + d4]
                  : make_float4(0.f,0.f,0.f,0.f);
        }
    } else {
#pragma unroll
        for (int j = 0; j < 7; j++) {
            xr[j] = (l0 + j < Lseq)
                  ? *(const float4*)&xz[(size_t)(t0+j)*2*DI + d4]
                  : make_float4(0.f,0.f,0.f,0.f);
        }
    }

    const float* X  = (const float*)xr;
    const float* Wp = (const float*)wr;
    const float* Bp = (const float*)&b4;
#pragma unroll
    for (int i2 = 0; i2 < 4; i2++) {
        float o[4];
#pragma unroll
        for (int c = 0; c < 4; c++) {
            float a = Bp[c];
            if (br == 0) {
                a = fmaf(Wp[c*4+0], X[i2*4+c],     a);
                a = fmaf(Wp[c*4+1], X[(i2+1)*4+c], a);
                a = fmaf(Wp[c*4+2], X[(i2+2)*4+c], a);
                a = fmaf(Wp[c*4+3], X[(i2+3)*4+c], a);
            } else {
                a = fmaf(Wp[c*4+3], X[i2*4+c],     a);
                a = fmaf(Wp[c*4+2], X[(i2+1)*4+c], a);
                a = fmaf(Wp[c*4+1], X[(i2+2)*4+c], a);
                a = fmaf(Wp[c*4+0], X[(i2+3)*4+c], a);
            }
            float sg = 1.f / (1.f + __expf(-a));
            o[c] = a * sg;
        }
        int t = t0 + i2;
        *(float4*)&g_xc[br][(size_t)t*DI + d4] = make_float4(o[0], o[1], o[2], o[3]);
        *(__nv_bfloat162*)&g_xc_bf[br][(size_t)t*DI + d4] =
            __float22bfloat162_rn(make_float2(o[0], o[1]));
        *(__nv_bfloat162*)&g_xc_bf[br][(size_t)t*DI + d4 + 2] =
            __float22bfloat162_rn(make_float2(o[2], o[3]));
    }
}

// ---------------- selective scan: 4-step pipelined reduction ----------------
__global__ __launch_bounds__(128) void scan_kernel(
    const float* __restrict__ Alog0, const float* __restrict__ Alog1,
    const float* __restrict__ Dv0,   const float* __restrict__ Dv1)
{
    int br = blockIdx.z;
    int b  = blockIdx.y;
    const float* Alog = br ? Alog1 : Alog0;
    const float* Dvec = br ? Dv1   : Dv0;
    const float* dt   = g_dt[br];
    const float* xc   = g_xc[br];
    const float* xd   = g_xdbl[br];
    const float* xz   = g_xz[br];

    int lane = threadIdx.x & 31;
    int warp = threadIdx.x >> 5;
    int n    = lane & 15;
    int d    = blockIdx.x * 8 + warp * 2 + (lane >> 4);

    float A  = -__expf(Alog[d*NS + n]);
    float Dp = Dvec[d];
    float h  = 0.f;

    int step = br ? -1 : 1;
    int t = b*Lseq + (br ? Lseq-1 : 0);

    float dt4[4], xv4[4], Bv4[4], Cv4[4], z4[4];
    {
        int tq = t;
#pragma unroll
        for (int j = 0; j < 4; j++) {
            dt4[j] = dt[(size_t)tq*DI + d];
            xv4[j] = xc[(size_t)tq*DI + d];
            Bv4[j] = xd[(size_t)tq*XDB + DTR + n];
            Cv4[j] = xd[(size_t)tq*XDB + DTR + NS + n];
            z4[j]  = xz[(size_t)tq*2*DI + DI + d];
            tq += step;
        }
    }

    for (int s = 0; s < Lseq; s += 4) {
        float nd[4], nx[4], nB[4], nC[4], nz[4];
        if (s + 4 < Lseq) {
            int tq = t + 4*step;
#pragma unroll
            for (int j = 0; j < 4; j++) {
                nd[j] = dt[(size_t)tq*DI + d];
                nx[j] = xc[(size_t)tq*DI + d];
                nB[j] = xd[(size_t)tq*XDB + DTR + n];
                nC[j] = xd[(size_t)tq*XDB + DTR + NS + n];
                nz[j] = xz[(size_t)tq*2*DI + DI + d];
                tq += step;
            }
        } else {
#pragma unroll
            for (int j = 0; j < 4; j++) {
                nd[j] = 0.f; nx[j] = 0.f; nB[j] = 0.f; nC[j] = 0.f; nz[j] = 0.f;
            }
        }
        float ya[4];
#pragma unroll
        for (int j = 0; j < 4; j++) {
            float a = __expf(dt4[j] * A);
            h = fmaf(a, h, dt4[j] * xv4[j] * Bv4[j]);
            ya[j] = h * Cv4[j];
        }
#pragma unroll
        for (int off = 8; off; off >>= 1) {
#pragma unroll
            for (int j = 0; j < 4; j++)
                ya[j] += __shfl_xor_sync(0xffffffffu, ya[j], off);
        }
        if (n == 0) {
#pragma unroll
            for (int j = 0; j < 4; j++) {
                float sz = z4[j] / (1.f + __expf(-z4[j]));
                int tj = t + j*step;
                g_ycat_bf[(size_t)tj*2*DI + br*DI + d] =
                    __float2bfloat16(fmaf(xv4[j], Dp, ya[j]) * sz);
            }
        }
#pragma unroll
        for (int j = 0; j < 4; j++) {
            dt4[j] = nd[j]; xv4[j] = nx[j]; Bv4[j] = nB[j];
            Cv4[j] = nC[j]; z4[j]  = nz[j];
        }
        t += 4*step;
    }
}

// ---------------- launcher ----------------
extern "C" void kernel_launch(void* const* d_in, const int* in_sizes, int n_in,
                              void* d_out, int out_size)
{
    const float* u       = (const float*)d_in[0];
    const float* norm_w  = (const float*)d_in[1];
    const float* norm_b  = (const float*)d_in[2];
    const float* f_in_w  = (const float*)d_in[3];
    const float* f_cw    = (const float*)d_in[4];
    const float* f_cb    = (const float*)d_in[5];
    const float* f_Alog  = (const float*)d_in[6];
    const float* f_xpw   = (const float*)d_in[7];
    const float* f_dtw   = (const float*)d_in[8];
    const float* f_dtb   = (const float*)d_in[9];
    const float* f_D     = (const float*)d_in[10];
    const float* b_in_w  = (const float*)d_in[11];
    const float* b_cw    = (const float*)d_in[12];
    const float* b_cb    = (const float*)d_in[13];
    const float* b_Alog  = (const float*)d_in[14];
    const float* b_xpw   = (const float*)d_in[15];
    const float* b_dtw   = (const float*)d_in[16];
    const float* b_dtb   = (const float*)d_in[17];
    const float* b_D     = (const float*)d_in[18];
    const float* out_w   = (const float*)d_in[19];
    float* out = (float*)d_out;

    float *xz, *dt, *xdp, *odp;
    __nv_bfloat16 *un_bf, *xc_bf, *xd_bf, *ycat_bf;
    __nv_bfloat16 *inw_bf, *xpw_bf, *dtw_bf, *outw_bf;
    cudaGetSymbolAddress((void**)&xz,     g_xz);
    cudaGetSymbolAddress((void**)&dt,     g_dt);
    cudaGetSymbolAddress((void**)&xdp,    g_xdp);
    cudaGetSymbolAddress((void**)&odp,    g_odp);
    cudaGetSymbolAddress((void**)&un_bf,  g_un_bf);
    cudaGetSymbolAddress((void**)&xc_bf,  g_xc_bf);
    cudaGetSymbolAddress((void**)&xd_bf,  g_xd_bf);
    cudaGetSymbolAddress((void**)&ycat_bf,g_ycat_bf);
    cudaGetSymbolAddress((void**)&inw_bf, g_inw_bf);
    cudaGetSymbolAddress((void**)&xpw_bf, g_xpw_bf);
    cudaGetSymbolAddress((void**)&dtw_bf, g_dtw_bf);
    cudaGetSymbolAddress((void**)&outw_bf,g_outw_bf);

    float* xz0 = xz;   float* xz1 = xz + (size_t)TT*2*DI;
    float* dt0 = dt;   float* dt1 = dt + (size_t)TT*DI;
    __nv_bfloat16* xcb0 = xc_bf;  __nv_bfloat16* xcb1 = xc_bf + (size_t)TT*DI;
    __nv_bfloat16* xdb0 = xd_bf;  __nv_bfloat16* xdb1 = xd_bf + (size_t)TT*XDB;
    __nv_bfloat16* inw0 = inw_bf; __nv_bfloat16* inw1 = inw_bf + (size_t)IN_W;
    __nv_bfloat16* xpw0 = xpw_bf; __nv_bfloat16* xpw1 = xpw_bf + (size_t)XP_W;
    __nv_bfloat16* dtw0 = dtw_bf; __nv_bfloat16* dtw1 = dtw_bf + (size_t)DT_W;

    constexpr int SM_BIG = 3 * 32768;        // 98304
    constexpr int SM_XP  = 4 *  96 * 64;     // 24576
    constexpr int SM_DT  = 4 * 256 * 64;     // 65536
    cudaFuncSetAttribute((const void*)gemm_big<0>,
        cudaFuncAttributeMaxDynamicSharedMemorySize, SM_BIG);
    cudaFuncSetAttribute((const void*)gemm_big<3>,
        cudaFuncAttributeMaxDynamicSharedMemorySize, SM_BIG);
    cudaFuncSetAttribute((const void*)gemm_xp,
        cudaFuncAttributeMaxDynamicSharedMemorySize, SM_XP);
    cudaFuncSetAttribute((const void*)gemm_dt,
        cudaFuncAttributeMaxDynamicSharedMemorySize, SM_DT);

    // 0) weights -> bf16 (vectorized)
    cvt_weights<<<(WTOT/8 + 255)/256, 256>>>(f_in_w, b_in_w, f_xpw, b_xpw,
                                             f_dtw, b_dtw, out_w);
    // 1) layernorm -> bf16
    ln_kernel<<<TT, 256>>>(u, norm_w, norm_b);

    // 2) in-proj: (2048x768) -> 3072 per branch.  768 blocks.
    gemm_big<0><<<dim3(2*DI/128, TT/128, 2), 128, SM_BIG>>>(
        un_bf, un_bf, DM, inw0, inw1, DM, xz0, xz1, 2*DI, DM, nullptr);

    // 3) conv + silu (4 tokens/thread)
    conv_silu<<<dim3((TT/4)*(DI/4)/256, 2), 256>>>(f_cw, f_cb, b_cw, b_cb);

    // 4) xproj split-K: 512 blocks -> partials, then reduce
    gemm_xp<<<dim3(XDB/64, TT/32, 4), 128, SM_XP>>>(
        xcb0, xcb1, xpw0, xpw1, xdp);
    reduce_xd<<<dim3(TT*XDB/4/256, 2), 256>>>();

    // 5) dt: (2048x96) -> 1536, softplus+bias
    gemm_dt<<<dim3(DI/128, TT/128, 2), 256, SM_DT>>>(
        xdb0, xdb1, dtw0, dtw1, dt0, dt1, f_dtb, b_dtb);

    // 6) selective scan + gate -> bf16 ycat
    scan_kernel<<<dim3(DI/8, Bb, 2), 128>>>(f_Alog, b_Alog, f_D, b_D);

    // 7) out-proj split-K x4: 384 blocks, K=768 each -> partials
    gemm_big<3><<<dim3(DM/128, TT/128, OSPLIT), 128, SM_BIG>>>(
        ycat_bf, nullptr, 2*DI, outw_bf, nullptr, 2*DI, odp, nullptr, DM,
        (2*DI)/OSPLIT, nullptr);
    // 8) reduce partials + residual -> out
    reduce_out<<<TT*DM/4/256, 256>>>(u, out);
}

// round 9
// speedup vs baseline: 5.9524x; 1.2476x over previous
#include <cuda_runtime.h>
#include <cuda_bf16.h>
#include <math.h>
#include <stdint.h>

#define Bb   2
#define Lseq 1024
#define DM   768
#define DI   1536
#define NS   16
#define DTR  96
#define XDB  (DTR + 2*NS)   // 128
#define TT   (Bb*Lseq)      // 2048

#define IN_W  (2*DI*DM)
#define XP_W  (XDB*DI)
#define DT_W  (DI*DTR)
#define OUT_W (DM*2*DI)
#define WTOT  (2*IN_W + 2*XP_W + 2*DT_W + OUT_W)   // 7766016
#define NCVT  (WTOT/8/256)                          // 3792 blocks
#define OSPLIT 2

// ---------------- fp32 scratch ----------------
__device__ float g_xz[2][TT*2*DI];
__device__ float g_xc[2][TT*DI];
__device__ float g_xdbl[2][TT*XDB];
__device__ float g_dt[2][TT*DI];
__device__ float g_xdp[4][TT*XDB];        // xproj split-K partials
__device__ float g_odp[OSPLIT][TT*DM];    // out-proj split-K partials
__device__ float g_ycf[2][TT*DI];         // scan output (pre-gate), fp32
// ---------------- bf16 scratch ----------------
__device__ __nv_bfloat16 g_un_bf[TT*DM];
__device__ __nv_bfloat16 g_xc_bf[2][TT*DI];
__device__ __nv_bfloat16 g_xd_bf[2][TT*XDB];
__device__ __nv_bfloat16 g_ycat_bf[TT*2*DI];
__device__ __nv_bfloat16 g_inw_bf[2][IN_W];
__device__ __nv_bfloat16 g_xpw_bf[2][XP_W];
__device__ __nv_bfloat16 g_dtw_bf[2][DT_W];
__device__ __nv_bfloat16 g_outw_bf[OUT_W];

// ---------------- helpers ----------------
__device__ __forceinline__ void cp16(uint32_t dst_s, const void* src) {
    asm volatile("cp.async.ca.shared.global [%0], [%1], 16;\n" :: "r"(dst_s), "l"(src));
}
__device__ __forceinline__ void cp_commit() {
    asm volatile("cp.async.commit_group;\n");
}
template<int N> __device__ __forceinline__ void cp_wait() {
    asm volatile("cp.async.wait_group %0;\n" :: "n"(N));
}
__device__ __forceinline__ void ldsm4(uint32_t& r0, uint32_t& r1,
                                      uint32_t& r2, uint32_t& r3, uint32_t a) {
    asm volatile("ldmatrix.sync.aligned.m8n8.x4.shared.b16 {%0,%1,%2,%3}, [%4];\n"
        : "=r"(r0), "=r"(r1), "=r"(r2), "=r"(r3) : "r"(a));
}
__device__ __forceinline__ void mma_bf16(
    float& c0, float& c1, float& c2, float& c3,
    uint32_t a0, uint32_t a1, uint32_t a2, uint32_t a3,
    uint32_t b0, uint32_t b1)
{
    asm volatile(
        "mma.sync.aligned.m16n8k16.row.col.f32.bf16.bf16.f32 "
        "{%0,%1,%2,%3}, {%4,%5,%6,%7}, {%8,%9}, {%0,%1,%2,%3};\n"
        : "+f"(c0), "+f"(c1), "+f"(c2), "+f"(c3)
        : "r"(a0), "r"(a1), "r"(a2), "r"(a3), "r"(b0), "r"(b1));
}
__device__ __forceinline__ uint32_t pk2(float a, float b) {
    __nv_bfloat162 h = __float22bfloat162_rn(make_float2(a, b));
    return *reinterpret_cast<uint32_t*>(&h);
}

// ---------------- prep: weight cvt (blocks < NCVT) + layernorm (rest) ----------------
__global__ __launch_bounds__(256) void prep_kernel(
    const float* __restrict__ u, const float* __restrict__ nw,
    const float* __restrict__ nb,
    const float* __restrict__ fw, const float* __restrict__ bw,
    const float* __restrict__ fx, const float* __restrict__ bx,
    const float* __restrict__ fd, const float* __restrict__ bd,
    const float* __restrict__ ow)
{
    if (blockIdx.x < NCVT) {
        long long i = ((long long)blockIdx.x * 256 + threadIdx.x) * 8;
        const float* s; __nv_bfloat16* dst;
        if (i < IN_W)                 { s = fw + i; dst = &g_inw_bf[0][i]; }
        else if ((i -= IN_W) < IN_W)  { s = bw + i; dst = &g_inw_bf[1][i]; }
        else if ((i -= IN_W) < XP_W)  { s = fx + i; dst = &g_xpw_bf[0][i]; }
        else if ((i -= XP_W) < XP_W)  { s = bx + i; dst = &g_xpw_bf[1][i]; }
        else if ((i -= XP_W) < DT_W)  { s = fd + i; dst = &g_dtw_bf[0][i]; }
        else if ((i -= DT_W) < DT_W)  { s = bd + i; dst = &g_dtw_bf[1][i]; }
        else if ((i -= DT_W) < OUT_W) { s = ow + i; dst = &g_outw_bf[i]; }
        else return;
        float4 lo = *(const float4*)s;
        float4 hi = *(const float4*)(s + 4);
        uint4 o;
        o.x = pk2(lo.x, lo.y); o.y = pk2(lo.z, lo.w);
        o.z = pk2(hi.x, hi.y); o.w = pk2(hi.z, hi.w);
        *(uint4*)dst = o;
        return;
    }
    // layernorm
    int t = blockIdx.x - NCVT;
    const float* row = u + (size_t)t * DM;
    float v[3];
    float s = 0.f, s2 = 0.f;
#pragma unroll
    for (int i = 0; i < 3; i++) {
        v[i] = row[threadIdx.x + i*256];
        s  += v[i];
        s2 += v[i]*v[i];
    }
#pragma unroll
    for (int o = 16; o; o >>= 1) {
        s  += __shfl_xor_sync(0xffffffffu, s,  o);
        s2 += __shfl_xor_sync(0xffffffffu, s2, o);
    }
    __shared__ float ss[8], ss2[8];
    int wid = threadIdx.x >> 5, ln = threadIdx.x & 31;
    if (ln == 0) { ss[wid] = s; ss2[wid] = s2; }
    __syncthreads();
    float ts = 0.f, ts2 = 0.f;
#pragma unroll
    for (int i = 0; i < 8; i++) { ts += ss[i]; ts2 += ss2[i]; }
    float mu  = ts * (1.f/DM);
    float var = ts2 * (1.f/DM) - mu*mu;
    float rs  = rsqrtf(var + 1e-5f);
#pragma unroll
    for (int i = 0; i < 3; i++) {
        int c = threadIdx.x + i*256;
        g_un_bf[(size_t)t*DM + c] = __float2bfloat16((v[i]-mu)*rs*nw[c] + nb[c]);
    }
}

// ======== gemm_big: 128x128 CTA tile, 4 warps (64x64 each), k64 slabs ========
// MODE 0: plain fp32 (z = branch).  MODE 3: split-K (z = k-chunk; -> C0+z*TT*DM).
template<int MODE>
__global__ void __launch_bounds__(128) gemm_big(
    const __nv_bfloat16* __restrict__ A0, const __nv_bfloat16* __restrict__ A1, int lda,
    const __nv_bfloat16* __restrict__ W0, const __nv_bfloat16* __restrict__ W1, int ldw,
    float* __restrict__ C0, float* __restrict__ C1, int ldc,
    int K)
{
    extern __shared__ char smem[];
    uint32_t sb = (uint32_t)__cvta_generic_to_shared(smem);

    const __nv_bfloat16* A;
    const __nv_bfloat16* W;
    float* C;
    if (MODE == 3) {
        A = A0 + (size_t)blockIdx.z * K;
        W = W0 + (size_t)blockIdx.z * K;
        C = C0 + (size_t)blockIdx.z * ((size_t)TT * DM);
    } else {
        A = blockIdx.z ? A1 : A0;
        W = blockIdx.z ? W1 : W0;
        C = blockIdx.z ? C1 : C0;
    }

    int tid  = threadIdx.x;
    int lane = tid & 31;
    int w    = tid >> 5;
    int wm   = w >> 1;
    int wn   = w & 1;
    int bm   = blockIdx.y * 128;
    int bn   = blockIdx.x * 128;

    int ch = tid & 7;
    int rb = tid >> 3;
    const __nv_bfloat16* ap = A + (size_t)(bm + rb) * lda + ch * 8;
    const __nv_bfloat16* wp = W + (size_t)(bn + rb) * ldw + ch * 8;
    uint32_t ao = (uint32_t)(rb * 128 + ((ch ^ (rb & 7)) * 16));
    uint32_t bo = 16384u + ao;

    int nk = K / 64;
#pragma unroll
    for (int p = 0; p < 2; p++) {
#pragma unroll
        for (int v = 0; v < 8; v++) {
            cp16(sb + p*32768 + ao + v*2048, ap + (size_t)v*16*lda + p*64);
            cp16(sb + p*32768 + bo + v*2048, wp + (size_t)v*16*ldw + p*64);
        }
        cp_commit();
    }

    float acc[4][8][4] = {};
    int arow = lane & 15;
    int ach  = lane >> 4;
    int brow = ((lane >> 4) << 3) + (lane & 7);
    int bch  = (lane >> 3) & 1;
    int r0   = lane >> 2;
    int c0   = lane & 3;

    for (int i = 0; i < nk; i++) {
        int st = i % 3;
        cp_wait<1>();
        __syncthreads();
        {
            int s2 = (i + 2) % 3;
            if (i + 2 < nk) {
#pragma unroll
                for (int v = 0; v < 8; v++) {
                    cp16(sb + s2*32768 + ao + v*2048, ap + (size_t)v*16*lda + (i+2)*64);
                    cp16(sb + s2*32768 + bo + v*2048, wp + (size_t)v*16*ldw + (i+2)*64);
                }
            }
            cp_commit();
        }
        uint32_t base = sb + st*32768;
#pragma unroll
        for (int kk = 0; kk < 4; kk++) {
            uint32_t ar[4][4];
#pragma unroll
            for (int ii = 0; ii < 4; ii++) {
                int row = wm*64 + ii*16 + arow;
                int pos = (2*kk + ach) ^ (row & 7);
                ldsm4(ar[ii][0], ar[ii][1], ar[ii][2], ar[ii][3],
                      base + row*128 + pos*16);
            }
            uint32_t br_[8][2];
#pragma unroll
            for (int j2 = 0; j2 < 4; j2++) {
                int row = wn*64 + j2*16 + brow;
                int pos = (2*kk + bch) ^ (row & 7);
                ldsm4(br_[2*j2][0], br_[2*j2][1], br_[2*j2+1][0], br_[2*j2+1][1],
                      base + 16384 + row*128 + pos*16);
            }
#pragma unroll
            for (int ii = 0; ii < 4; ii++)
#pragma unroll
                for (int j = 0; j < 8; j++)
                    mma_bf16(acc[ii][j][0], acc[ii][j][1],
                             acc[ii][j][2], acc[ii][j][3],
                             ar[ii][0], ar[ii][1], ar[ii][2], ar[ii][3],
                             br_[j][0], br_[j][1]);
        }
    }

#pragma unroll
    for (int ii = 0; ii < 4; ii++) {
        int m0 = bm + wm*64 + ii*16 + r0;
#pragma unroll
        for (int j = 0; j < 8; j++) {
            int n0 = bn + wn*64 + j*8 + c0*2;
            *(float2*)&C[(size_t)m0 * ldc + n0] =
                make_float2(acc[ii][j][0], acc[ii][j][1]);
            *(float2*)&C[(size_t)(m0+8) * ldc + n0] =
                make_float2(acc[ii][j][2], acc[ii][j][3]);
        }
    }
}

// ---------------- out-proj reduce: partials + residual -> out ----------------
__global__ __launch_bounds__(256) void reduce_out(const float* __restrict__ u,
                                                  float* __restrict__ out)
{
    int i4 = (blockIdx.x * 256 + threadIdx.x) * 4;
    if (i4 >= TT*DM) return;
    float4 s = *(const float4*)&u[i4];
#pragma unroll
    for (int p = 0; p < OSPLIT; p++) {
        float4 a = *(const float4*)&g_odp[p][i4];
        s.x += a.x; s.y += a.y; s.z += a.z; s.w += a.w;
    }
    *(float4*)&out[i4] = s;
}

// ======== gemm_xp: xproj split-K.  BM=32, BN=64, 4 warps, K=768/part ========
__global__ void __launch_bounds__(128) gemm_xp(
    const __nv_bfloat16* __restrict__ Ab0, const __nv_bfloat16* __restrict__ Ab1,
    const __nv_bfloat16* __restrict__ Wb0, const __nv_bfloat16* __restrict__ Wb1,
    float* __restrict__ Cp)
{
    constexpr int BM = 32, BN = 64, THREADS = 128;
    constexpr int SWORDS = (BM + BN) * 16;
    constexpr int LPT = (BM + BN) * 4 / THREADS;   // 3
    constexpr int KPART = 768;

    extern __shared__ uint32_t sm[];
    uint32_t smem_base = (uint32_t)__cvta_generic_to_shared(sm);

    int z  = blockIdx.z;
    int br = z >> 1;
    int kh = z & 1;
    const __nv_bfloat16* A = (br ? Ab1 : Ab0) + kh * KPART;
    const __nv_bfloat16* W = (br ? Wb1 : Wb0) + kh * KPART;
    float* C = Cp + (size_t)z * (TT*XDB);

    int tid  = threadIdx.x;
    int lane = tid & 31;
    int w    = tid >> 5;
    int wm   = w >> 1;
    int wn   = w & 1;
    int bm   = blockIdx.y * BM;
    int bn   = blockIdx.x * BN;
    int r0   = lane >> 2;
    int c0   = lane & 3;

    const __nv_bfloat16* lsrc[LPT];
    uint32_t ldst[LPT];
#pragma unroll
    for (int u = 0; u < LPT; u++) {
        int i   = tid + u * THREADS;
        int row = i >> 2;
        int x   = i & 3;
        if (row < BM) {
            lsrc[u] = A + (size_t)(bm + row) * DI + x * 8;
            ldst[u] = row * 16 + (x ^ ((row >> 1) & 3)) * 4;
        } else {
            int r = row - BM;
            lsrc[u] = W + (size_t)(bn + r) * DI + x * 8;
            ldst[u] = BM * 16 + r * 16 + (x ^ ((r >> 1) & 3)) * 4;
        }
    }

    constexpr int nk = KPART / 32;   // 24
#pragma unroll
    for (int p = 0; p < 3; p++) {
#pragma unroll
        for (int u = 0; u < LPT; u++)
            cp16(smem_base + (p*SWORDS + ldst[u])*4, lsrc[u] + p*32);
        cp_commit();
    }

    float acc[1][4][4] = {};
    int arow = lane & 15;
    int ach  = lane >> 4;
    int brow = ((lane >> 4) << 3) + (lane & 7);
    int bch  = (lane >> 3) & 1;

    for (int i = 0; i < nk; i++) {
        int st = i & 3;
        int rem = nk - 1 - i;
        if (rem >= 2)      cp_wait<2>();
        else if (rem == 1) cp_wait<1>();
        else               cp_wait<0>();
        __syncthreads();
        if (i + 3 < nk) {
            int st2 = (i + 3) & 3;
#pragma unroll
            for (int u = 0; u < LPT; u++)
                cp16(smem_base + (st2*SWORDS + ldst[u])*4, lsrc[u] + (i+3)*32);
            cp_commit();
        }
        uint32_t stw = smem_base + st*SWORDS*4;
#pragma unroll
        for (int kk = 0; kk < 2; kk++) {
            uint32_t ar[4];
            {
                int row = wm*16 + arow;
                int pos = (2*kk + ach) ^ ((row >> 1) & 3);
                ldsm4(ar[0], ar[1], ar[2], ar[3], stw + (row*16 + pos*4)*4);
            }
            uint32_t br_[4][2];
#pragma unroll
            for (int j2 = 0; j2 < 2; j2++) {
                int row = wn*32 + j2*16 + brow;
                int pos = (2*kk + bch) ^ ((row >> 1) & 3);
                ldsm4(br_[2*j2][0], br_[2*j2][1], br_[2*j2+1][0], br_[2*j2+1][1],
                      stw + (BM*16 + row*16 + pos*4)*4);
            }
#pragma unroll
            for (int j = 0; j < 4; j++)
                mma_bf16(acc[0][j][0], acc[0][j][1], acc[0][j][2], acc[0][j][3],
                         ar[0], ar[1], ar[2], ar[3], br_[j][0], br_[j][1]);
        }
    }

    {
        int m0 = bm + wm*16 + r0;
#pragma unroll
        for (int j = 0; j < 4; j++) {
            int n0 = bn + wn*32 + j*8 + c0*2;
            *(float2*)&C[(size_t)m0 * XDB + n0]     = make_float2(acc[0][j][0], acc[0][j][1]);
            *(float2*)&C[(size_t)(m0+8) * XDB + n0] = make_float2(acc[0][j][2], acc[0][j][3]);
        }
    }
}

// ---------------- reduce xproj partials -> fp32 + bf16 ----------------
__global__ __launch_bounds__(256) void reduce_xd()
{
    int br = blockIdx.y;
    int i4 = (blockIdx.x * 256 + threadIdx.x) * 4;
    if (i4 >= TT*XDB) return;
    float4 a = *(const float4*)&g_xdp[br*2 + 0][i4];
    float4 b = *(const float4*)&g_xdp[br*2 + 1][i4];
    float4 s = make_float4(a.x+b.x, a.y+b.y, a.z+b.z, a.w+b.w);
    *(float4*)&g_xdbl[br][i4] = s;
    *(__nv_bfloat162*)&g_xd_bf[br][i4]   = __float22bfloat162_rn(make_float2(s.x, s.y));
    *(__nv_bfloat162*)&g_xd_bf[br][i4+2] = __float22bfloat162_rn(make_float2(s.z, s.w));
}

// ---------------- dt GEMM: mma.sync, 128x128, K=96, softplus ----------------
__global__ void __launch_bounds__(256) gemm_dt(
    const __nv_bfloat16* __restrict__ A0, const __nv_bfloat16* __restrict__ A1,
    const __nv_bfloat16* __restrict__ W0, const __nv_bfloat16* __restrict__ W1,
    float* __restrict__ C0, float* __restrict__ C1,
    const float* __restrict__ bias0, const float* __restrict__ bias1)
{
    constexpr int BM = 128, BN = 128, THREADS = 256;
    constexpr int SWORDS = (BM + BN) * 16;
    constexpr int LPT = (BM + BN) * 4 / THREADS;  // 4
    constexpr int K = DTR;                        // 96

    extern __shared__ uint32_t sm[];
    uint32_t smem_base = (uint32_t)__cvta_generic_to_shared(sm);

    const __nv_bfloat16* A = blockIdx.z ? A1 : A0;
    const __nv_bfloat16* W = blockIdx.z ? W1 : W0;
    float*       C    = blockIdx.z ? C1 : C0;
    const float* bias = blockIdx.z ? bias1 : bias0;

    int tid  = threadIdx.x;
    int lane = tid & 31;
    int w    = tid >> 5;
    int wm   = w >> 1;
    int wn   = w & 1;
    int bm   = blockIdx.y * BM;
    int bn   = blockIdx.x * BN;
    int r0   = lane >> 2;
    int c0   = lane & 3;

    const __nv_bfloat16* lsrc[LPT];
    uint32_t ldst[LPT];
#pragma unroll
    for (int u = 0; u < LPT; u++) {
        int i   = tid + u * THREADS;
        int row = i >> 2;
        int x   = i & 3;
        if (row < BM) {
            lsrc[u] = A + (size_t)(bm + row) * XDB + x * 8;
            ldst[u] = row * 16 + (x ^ ((row >> 1) & 3)) * 4;
        } else {
            int r = row - BM;
            lsrc[u] = W + (size_t)(bn + r) * DTR + x * 8;
            ldst[u] = BM * 16 + r * 16 + (x ^ ((r >> 1) & 3)) * 4;
        }
    }

    constexpr int nk = K / 32;   // 3
#pragma unroll
    for (int p = 0; p < 3; p++) {
#pragma unroll
        for (int u = 0; u < LPT; u++)
            cp16(smem_base + (p*SWORDS + ldst[u])*4, lsrc[u] + p*32);
        cp_commit();
    }

    float acc[2][8][4] = {};
    int arow = lane & 15;
    int ach  = lane >> 4;
    int brow = ((lane >> 4) << 3) + (lane & 7);
    int bch  = (lane >> 3) & 1;

    for (int i = 0; i < nk; i++) {
        int st = i & 3;
        int rem = nk - 1 - i;
        if (rem >= 2)      cp_wait<2>();
        else if (rem == 1) cp_wait<1>();
        else               cp_wait<0>();
        __syncthreads();
        uint32_t stw = smem_base + st*SWORDS*4;
#pragma unroll
        for (int kk = 0; kk < 2; kk++) {
            uint32_t ar[2][4];
#pragma unroll
            for (int ii = 0; ii < 2; ii++) {
                int row = wm*32 + ii*16 + arow;
                int pos = (2*kk + ach) ^ ((row >> 1) & 3);
                ldsm4(ar[ii][0], ar[ii][1], ar[ii][2], ar[ii][3],
                      stw + (row*16 + pos*4)*4);
            }
            uint32_t br_[8][2];
#pragma unroll
            for (int j2 = 0; j2 < 4; j2++) {
                int row = wn*64 + j2*16 + brow;
                int pos = (2*kk + bch) ^ ((row >> 1) & 3);
                ldsm4(br_[2*j2][0], br_[2*j2][1], br_[2*j2+1][0], br_[2*j2+1][1],
                      stw + (BM*16 + row*16 + pos*4)*4);
            }
#pragma unroll
            for (int ii = 0; ii < 2; ii++)
#pragma unroll
                for (int j = 0; j < 8; j++)
                    mma_bf16(acc[ii][j][0], acc[ii][j][1],
                             acc[ii][j][2], acc[ii][j][3],
                             ar[ii][0], ar[ii][1], ar[ii][2], ar[ii][3],
                             br_[j][0], br_[j][1]);
        }
    }

#pragma unroll
    for (int ii = 0; ii < 2; ii++) {
        int m0 = bm + wm*32 + ii*16 + r0;
#pragma unroll
        for (int j = 0; j < 8; j++) {
            int n0 = bn + wn*64 + j*8 + c0*2;
            float v0 = acc[ii][j][0], v1 = acc[ii][j][1];
            float v2 = acc[ii][j][2], v3 = acc[ii][j][3];
            float b0v = bias[n0], b1v = bias[n0 + 1];
            v0 += b0v; v1 += b1v; v2 += b0v; v3 += b1v;
            v0 = fmaxf(v0, 0.f) + log1pf(__expf(-fabsf(v0)));
            v1 = fmaxf(v1, 0.f) + log1pf(__expf(-fabsf(v1)));
            v2 = fmaxf(v2, 0.f) + log1pf(__expf(-fabsf(v2)));
            v3 = fmaxf(v3, 0.f) + log1pf(__expf(-fabsf(v3)));
            *(float2*)&C[(size_t)m0 * DI + n0]     = make_float2(v0, v1);
            *(float2*)&C[(size_t)(m0+8) * DI + n0] = make_float2(v2, v3);
        }
    }
}

// ---------------- depthwise conv (K=4) + silu; 4 tokens x 4 channels ----------------
__global__ __launch_bounds__(256) void conv_silu(
    const float* __restrict__ cw0, const float* __restrict__ cb0,
    const float* __restrict__ cw1, const float* __restrict__ cb1)
{
    int br = blockIdx.y;
    const float* cw = br ? cw1 : cw0;
    const float* cb = br ? cb1 : cb0;
    const float* xz = g_xz[br];

    constexpr int ND4 = DI/4;
    int idx = blockIdx.x * 256 + threadIdx.x;
    if (idx >= (TT/4)*ND4) return;
    int tq = idx / ND4;
    int d4 = (idx % ND4) * 4;
    int t0 = tq * 4;
    int l0 = t0 % Lseq;

    float4 wr[4];
#pragma unroll
    for (int i = 0; i < 4; i++) wr[i] = *(const float4*)&cw[(d4+i)*4];
    float4 b4 = *(const float4*)&cb[d4];

    float4 xr[7];
    if (br == 0) {
#pragma unroll
        for (int j = 0; j < 7; j++) {
            int off = j - 3;
            xr[j] = (l0 + off >= 0)
                  ? *(const float4*)&xz[(size_t)(t0+off)*2*DI + d4]
                  : make_float4(0.f,0.f,0.f,0.f);
        }
    } else {
#pragma unroll
        for (int j = 0; j < 7; j++) {
            xr[j] = (l0 + j < Lseq)
                  ? *(const float4*)&xz[(size_t)(t0+j)*2*DI + d4]
                  : make_float4(0.f,0.f,0.f,0.f);
        }
    }

    const float* X  = (const float*)xr;
    const float* Wp = (const float*)wr;
    const float* Bp = (const float*)&b4;
#pragma unroll
    for (int i2 = 0; i2 < 4; i2++) {
        float o[4];
#pragma unroll
        for (int c = 0; c < 4; c++) {
            float a = Bp[c];
            if (br == 0) {
                a = fmaf(Wp[c*4+0], X[i2*4+c],     a);
                a = fmaf(Wp[c*4+1], X[(i2+1)*4+c], a);
                a = fmaf(Wp[c*4+2], X[(i2+2)*4+c], a);
                a = fmaf(Wp[c*4+3], X[(i2+3)*4+c], a);
            } else {
                a = fmaf(Wp[c*4+3], X[i2*4+c],     a);
                a = fmaf(Wp[c*4+2], X[(i2+1)*4+c], a);
                a = fmaf(Wp[c*4+1], X[(i2+2)*4+c], a);
                a = fmaf(Wp[c*4+0], X[(i2+3)*4+c], a);
            }
            float sg = 1.f / (1.f + __expf(-a));
            o[c] = a * sg;
        }
        int t = t0 + i2;
        *(float4*)&g_xc[br][(size_t)t*DI + d4] = make_float4(o[0], o[1], o[2], o[3]);
        *(__nv_bfloat162*)&g_xc_bf[br][(size_t)t*DI + d4] =
            __float22bfloat162_rn(make_float2(o[0], o[1]));
        *(__nv_bfloat162*)&g_xc_bf[br][(size_t)t*DI + d4 + 2] =
            __float22bfloat162_rn(make_float2(o[2], o[3]));
    }
}

// ---------------- selective scan: no gate, fp32 out, 4-step pipelined ----------------
__global__ __launch_bounds__(128) void scan_kernel(
    const float* __restrict__ Alog0, const float* __restrict__ Alog1,
    const float* __restrict__ Dv0,   const float* __restrict__ Dv1)
{
    int br = blockIdx.z;
    int b  = blockIdx.y;
    const float* Alog = br ? Alog1 : Alog0;
    const float* Dvec = br ? Dv1   : Dv0;
    const float* dt   = g_dt[br];
    const float* xc   = g_xc[br];
    const float* xd   = g_xdbl[br];
    float*       yo   = g_ycf[br];

    int lane = threadIdx.x & 31;
    int warp = threadIdx.x >> 5;
    int n    = lane & 15;
    int d    = blockIdx.x * 8 + warp * 2 + (lane >> 4);

    float A  = -__expf(Alog[d*NS + n]);
    float Dp = Dvec[d];
    float h  = 0.f;

    int step = br ? -1 : 1;
    int t = b*Lseq + (br ? Lseq-1 : 0);

    float dt4[4], xv4[4], Bv4[4], Cv4[4];
    {
        int tq = t;
#pragma unroll
        for (int j = 0; j < 4; j++) {
            dt4[j] = dt[(size_t)tq*DI + d];
            xv4[j] = xc[(size_t)tq*DI + d];
            Bv4[j] = xd[(size_t)tq*XDB + DTR + n];
            Cv4[j] = xd[(size_t)tq*XDB + DTR + NS + n];
            tq += step;
        }
    }

    for (int s = 0; s < Lseq; s += 4) {
        float nd[4], nx[4], nB[4], nC[4];
        if (s + 4 < Lseq) {
            int tq = t + 4*step;
#pragma unroll
            for (int j = 0; j < 4; j++) {
                nd[j] = dt[(size_t)tq*DI + d];
                nx[j] = xc[(size_t)tq*DI + d];
                nB[j] = xd[(size_t)tq*XDB + DTR + n];
                nC[j] = xd[(size_t)tq*XDB + DTR + NS + n];
                tq += step;
            }
        } else {
#pragma unroll
            for (int j = 0; j < 4; j++) { nd[j]=0.f; nx[j]=0.f; nB[j]=0.f; nC[j]=0.f; }
        }
        float ya[4];
#pragma unroll
        for (int j = 0; j < 4; j++) {
            float a = __expf(dt4[j] * A);
            h = fmaf(a, h, dt4[j] * xv4[j] * Bv4[j]);
            ya[j] = h * Cv4[j];
        }
#pragma unroll
        for (int off = 8; off; off >>= 1) {
#pragma unroll
            for (int j = 0; j < 4; j++)
                ya[j] += __shfl_xor_sync(0xffffffffu, ya[j], off);
        }
        if (n == 0) {
#pragma unroll
            for (int j = 0; j < 4; j++) {
                int tj = t + j*step;
                yo[(size_t)tj*DI + d] = fmaf(xv4[j], Dp, ya[j]);
            }
        }
#pragma unroll
        for (int j = 0; j < 4; j++) {
            dt4[j] = nd[j]; xv4[j] = nx[j]; Bv4[j] = nB[j]; Cv4[j] = nC[j];
        }
        t += 4*step;
    }
}

// ---------------- gate: ycat_bf = ycf * silu(z), vectorized x4 ----------------
__global__ __launch_bounds__(256) void gate_kernel()
{
    int br = blockIdx.y;
    int i4 = (blockIdx.x * 256 + threadIdx.x) * 4;
    if (i4 >= TT*DI) return;
    int t = i4 / DI;
    int d = i4 % DI;
    float4 y = *(const float4*)&g_ycf[br][i4];
    float4 z = *(const float4*)&g_xz[br][(size_t)t*2*DI + DI + d];
    float o[4];
    const float* yp = (const float*)&y;
    const float* zp = (const float*)&z;
#pragma unroll
    for (int i = 0; i < 4; i++) {
        float sz = zp[i] / (1.f + __expf(-zp[i]));
        o[i] = yp[i] * sz;
    }
    __nv_bfloat16* dst = &g_ycat_bf[(size_t)t*2*DI + br*DI + d];
    *(__nv_bfloat162*)dst       = __float22bfloat162_rn(make_float2(o[0], o[1]));
    *(__nv_bfloat162*)(dst + 2) = __float22bfloat162_rn(make_float2(o[2], o[3]));
}

// ---------------- launcher ----------------
extern "C" void kernel_launch(void* const* d_in, const int* in_sizes, int n_in,
                              void* d_out, int out_size)
{
    const float* u       = (const float*)d_in[0];
    const float* norm_w  = (const float*)d_in[1];
    const float* norm_b  = (const float*)d_in[2];
    const float* f_in_w  = (const float*)d_in[3];
    const float* f_cw    = (const float*)d_in[4];
    const float* f_cb    = (const float*)d_in[5];
    const float* f_Alog  = (const float*)d_in[6];
    const float* f_xpw   = (const float*)d_in[7];
    const float* f_dtw   = (const float*)d_in[8];
    const float* f_dtb   = (const float*)d_in[9];
    const float* f_D     = (const float*)d_in[10];
    const float* b_in_w  = (const float*)d_in[11];
    const float* b_cw    = (const float*)d_in[12];
    const float* b_cb    = (const float*)d_in[13];
    const float* b_Alog  = (const float*)d_in[14];
    const float* b_xpw   = (const float*)d_in[15];
    const float* b_dtw   = (const float*)d_in[16];
    const float* b_dtb   = (const float*)d_in[17];
    const float* b_D     = (const float*)d_in[18];
    const float* out_w   = (const float*)d_in[19];
    float* out = (float*)d_out;

    float *xz, *dt, *xdp, *odp;
    __nv_bfloat16 *un_bf, *xc_bf, *xd_bf, *ycat_bf;
    __nv_bfloat16 *inw_bf, *xpw_bf, *dtw_bf, *outw_bf;
    cudaGetSymbolAddress((void**)&xz,     g_xz);
    cudaGetSymbolAddress((void**)&dt,     g_dt);
    cudaGetSymbolAddress((void**)&xdp,    g_xdp);
    cudaGetSymbolAddress((void**)&odp,    g_odp);
    cudaGetSymbolAddress((void**)&un_bf,  g_un_bf);
    cudaGetSymbolAddress((void**)&xc_bf,  g_xc_bf);
    cudaGetSymbolAddress((void**)&xd_bf,  g_xd_bf);
    cudaGetSymbolAddress((void**)&ycat_bf,g_ycat_bf);
    cudaGetSymbolAddress((void**)&inw_bf, g_inw_bf);
    cudaGetSymbolAddress((void**)&xpw_bf, g_xpw_bf);
    cudaGetSymbolAddress((void**)&dtw_bf, g_dtw_bf);
    cudaGetSymbolAddress((void**)&outw_bf,g_outw_bf);

    float* xz0 = xz;   float* xz1 = xz + (size_t)TT*2*DI;
    float* dt0 = dt;   float* dt1 = dt + (size_t)TT*DI;
    __nv_bfloat16* xcb0 = xc_bf;  __nv_bfloat16* xcb1 = xc_bf + (size_t)TT*DI;
    __nv_bfloat16* xdb0 = xd_bf;  __nv_bfloat16* xdb1 = xd_bf + (size_t)TT*XDB;
    __nv_bfloat16* inw0 = inw_bf; __nv_bfloat16* inw1 = inw_bf + (size_t)IN_W;
    __nv_bfloat16* xpw0 = xpw_bf; __nv_bfloat16* xpw1 = xpw_bf + (size_t)XP_W;
    __nv_bfloat16* dtw0 = dtw_bf; __nv_bfloat16* dtw1 = dtw_bf + (size_t)DT_W;

    constexpr int SM_BIG = 3 * 32768;
    constexpr int SM_XP  = 4 *  96 * 64;
    constexpr int SM_DT  = 4 * 256 * 64;
    cudaFuncSetAttribute((const void*)gemm_big<0>,
        cudaFuncAttributeMaxDynamicSharedMemorySize, SM_BIG);
    cudaFuncSetAttribute((const void*)gemm_big<3>,
        cudaFuncAttributeMaxDynamicSharedMemorySize, SM_BIG);
    cudaFuncSetAttribute((const void*)gemm_xp,
        cudaFuncAttributeMaxDynamicSharedMemorySize, SM_XP);
    cudaFuncSetAttribute((const void*)gemm_dt,
        cudaFuncAttributeMaxDynamicSharedMemorySize, SM_DT);

    // 0) weights->bf16 + layernorm (merged)
    prep_kernel<<<NCVT + TT, 256>>>(u, norm_w, norm_b,
                                    f_in_w, b_in_w, f_xpw, b_xpw,
                                    f_dtw, b_dtw, out_w);

    // 1) in-proj: (2048x768) -> 3072 per branch
    gemm_big<0><<<dim3(2*DI/128, TT/128, 2), 128, SM_BIG>>>(
        un_bf, un_bf, DM, inw0, inw1, DM, xz0, xz1, 2*DI, DM);

    // 2) conv + silu
    conv_silu<<<dim3((TT/4)*(DI/4)/256, 2), 256>>>(f_cw, f_cb, b_cw, b_cb);

    // 3) xproj split-K + reduce
    gemm_xp<<<dim3(XDB/64, TT/32, 4), 128, SM_XP>>>(
        xcb0, xcb1, xpw0, xpw1, xdp);
    reduce_xd<<<dim3(TT*XDB/4/256, 2), 256>>>();

    // 4) dt: softplus+bias
    gemm_dt<<<dim3(DI/128, TT/128, 2), 256, SM_DT>>>(
        xdb0, xdb1, dtw0, dtw1, dt0, dt1, f_dtb, b_dtb);

    // 5) selective scan (no gate) -> fp32 ycf
    scan_kernel<<<dim3(DI/8, Bb, 2), 128>>>(f_Alog, b_Alog, f_D, b_D);

    // 6) gate: ycat_bf = ycf * silu(z)
    gate_kernel<<<dim3(TT*DI/4/256, 2), 256>>>();

    // 7) out-proj split-K x2 -> partials, then reduce + residual
    gemm_big<3><<<dim3(DM/128, TT/128, OSPLIT), 128, SM_BIG>>>(
        ycat_bf, nullptr, 2*DI, outw_bf, nullptr, 2*DI, odp, nullptr, DM,
        (2*DI)/OSPLIT);
    reduce_out<<<TT*DM/4/256, 256>>>(u, out);
}